// round 1
// baseline (speedup 1.0000x reference)
#include <cuda_runtime.h>

#define NMAX 500000
#define EMAX 2000000
#define GMAX 16384
#define ND 44
#define ED 12
#define HD 64
#define EMB 128

// Scratch (allocation-free rule: __device__ globals)
__device__ float g_agg1[(size_t)NMAX * ND];   // 88 MB
__device__ float g_h1  [(size_t)NMAX * HD];   // 128 MB
__device__ float g_agg2[(size_t)NMAX * HD];   // 128 MB
__device__ int   g_cnt [GMAX];

// ---------------------------------------------------------------------------
__global__ void zero_all(float* __restrict__ out, long n_out, int N) {
    long idx = (long)blockIdx.x * blockDim.x + threadIdx.x;
    long st  = (long)gridDim.x * blockDim.x;
    long n1 = (long)N * ND, n2 = (long)N * HD;
    for (long i = idx; i < n1; i += st) g_agg1[i] = 0.f;
    for (long i = idx; i < n2; i += st) g_agg2[i] = 0.f;
    for (long i = idx; i < n_out; i += st) out[i] = 0.f;
    for (long i = idx; i < GMAX; i += st) g_cnt[i] = 0;
}

// ---------------------------------------------------------------------------
// Layer-1 edge pass: msg = relu(x[src] + edge_attr@W + b); scatter-add @ dst.
// 64-thread group per edge, lane = feature (44 active). relu==0 -> skip atomic.
__global__ void edge1_kernel(const float* __restrict__ x, const float* __restrict__ ea,
                             const int* __restrict__ src, const int* __restrict__ dst,
                             const float* __restrict__ W, const float* __restrict__ b, int E) {
    __shared__ float sW[ED * ND];
    __shared__ float sb[ND];
    int t = threadIdx.x;
    for (int i = t; i < ED * ND; i += blockDim.x) sW[i] = W[i];
    if (t < ND) sb[t] = b[t];
    __syncthreads();
    int grp = t >> 6, j = t & 63;
    long e = (long)blockIdx.x * 4 + grp;
    long stride = (long)gridDim.x * 4;
    for (; e < E; e += stride) {
        if (j < ND) {
            int s = src[e], d = dst[e];
            const float* eap = ea + e * ED;
            float acc = sb[j];
            #pragma unroll
            for (int k = 0; k < ED; k++) acc = fmaf(eap[k], sW[k * ND + j], acc);
            float m = x[(long)s * ND + j] + acc;
            if (m > 0.f) atomicAdd(&g_agg1[(long)d * ND + j], m);
        }
    }
}

// Layer-2 edge pass: msg = relu(h1[src] + edge_attr@W + b); scatter-add @ dst.
__global__ void edge2_kernel(const float* __restrict__ ea,
                             const int* __restrict__ src, const int* __restrict__ dst,
                             const float* __restrict__ W, const float* __restrict__ b, int E) {
    __shared__ float sW[ED * HD];
    __shared__ float sb[HD];
    int t = threadIdx.x;
    for (int i = t; i < ED * HD; i += blockDim.x) sW[i] = W[i];
    if (t < HD) sb[t] = b[t];
    __syncthreads();
    int grp = t >> 6, j = t & 63;
    long e = (long)blockIdx.x * 4 + grp;
    long stride = (long)gridDim.x * 4;
    for (; e < E; e += stride) {
        int s = src[e], d = dst[e];
        const float* eap = ea + e * ED;
        float acc = sb[j];
        #pragma unroll
        for (int k = 0; k < ED; k++) acc = fmaf(eap[k], sW[k * HD + j], acc);
        float m = g_h1[(long)s * HD + j] + acc;
        if (m > 0.f) atomicAdd(&g_agg2[(long)d * HD + j], m);
    }
}

// ---------------------------------------------------------------------------
// Node MLP 1: h1 = relu( relu((x+agg1)@Wa+ba) @ Wb + bb ). Warp per node.
// lane holds 2 output features; inputs broadcast via shfl; weights in SMEM.
__global__ void mlp1_kernel(const float* __restrict__ x,
                            const float* __restrict__ Wa, const float* __restrict__ ba,
                            const float* __restrict__ Wb, const float* __restrict__ bb, int N) {
    __shared__ float sWa[ND * HD], sWb[HD * HD], sba[HD], sbb[HD];
    int t = threadIdx.x;
    for (int i = t; i < ND * HD; i += blockDim.x) sWa[i] = Wa[i];
    for (int i = t; i < HD * HD; i += blockDim.x) sWb[i] = Wb[i];
    if (t < HD) { sba[t] = ba[t]; sbb[t] = bb[t]; }
    __syncthreads();
    int lane = t & 31, warp = t >> 5, wpb = blockDim.x >> 5;
    for (long n = (long)blockIdx.x * wpb + warp; n < N; n += (long)gridDim.x * wpb) {
        const float* xr = x + n * ND;
        const float* ar = g_agg1 + n * ND;
        float va = xr[lane] + ar[lane];                           // lanes 0..31
        float vb = (lane < ND - 32) ? (xr[32 + lane] + ar[32 + lane]) : 0.f;  // 32..43
        float h0 = sba[lane], h1v = sba[lane + 32];
        #pragma unroll
        for (int k = 0; k < 32; k++) {
            float ik = __shfl_sync(0xffffffffu, va, k);
            h0  = fmaf(ik, sWa[k * HD + lane], h0);
            h1v = fmaf(ik, sWa[k * HD + lane + 32], h1v);
        }
        #pragma unroll
        for (int k = 0; k < ND - 32; k++) {
            float ik = __shfl_sync(0xffffffffu, vb, k);
            h0  = fmaf(ik, sWa[(32 + k) * HD + lane], h0);
            h1v = fmaf(ik, sWa[(32 + k) * HD + lane + 32], h1v);
        }
        h0 = fmaxf(h0, 0.f); h1v = fmaxf(h1v, 0.f);
        float o0 = sbb[lane], o1 = sbb[lane + 32];
        #pragma unroll
        for (int k = 0; k < 32; k++) {
            float a0 = __shfl_sync(0xffffffffu, h0, k);
            float a1 = __shfl_sync(0xffffffffu, h1v, k);
            o0 = fmaf(a0, sWb[k * HD + lane], o0);
            o0 = fmaf(a1, sWb[(k + 32) * HD + lane], o0);
            o1 = fmaf(a0, sWb[k * HD + lane + 32], o1);
            o1 = fmaf(a1, sWb[(k + 32) * HD + lane + 32], o1);
        }
        g_h1[n * HD + lane]      = fmaxf(o0, 0.f);   // outer relu of layer 1
        g_h1[n * HD + lane + 32] = fmaxf(o1, 0.f);
    }
}

// ---------------------------------------------------------------------------
// Node MLP 2 + pooling: h2 = relu((h1+agg2)@Wa+ba)@Wb+bb; atomicAdd into
// per-graph sums (d_out) + counts. Warp per node, 4 outputs per lane.
__global__ void mlp2_kernel(const float* __restrict__ Wa, const float* __restrict__ ba,
                            const float* __restrict__ Wb, const float* __restrict__ bb,
                            const int* __restrict__ batch, float* __restrict__ out, int N) {
    extern __shared__ float sm[];
    float* sWa = sm;                       // 64*128
    float* sWb = sm + HD * EMB;            // 128*128
    float* sba = sWb + EMB * EMB;
    float* sbb = sba + EMB;
    int t = threadIdx.x;
    for (int i = t; i < HD * EMB; i += blockDim.x) sWa[i] = Wa[i];
    for (int i = t; i < EMB * EMB; i += blockDim.x) sWb[i] = Wb[i];
    if (t < EMB) { sba[t] = ba[t]; sbb[t] = bb[t]; }
    __syncthreads();
    int lane = t & 31, warp = t >> 5, wpb = blockDim.x >> 5;
    for (long n = (long)blockIdx.x * wpb + warp; n < N; n += (long)gridDim.x * wpb) {
        const float* hr = g_h1 + n * HD;
        const float* ar = g_agg2 + n * HD;
        float va = hr[lane] + ar[lane];
        float vb = hr[lane + 32] + ar[lane + 32];
        float h[4];
        #pragma unroll
        for (int i = 0; i < 4; i++) h[i] = sba[lane + 32 * i];
        #pragma unroll
        for (int k = 0; k < 32; k++) {
            float i0 = __shfl_sync(0xffffffffu, va, k);
            float i1 = __shfl_sync(0xffffffffu, vb, k);
            #pragma unroll
            for (int i = 0; i < 4; i++) {
                h[i] = fmaf(i0, sWa[k * EMB + lane + 32 * i], h[i]);
                h[i] = fmaf(i1, sWa[(k + 32) * EMB + lane + 32 * i], h[i]);
            }
        }
        #pragma unroll
        for (int i = 0; i < 4; i++) h[i] = fmaxf(h[i], 0.f);
        float o[4];
        #pragma unroll
        for (int i = 0; i < 4; i++) o[i] = sbb[lane + 32 * i];
        #pragma unroll
        for (int k = 0; k < 32; k++) {
            float a0 = __shfl_sync(0xffffffffu, h[0], k);
            float a1 = __shfl_sync(0xffffffffu, h[1], k);
            float a2 = __shfl_sync(0xffffffffu, h[2], k);
            float a3 = __shfl_sync(0xffffffffu, h[3], k);
            #pragma unroll
            for (int i = 0; i < 4; i++) {
                o[i] = fmaf(a0, sWb[k * EMB + lane + 32 * i], o[i]);
                o[i] = fmaf(a1, sWb[(k + 32) * EMB + lane + 32 * i], o[i]);
                o[i] = fmaf(a2, sWb[(k + 64) * EMB + lane + 32 * i], o[i]);
                o[i] = fmaf(a3, sWb[(k + 96) * EMB + lane + 32 * i], o[i]);
            }
        }
        int g = batch[n];
        #pragma unroll
        for (int i = 0; i < 4; i++) atomicAdd(&out[(long)g * EMB + lane + 32 * i], o[i]);
        if (lane == 0) atomicAdd(&g_cnt[g], 1);
    }
}

// ---------------------------------------------------------------------------
__global__ void div_kernel(float* __restrict__ out, int total) {
    int idx = blockIdx.x * blockDim.x + threadIdx.x;
    if (idx < total) {
        int g = idx >> 7;  // /EMB
        int c = g_cnt[g];
        out[idx] /= (float)(c > 0 ? c : 1);
    }
}

// ---------------------------------------------------------------------------
extern "C" void kernel_launch(void* const* d_in, const int* in_sizes, int n_in,
                              void* d_out, int out_size) {
    const float* x     = (const float*)d_in[0];
    const float* ea    = (const float*)d_in[1];
    const int*   ei    = (const int*)  d_in[2];
    const int*   batch = (const int*)  d_in[3];
    const float* el1_w = (const float*)d_in[4];
    const float* el1_b = (const float*)d_in[5];
    const float* w1a   = (const float*)d_in[6];
    const float* b1a   = (const float*)d_in[7];
    const float* w1b   = (const float*)d_in[8];
    const float* b1b   = (const float*)d_in[9];
    const float* el2_w = (const float*)d_in[10];
    const float* el2_b = (const float*)d_in[11];
    const float* w2a   = (const float*)d_in[12];
    const float* b2a   = (const float*)d_in[13];
    const float* w2b   = (const float*)d_in[14];
    const float* b2b   = (const float*)d_in[15];

    int N = in_sizes[0] / ND;
    int E = in_sizes[1] / ED;
    float* out = (float*)d_out;
    const int* src = ei;
    const int* dst = ei + E;

    zero_all<<<2048, 256>>>(out, (long)out_size, N);

    edge1_kernel<<<2368, 256>>>(x, ea, src, dst, el1_w, el1_b, E);
    mlp1_kernel<<<1184, 256>>>(x, w1a, b1a, w1b, b1b, N);

    edge2_kernel<<<2368, 256>>>(ea, src, dst, el2_w, el2_b, E);

    int smem = (HD * EMB + EMB * EMB + 2 * EMB) * (int)sizeof(float);  // ~99.3 KB
    cudaFuncSetAttribute(mlp2_kernel, cudaFuncAttributeMaxDynamicSharedMemorySize, smem);
    mlp2_kernel<<<296, 512, smem>>>(w2a, b2a, w2b, b2b, batch, out, N);

    div_kernel<<<(out_size + 255) / 256, 256>>>(out, out_size);
}

// round 2
// speedup vs baseline: 1.9418x; 1.9418x over previous
#include <cuda_runtime.h>

#define ND 44
#define ED 12
#define HD 64
#define EMB 128
#define NMAX 500000
#define GMAX 16384

// Scratch (__device__ globals per allocation-free rule)
__device__ float g_agg1[(size_t)NMAX * ND];   // 88 MB
__device__ float g_h1  [(size_t)NMAX * HD];   // 128 MB
__device__ float g_agg2[(size_t)NMAX * HD];   // 128 MB
__device__ int   g_cnt [GMAX];

__device__ __forceinline__ void red4(float* p, float a, float b, float c, float d) {
    asm volatile("red.global.add.v4.f32 [%0], {%1,%2,%3,%4};"
                 :: "l"(p), "f"(a), "f"(b), "f"(c), "f"(d) : "memory");
}

// ---------------------------------------------------------------------------
__global__ void zero_all(float* __restrict__ out, long n_out, int N) {
    long idx = (long)blockIdx.x * blockDim.x + threadIdx.x;
    long st  = (long)gridDim.x * blockDim.x;
    float4 z = make_float4(0.f, 0.f, 0.f, 0.f);
    long n1 = (long)N * ND / 4, n2 = (long)N * HD / 4;
    float4* a1 = (float4*)g_agg1;
    float4* a2 = (float4*)g_agg2;
    float4* ov = (float4*)out;
    for (long i = idx; i < n1; i += st) a1[i] = z;
    for (long i = idx; i < n2; i += st) a2[i] = z;
    for (long i = idx; i < n_out / 4; i += st) ov[i] = z;
    for (long i = idx; i < GMAX; i += st) g_cnt[i] = 0;
}

__global__ void count_kernel(const int* __restrict__ batch, int N) {
    int i = blockIdx.x * blockDim.x + threadIdx.x;
    if (i < N) atomicAdd(&g_cnt[batch[i]], 1);
}

// ---------------------------------------------------------------------------
// Edge pass layer 1: 11 threads per edge, each owns a float4 feature chunk.
// Weights (12x4 per chunk) live in registers. blockDim = 352 (32 edges/block).
__global__ void __launch_bounds__(352) edge1_kernel(
    const float* __restrict__ x, const float* __restrict__ ea,
    const int* __restrict__ src, const int* __restrict__ dst,
    const float* __restrict__ W, const float* __restrict__ b, int E) {
    int t = threadIdx.x;
    int grp = t / 11;
    int c = t - grp * 11;          // chunk 0..10 (features 4c..4c+3)
    float w[ED][4];
    #pragma unroll
    for (int k = 0; k < ED; k++) {
        float4 v = *(const float4*)(W + k * ND + 4 * c);
        w[k][0] = v.x; w[k][1] = v.y; w[k][2] = v.z; w[k][3] = v.w;
    }
    float4 bias = *(const float4*)(b + 4 * c);
    for (long e = (long)blockIdx.x * 32 + grp; e < E; e += (long)gridDim.x * 32) {
        int s = __ldg(src + e), d = __ldg(dst + e);
        float4 xv = *(const float4*)(x + (long)s * ND + 4 * c);
        float4 e0 = *(const float4*)(ea + e * ED);
        float4 e1 = *(const float4*)(ea + e * ED + 4);
        float4 e2 = *(const float4*)(ea + e * ED + 8);
        float eav[ED] = {e0.x, e0.y, e0.z, e0.w, e1.x, e1.y, e1.z, e1.w,
                         e2.x, e2.y, e2.z, e2.w};
        float m0 = bias.x, m1 = bias.y, m2 = bias.z, m3 = bias.w;
        #pragma unroll
        for (int k = 0; k < ED; k++) {
            m0 = fmaf(eav[k], w[k][0], m0);
            m1 = fmaf(eav[k], w[k][1], m1);
            m2 = fmaf(eav[k], w[k][2], m2);
            m3 = fmaf(eav[k], w[k][3], m3);
        }
        m0 = fmaxf(m0 + xv.x, 0.f); m1 = fmaxf(m1 + xv.y, 0.f);
        m2 = fmaxf(m2 + xv.z, 0.f); m3 = fmaxf(m3 + xv.w, 0.f);
        if (fmaxf(fmaxf(m0, m1), fmaxf(m2, m3)) > 0.f)
            red4(g_agg1 + (long)d * ND + 4 * c, m0, m1, m2, m3);
    }
}

// Edge pass layer 2: 16 threads per edge (HD=64). blockDim = 256.
__global__ void __launch_bounds__(256) edge2_kernel(
    const float* __restrict__ ea,
    const int* __restrict__ src, const int* __restrict__ dst,
    const float* __restrict__ W, const float* __restrict__ b, int E) {
    int t = threadIdx.x;
    int grp = t >> 4;
    int c = t & 15;
    float w[ED][4];
    #pragma unroll
    for (int k = 0; k < ED; k++) {
        float4 v = *(const float4*)(W + k * HD + 4 * c);
        w[k][0] = v.x; w[k][1] = v.y; w[k][2] = v.z; w[k][3] = v.w;
    }
    float4 bias = *(const float4*)(b + 4 * c);
    for (long e = (long)blockIdx.x * 16 + grp; e < E; e += (long)gridDim.x * 16) {
        int s = __ldg(src + e), d = __ldg(dst + e);
        float4 hv = *(const float4*)(g_h1 + (long)s * HD + 4 * c);
        float4 e0 = *(const float4*)(ea + e * ED);
        float4 e1 = *(const float4*)(ea + e * ED + 4);
        float4 e2 = *(const float4*)(ea + e * ED + 8);
        float eav[ED] = {e0.x, e0.y, e0.z, e0.w, e1.x, e1.y, e1.z, e1.w,
                         e2.x, e2.y, e2.z, e2.w};
        float m0 = bias.x, m1 = bias.y, m2 = bias.z, m3 = bias.w;
        #pragma unroll
        for (int k = 0; k < ED; k++) {
            m0 = fmaf(eav[k], w[k][0], m0);
            m1 = fmaf(eav[k], w[k][1], m1);
            m2 = fmaf(eav[k], w[k][2], m2);
            m3 = fmaf(eav[k], w[k][3], m3);
        }
        m0 = fmaxf(m0 + hv.x, 0.f); m1 = fmaxf(m1 + hv.y, 0.f);
        m2 = fmaxf(m2 + hv.z, 0.f); m3 = fmaxf(m3 + hv.w, 0.f);
        if (fmaxf(fmaxf(m0, m1), fmaxf(m2, m3)) > 0.f)
            red4(g_agg2 + (long)d * HD + 4 * c, m0, m1, m2, m3);
    }
}

// ---------------------------------------------------------------------------
// MLP1: h1 = relu( relu((x+agg1)@Wa+ba) @ Wb + bb ).
// Register-tiled GEMM: 64-node tiles, thread tile 4 nodes x 4 outs.
// Weights staged in smem once per block; grid-stride over tiles.
#define S1 68   // padded node-stride for Xt
__global__ void __launch_bounds__(256) mlp1_kernel(
    const float* __restrict__ x,
    const float* __restrict__ Wa, const float* __restrict__ ba,
    const float* __restrict__ Wb, const float* __restrict__ bb, int N) {
    extern __shared__ float sm[];
    float* sXt = sm;                 // [44][68]  X transposed
    float* sWa = sXt + ND * S1;      // [44][64]
    float* sH  = sWa + ND * HD;      // [64][68]  H in [node][j]
    float* sWb = sH + HD * S1;       // [64][64]
    float* sb1 = sWb + HD * HD;
    float* sb2 = sb1 + HD;
    int t = threadIdx.x;
    for (int i = t; i < ND * HD; i += 256) sWa[i] = Wa[i];
    for (int i = t; i < HD * HD; i += 256) sWb[i] = Wb[i];
    if (t < HD) { sb1[t] = ba[t]; sb2[t] = bb[t]; }
    int tx = t & 15, ty = t >> 4;    // j0 = 4*tx, n0 = 4*ty
    long ntiles = (N + 63) >> 6;
    for (long tile = blockIdx.x; tile < ntiles; tile += gridDim.x) {
        long n_base = tile * 64;
        __syncthreads();
        for (int i = t; i < 64 * ND; i += 256) {
            int n = i / ND, f = i - n * ND;
            long gn = n_base + n;
            float v = 0.f;
            if (gn < N) v = x[gn * ND + f] + g_agg1[gn * ND + f];
            sXt[f * S1 + n] = v;
        }
        __syncthreads();
        // stage 1: H[64x64] = relu(Xt^T @ Wa + b1)
        float acc[4][4];
        {
            float4 bv = *(float4*)(sb1 + 4 * tx);
            #pragma unroll
            for (int i = 0; i < 4; i++) {
                acc[i][0] = bv.x; acc[i][1] = bv.y; acc[i][2] = bv.z; acc[i][3] = bv.w;
            }
        }
        #pragma unroll 4
        for (int k = 0; k < ND; k++) {
            float4 xv = *(float4*)(sXt + k * S1 + 4 * ty);
            float4 wv = *(float4*)(sWa + k * HD + 4 * tx);
            float xs[4] = {xv.x, xv.y, xv.z, xv.w};
            float ws[4] = {wv.x, wv.y, wv.z, wv.w};
            #pragma unroll
            for (int i = 0; i < 4; i++)
                #pragma unroll
                for (int j = 0; j < 4; j++)
                    acc[i][j] = fmaf(xs[i], ws[j], acc[i][j]);
        }
        #pragma unroll
        for (int i = 0; i < 4; i++) {
            float4 hv = make_float4(fmaxf(acc[i][0], 0.f), fmaxf(acc[i][1], 0.f),
                                    fmaxf(acc[i][2], 0.f), fmaxf(acc[i][3], 0.f));
            *(float4*)(sH + (4 * ty + i) * S1 + 4 * tx) = hv;
        }
        __syncthreads();
        // stage 2: O = H @ Wb + b2, outer relu, store to g_h1
        float o[4][4];
        {
            float4 bv = *(float4*)(sb2 + 4 * tx);
            #pragma unroll
            for (int i = 0; i < 4; i++) {
                o[i][0] = bv.x; o[i][1] = bv.y; o[i][2] = bv.z; o[i][3] = bv.w;
            }
        }
        #pragma unroll 2
        for (int k = 0; k < HD; k += 2) {
            float2 h[4];
            #pragma unroll
            for (int i = 0; i < 4; i++)
                h[i] = *(float2*)(sH + (4 * ty + i) * S1 + k);
            float4 w0 = *(float4*)(sWb + k * HD + 4 * tx);
            float4 w1 = *(float4*)(sWb + (k + 1) * HD + 4 * tx);
            float w0s[4] = {w0.x, w0.y, w0.z, w0.w};
            float w1s[4] = {w1.x, w1.y, w1.z, w1.w};
            #pragma unroll
            for (int i = 0; i < 4; i++)
                #pragma unroll
                for (int j = 0; j < 4; j++) {
                    o[i][j] = fmaf(h[i].x, w0s[j], o[i][j]);
                    o[i][j] = fmaf(h[i].y, w1s[j], o[i][j]);
                }
        }
        #pragma unroll
        for (int i = 0; i < 4; i++) {
            long gn = n_base + 4 * ty + i;
            if (gn < N) {
                float4 v = make_float4(fmaxf(o[i][0], 0.f), fmaxf(o[i][1], 0.f),
                                       fmaxf(o[i][2], 0.f), fmaxf(o[i][3], 0.f));
                *(float4*)(g_h1 + gn * HD + 4 * tx) = v;
            }
        }
    }
}

// ---------------------------------------------------------------------------
// MLP2 + pooling: h2 = relu((h1+agg2)@Wa+ba)@Wb+bb; run-length-compressed
// v4 reductions into per-graph sums. 64-node tiles, thread tile 8n x 4j.
#define S2 68    // Xt node-stride
#define SH 132   // H row stride (j-major rows of 128 -> pad to 132)
__global__ void __launch_bounds__(256) mlp2_kernel(
    const float* __restrict__ Wa, const float* __restrict__ ba,
    const float* __restrict__ Wb, const float* __restrict__ bb,
    const int* __restrict__ batch, float* __restrict__ out, int N) {
    extern __shared__ float sm[];
    float* sXt = sm;                  // [64][68]
    float* sWa = sXt + HD * S2;       // [64][128]
    float* sH  = sWa + HD * EMB;      // [64][132]
    float* sWb = sH + 64 * SH;        // [128][128]
    float* sb1 = sWb + EMB * EMB;
    float* sb2 = sb1 + EMB;
    int t = threadIdx.x;
    for (int i = t; i < HD * EMB; i += 256) sWa[i] = Wa[i];
    for (int i = t; i < EMB * EMB; i += 256) sWb[i] = Wb[i];
    if (t < EMB) { sb1[t] = ba[t]; sb2[t] = bb[t]; }
    int tx = t & 31, ty = t >> 5;     // j0 = 4*tx (128), n0 = 8*ty (64)
    long ntiles = (N + 63) >> 6;
    for (long tile = blockIdx.x; tile < ntiles; tile += gridDim.x) {
        long n_base = tile * 64;
        __syncthreads();
        for (int i = t; i < 64 * HD; i += 256) {
            int n = i >> 6, f = i & 63;
            long gn = n_base + n;
            float v = 0.f;
            if (gn < N) v = g_h1[gn * HD + f] + g_agg2[gn * HD + f];
            sXt[f * S2 + n] = v;
        }
        __syncthreads();
        // stage 1: H[64x128] = relu(X @ Wa + b1)
        float acc[8][4];
        {
            float4 bv = *(float4*)(sb1 + 4 * tx);
            #pragma unroll
            for (int i = 0; i < 8; i++) {
                acc[i][0] = bv.x; acc[i][1] = bv.y; acc[i][2] = bv.z; acc[i][3] = bv.w;
            }
        }
        #pragma unroll 2
        for (int k = 0; k < HD; k++) {
            float4 x0 = *(float4*)(sXt + k * S2 + 8 * ty);
            float4 x1 = *(float4*)(sXt + k * S2 + 8 * ty + 4);
            float4 wv = *(float4*)(sWa + k * EMB + 4 * tx);
            float xs[8] = {x0.x, x0.y, x0.z, x0.w, x1.x, x1.y, x1.z, x1.w};
            float ws[4] = {wv.x, wv.y, wv.z, wv.w};
            #pragma unroll
            for (int i = 0; i < 8; i++)
                #pragma unroll
                for (int j = 0; j < 4; j++)
                    acc[i][j] = fmaf(xs[i], ws[j], acc[i][j]);
        }
        #pragma unroll
        for (int i = 0; i < 8; i++) {
            float4 hv = make_float4(fmaxf(acc[i][0], 0.f), fmaxf(acc[i][1], 0.f),
                                    fmaxf(acc[i][2], 0.f), fmaxf(acc[i][3], 0.f));
            *(float4*)(sH + (8 * ty + i) * SH + 4 * tx) = hv;
        }
        __syncthreads();
        // stage 2: O = H @ Wb + b2
        float o[8][4];
        {
            float4 bv = *(float4*)(sb2 + 4 * tx);
            #pragma unroll
            for (int i = 0; i < 8; i++) {
                o[i][0] = bv.x; o[i][1] = bv.y; o[i][2] = bv.z; o[i][3] = bv.w;
            }
        }
        #pragma unroll 2
        for (int k = 0; k < EMB; k += 2) {
            float2 h[8];
            #pragma unroll
            for (int i = 0; i < 8; i++)
                h[i] = *(float2*)(sH + (8 * ty + i) * SH + k);
            float4 w0 = *(float4*)(sWb + k * EMB + 4 * tx);
            float4 w1 = *(float4*)(sWb + (k + 1) * EMB + 4 * tx);
            float w0s[4] = {w0.x, w0.y, w0.z, w0.w};
            float w1s[4] = {w1.x, w1.y, w1.z, w1.w};
            #pragma unroll
            for (int i = 0; i < 8; i++)
                #pragma unroll
                for (int j = 0; j < 4; j++) {
                    o[i][j] = fmaf(h[i].x, w0s[j], o[i][j]);
                    o[i][j] = fmaf(h[i].y, w1s[j], o[i][j]);
                }
        }
        // pooled epilogue: run-length over sorted batch, v4 reductions
        int cur = -1;
        float p0 = 0.f, p1 = 0.f, p2 = 0.f, p3 = 0.f;
        #pragma unroll
        for (int i = 0; i < 8; i++) {
            long gn = n_base + 8 * ty + i;
            if (gn < N) {
                int g = __ldg(batch + gn);
                if (g != cur) {
                    if (cur >= 0)
                        red4(out + (long)cur * EMB + 4 * tx, p0, p1, p2, p3);
                    cur = g; p0 = p1 = p2 = p3 = 0.f;
                }
                p0 += o[i][0]; p1 += o[i][1]; p2 += o[i][2]; p3 += o[i][3];
            }
        }
        if (cur >= 0)
            red4(out + (long)cur * EMB + 4 * tx, p0, p1, p2, p3);
    }
}

// ---------------------------------------------------------------------------
__global__ void div_kernel(float* __restrict__ out, int total) {
    int idx = blockIdx.x * blockDim.x + threadIdx.x;
    if (idx < total) {
        int g = idx >> 7;
        int c = g_cnt[g];
        out[idx] *= (1.0f / (float)(c > 0 ? c : 1));
    }
}

// ---------------------------------------------------------------------------
extern "C" void kernel_launch(void* const* d_in, const int* in_sizes, int n_in,
                              void* d_out, int out_size) {
    const float* x     = (const float*)d_in[0];
    const float* ea    = (const float*)d_in[1];
    const int*   ei    = (const int*)  d_in[2];
    const int*   batch = (const int*)  d_in[3];
    const float* el1_w = (const float*)d_in[4];
    const float* el1_b = (const float*)d_in[5];
    const float* w1a   = (const float*)d_in[6];
    const float* b1a   = (const float*)d_in[7];
    const float* w1b   = (const float*)d_in[8];
    const float* b1b   = (const float*)d_in[9];
    const float* el2_w = (const float*)d_in[10];
    const float* el2_b = (const float*)d_in[11];
    const float* w2a   = (const float*)d_in[12];
    const float* b2a   = (const float*)d_in[13];
    const float* w2b   = (const float*)d_in[14];
    const float* b2b   = (const float*)d_in[15];

    int N = in_sizes[0] / ND;
    int E = in_sizes[1] / ED;
    float* out = (float*)d_out;
    const int* src = ei;
    const int* dst = ei + E;

    zero_all<<<2048, 256>>>(out, (long)out_size, N);
    count_kernel<<<(N + 255) / 256, 256>>>(batch, N);

    edge1_kernel<<<2048, 352>>>(x, ea, src, dst, el1_w, el1_b, E);

    int smem1 = (ND * S1 + ND * HD + HD * S1 + HD * HD + 2 * HD) * (int)sizeof(float);
    cudaFuncSetAttribute(mlp1_kernel, cudaFuncAttributeMaxDynamicSharedMemorySize, smem1);
    mlp1_kernel<<<444, 256, smem1>>>(x, w1a, b1a, w1b, b1b, N);

    edge2_kernel<<<2048, 256>>>(ea, src, dst, el2_w, el2_b, E);

    int smem2 = (HD * S2 + HD * EMB + 64 * SH + EMB * EMB + 2 * EMB) * (int)sizeof(float);
    cudaFuncSetAttribute(mlp2_kernel, cudaFuncAttributeMaxDynamicSharedMemorySize, smem2);
    mlp2_kernel<<<296, 256, smem2>>>(w2a, b2a, w2b, b2b, batch, out, N);

    div_kernel<<<(out_size + 255) / 256, 256>>>(out, out_size);
}

// round 3
// speedup vs baseline: 2.0773x; 1.0698x over previous
#include <cuda_runtime.h>

#define ND 44
#define ED 12
#define HD 64
#define EMB 128
#define NMAX 500000
#define GMAX 16384

// Scratch (__device__ globals per allocation-free rule)
__device__ float g_agg1[(size_t)NMAX * ND];   // 88 MB
__device__ float g_h1  [(size_t)NMAX * HD];   // 128 MB
__device__ float g_agg2[(size_t)NMAX * HD];   // 128 MB
__device__ int   g_cnt [GMAX];

__device__ __forceinline__ void red4(float* p, float a, float b, float c, float d) {
    asm volatile("red.global.add.v4.f32 [%0], {%1,%2,%3,%4};"
                 :: "l"(p), "f"(a), "f"(b), "f"(c), "f"(d) : "memory");
}

// ---------------------------------------------------------------------------
__global__ void zero_all(float* __restrict__ out, long n_out, int N) {
    long idx = (long)blockIdx.x * blockDim.x + threadIdx.x;
    long st  = (long)gridDim.x * blockDim.x;
    float4 z = make_float4(0.f, 0.f, 0.f, 0.f);
    long n1 = (long)N * ND / 4, n2 = (long)N * HD / 4;
    float4* a1 = (float4*)g_agg1;
    float4* a2 = (float4*)g_agg2;
    float4* ov = (float4*)out;
    for (long i = idx; i < n1; i += st) a1[i] = z;
    for (long i = idx; i < n2; i += st) a2[i] = z;
    for (long i = idx; i < n_out / 4; i += st) ov[i] = z;
    for (long i = idx; i < GMAX; i += st) g_cnt[i] = 0;
}

__global__ void count_kernel(const int* __restrict__ batch, int N) {
    int i = blockIdx.x * blockDim.x + threadIdx.x;
    if (i < N) atomicAdd(&g_cnt[batch[i]], 1);
}

// ---------------------------------------------------------------------------
// Edge pass layer 1: 11 threads per edge, each owns a float4 feature chunk.
__global__ void __launch_bounds__(352) edge1_kernel(
    const float* __restrict__ x, const float* __restrict__ ea,
    const int* __restrict__ src, const int* __restrict__ dst,
    const float* __restrict__ W, const float* __restrict__ b, int E) {
    int t = threadIdx.x;
    int grp = t / 11;
    int c = t - grp * 11;          // chunk 0..10 (features 4c..4c+3)
    float w[ED][4];
    #pragma unroll
    for (int k = 0; k < ED; k++) {
        float4 v = *(const float4*)(W + k * ND + 4 * c);
        w[k][0] = v.x; w[k][1] = v.y; w[k][2] = v.z; w[k][3] = v.w;
    }
    float4 bias = *(const float4*)(b + 4 * c);
    for (long e = (long)blockIdx.x * 32 + grp; e < E; e += (long)gridDim.x * 32) {
        int s = __ldg(src + e), d = __ldg(dst + e);
        float4 xv = *(const float4*)(x + (long)s * ND + 4 * c);
        float4 e0 = *(const float4*)(ea + e * ED);
        float4 e1 = *(const float4*)(ea + e * ED + 4);
        float4 e2 = *(const float4*)(ea + e * ED + 8);
        float eav[ED] = {e0.x, e0.y, e0.z, e0.w, e1.x, e1.y, e1.z, e1.w,
                         e2.x, e2.y, e2.z, e2.w};
        float m0 = bias.x, m1 = bias.y, m2 = bias.z, m3 = bias.w;
        #pragma unroll
        for (int k = 0; k < ED; k++) {
            m0 = fmaf(eav[k], w[k][0], m0);
            m1 = fmaf(eav[k], w[k][1], m1);
            m2 = fmaf(eav[k], w[k][2], m2);
            m3 = fmaf(eav[k], w[k][3], m3);
        }
        m0 = fmaxf(m0 + xv.x, 0.f); m1 = fmaxf(m1 + xv.y, 0.f);
        m2 = fmaxf(m2 + xv.z, 0.f); m3 = fmaxf(m3 + xv.w, 0.f);
        if (fmaxf(fmaxf(m0, m1), fmaxf(m2, m3)) > 0.f)
            red4(g_agg1 + (long)d * ND + 4 * c, m0, m1, m2, m3);
    }
}

// Edge pass layer 2: 16 threads per edge (HD=64).
__global__ void __launch_bounds__(256) edge2_kernel(
    const float* __restrict__ ea,
    const int* __restrict__ src, const int* __restrict__ dst,
    const float* __restrict__ W, const float* __restrict__ b, int E) {
    int t = threadIdx.x;
    int grp = t >> 4;
    int c = t & 15;
    float w[ED][4];
    #pragma unroll
    for (int k = 0; k < ED; k++) {
        float4 v = *(const float4*)(W + k * HD + 4 * c);
        w[k][0] = v.x; w[k][1] = v.y; w[k][2] = v.z; w[k][3] = v.w;
    }
    float4 bias = *(const float4*)(b + 4 * c);
    for (long e = (long)blockIdx.x * 16 + grp; e < E; e += (long)gridDim.x * 16) {
        int s = __ldg(src + e), d = __ldg(dst + e);
        float4 hv = *(const float4*)(g_h1 + (long)s * HD + 4 * c);
        float4 e0 = *(const float4*)(ea + e * ED);
        float4 e1 = *(const float4*)(ea + e * ED + 4);
        float4 e2 = *(const float4*)(ea + e * ED + 8);
        float eav[ED] = {e0.x, e0.y, e0.z, e0.w, e1.x, e1.y, e1.z, e1.w,
                         e2.x, e2.y, e2.z, e2.w};
        float m0 = bias.x, m1 = bias.y, m2 = bias.z, m3 = bias.w;
        #pragma unroll
        for (int k = 0; k < ED; k++) {
            m0 = fmaf(eav[k], w[k][0], m0);
            m1 = fmaf(eav[k], w[k][1], m1);
            m2 = fmaf(eav[k], w[k][2], m2);
            m3 = fmaf(eav[k], w[k][3], m3);
        }
        m0 = fmaxf(m0 + hv.x, 0.f); m1 = fmaxf(m1 + hv.y, 0.f);
        m2 = fmaxf(m2 + hv.z, 0.f); m3 = fmaxf(m3 + hv.w, 0.f);
        if (fmaxf(fmaxf(m0, m1), fmaxf(m2, m3)) > 0.f)
            red4(g_agg2 + (long)d * HD + 4 * c, m0, m1, m2, m3);
    }
}

// ---------------------------------------------------------------------------
// MLP1: h1 = relu( relu((x+agg1)@Wa+ba) @ Wb + bb ).
// 256-node x 64-j tiles, 8x8 thread tiles (1.0 B LDS per FMA).
#define T1N 256
#define S1 260   // padded node-stride
__global__ void __launch_bounds__(256, 1) mlp1_kernel(
    const float* __restrict__ x,
    const float* __restrict__ Wa, const float* __restrict__ ba,
    const float* __restrict__ Wb, const float* __restrict__ bb, int N) {
    extern __shared__ float sm[];
    float* sXt = sm;                  // [44][260]
    float* sWa = sXt + ND * S1;       // [44][64]
    float* sHt = sWa + ND * HD;       // [64][260]  H transposed (k x n)
    float* sWb = sHt + HD * S1;       // [64][64]
    float* sb1 = sWb + HD * HD;
    float* sb2 = sb1 + HD;
    int t = threadIdx.x;
    for (int i = t; i < ND * HD; i += 256) sWa[i] = Wa[i];
    for (int i = t; i < HD * HD; i += 256) sWb[i] = Wb[i];
    if (t < HD) { sb1[t] = ba[t]; sb2[t] = bb[t]; }
    int tx = t & 7, ty = t >> 3;      // j0 = 8*tx (64), n0 = 8*ty (256)
    int j0 = 8 * tx, n0 = 8 * ty;
    long ntiles = (N + T1N - 1) / T1N;
    for (long tile = blockIdx.x; tile < ntiles; tile += gridDim.x) {
        long n_base = tile * T1N;
        __syncthreads();
        // stage X (transposed) : 256 nodes x 44 feats, float4 gmem reads
        for (int i = t; i < T1N * (ND / 4); i += 256) {
            int n = i / (ND / 4), c = i - n * (ND / 4);
            long gn = n_base + n;
            float4 v = make_float4(0.f, 0.f, 0.f, 0.f);
            if (gn < N) {
                float4 a = *(const float4*)(x + gn * ND + 4 * c);
                float4 bq = *(const float4*)(g_agg1 + gn * ND + 4 * c);
                v = make_float4(a.x + bq.x, a.y + bq.y, a.z + bq.z, a.w + bq.w);
            }
            sXt[(4 * c + 0) * S1 + n] = v.x;
            sXt[(4 * c + 1) * S1 + n] = v.y;
            sXt[(4 * c + 2) * S1 + n] = v.z;
            sXt[(4 * c + 3) * S1 + n] = v.w;
        }
        __syncthreads();
        // stage 1: Ht[j][n] = relu( sum_k Xt[k][n] * Wa[k][j] + b1[j] )
        float acc[8][8];
        #pragma unroll
        for (int j = 0; j < 8; j++) {
            float bj = sb1[j0 + j];
            #pragma unroll
            for (int i = 0; i < 8; i++) acc[i][j] = bj;
        }
        #pragma unroll 4
        for (int k = 0; k < ND; k++) {
            float4 x0 = *(float4*)(sXt + k * S1 + n0);
            float4 x1 = *(float4*)(sXt + k * S1 + n0 + 4);
            float4 w0 = *(float4*)(sWa + k * HD + j0);
            float4 w1 = *(float4*)(sWa + k * HD + j0 + 4);
            float xs[8] = {x0.x, x0.y, x0.z, x0.w, x1.x, x1.y, x1.z, x1.w};
            float ws[8] = {w0.x, w0.y, w0.z, w0.w, w1.x, w1.y, w1.z, w1.w};
            #pragma unroll
            for (int i = 0; i < 8; i++)
                #pragma unroll
                for (int j = 0; j < 8; j++)
                    acc[i][j] = fmaf(xs[i], ws[j], acc[i][j]);
        }
        #pragma unroll
        for (int j = 0; j < 8; j++) {
            float4 h0 = make_float4(fmaxf(acc[0][j], 0.f), fmaxf(acc[1][j], 0.f),
                                    fmaxf(acc[2][j], 0.f), fmaxf(acc[3][j], 0.f));
            float4 h1 = make_float4(fmaxf(acc[4][j], 0.f), fmaxf(acc[5][j], 0.f),
                                    fmaxf(acc[6][j], 0.f), fmaxf(acc[7][j], 0.f));
            *(float4*)(sHt + (j0 + j) * S1 + n0) = h0;
            *(float4*)(sHt + (j0 + j) * S1 + n0 + 4) = h1;
        }
        __syncthreads();
        // stage 2: O[n][j] = relu( sum_k Ht[k][n] * Wb[k][j] + b2[j] )
        float o[8][8];
        #pragma unroll
        for (int j = 0; j < 8; j++) {
            float bj = sb2[j0 + j];
            #pragma unroll
            for (int i = 0; i < 8; i++) o[i][j] = bj;
        }
        #pragma unroll 4
        for (int k = 0; k < HD; k++) {
            float4 h0 = *(float4*)(sHt + k * S1 + n0);
            float4 h1 = *(float4*)(sHt + k * S1 + n0 + 4);
            float4 w0 = *(float4*)(sWb + k * HD + j0);
            float4 w1 = *(float4*)(sWb + k * HD + j0 + 4);
            float hs[8] = {h0.x, h0.y, h0.z, h0.w, h1.x, h1.y, h1.z, h1.w};
            float ws[8] = {w0.x, w0.y, w0.z, w0.w, w1.x, w1.y, w1.z, w1.w};
            #pragma unroll
            for (int i = 0; i < 8; i++)
                #pragma unroll
                for (int j = 0; j < 8; j++)
                    o[i][j] = fmaf(hs[i], ws[j], o[i][j]);
        }
        #pragma unroll
        for (int i = 0; i < 8; i++) {
            long gn = n_base + n0 + i;
            if (gn < N) {
                float4 v0 = make_float4(fmaxf(o[i][0], 0.f), fmaxf(o[i][1], 0.f),
                                        fmaxf(o[i][2], 0.f), fmaxf(o[i][3], 0.f));
                float4 v1 = make_float4(fmaxf(o[i][4], 0.f), fmaxf(o[i][5], 0.f),
                                        fmaxf(o[i][6], 0.f), fmaxf(o[i][7], 0.f));
                *(float4*)(g_h1 + gn * HD + j0) = v0;
                *(float4*)(g_h1 + gn * HD + j0 + 4) = v1;
            }
        }
    }
}

// ---------------------------------------------------------------------------
// MLP2 + pooling: 128-node x 128-j tiles, 8x8 thread tiles.
#define T2N 128
#define S2 132
__global__ void __launch_bounds__(256, 1) mlp2_kernel(
    const float* __restrict__ Wa, const float* __restrict__ ba,
    const float* __restrict__ Wb, const float* __restrict__ bb,
    const int* __restrict__ batch, float* __restrict__ out, int N) {
    extern __shared__ float sm[];
    float* sXt = sm;                  // [64][132]
    float* sWa = sXt + HD * S2;       // [64][128]
    float* sHt = sWa + HD * EMB;      // [128][132]  (k x n)
    float* sWb = sHt + EMB * S2;      // [128][128]
    float* sb1 = sWb + EMB * EMB;
    float* sb2 = sb1 + EMB;
    int t = threadIdx.x;
    for (int i = t; i < HD * EMB; i += 256) sWa[i] = Wa[i];
    for (int i = t; i < EMB * EMB; i += 256) sWb[i] = Wb[i];
    if (t < EMB) { sb1[t] = ba[t]; sb2[t] = bb[t]; }
    int tx = t & 15, ty = t >> 4;     // j0 = 8*tx (128), n0 = 8*ty (128)
    int j0 = 8 * tx, n0 = 8 * ty;
    long ntiles = (N + T2N - 1) / T2N;
    for (long tile = blockIdx.x; tile < ntiles; tile += gridDim.x) {
        long n_base = tile * T2N;
        __syncthreads();
        for (int i = t; i < T2N * (HD / 4); i += 256) {
            int n = i >> 4, c = i & 15;
            long gn = n_base + n;
            float4 v = make_float4(0.f, 0.f, 0.f, 0.f);
            if (gn < N) {
                float4 a = *(const float4*)(g_h1 + gn * HD + 4 * c);
                float4 bq = *(const float4*)(g_agg2 + gn * HD + 4 * c);
                v = make_float4(a.x + bq.x, a.y + bq.y, a.z + bq.z, a.w + bq.w);
            }
            sXt[(4 * c + 0) * S2 + n] = v.x;
            sXt[(4 * c + 1) * S2 + n] = v.y;
            sXt[(4 * c + 2) * S2 + n] = v.z;
            sXt[(4 * c + 3) * S2 + n] = v.w;
        }
        __syncthreads();
        // stage 1: Ht[j][n] = relu( sum_k Xt[k][n]*Wa[k][j] + b1[j] )
        float acc[8][8];
        #pragma unroll
        for (int j = 0; j < 8; j++) {
            float bj = sb1[j0 + j];
            #pragma unroll
            for (int i = 0; i < 8; i++) acc[i][j] = bj;
        }
        #pragma unroll 4
        for (int k = 0; k < HD; k++) {
            float4 x0 = *(float4*)(sXt + k * S2 + n0);
            float4 x1 = *(float4*)(sXt + k * S2 + n0 + 4);
            float4 w0 = *(float4*)(sWa + k * EMB + j0);
            float4 w1 = *(float4*)(sWa + k * EMB + j0 + 4);
            float xs[8] = {x0.x, x0.y, x0.z, x0.w, x1.x, x1.y, x1.z, x1.w};
            float ws[8] = {w0.x, w0.y, w0.z, w0.w, w1.x, w1.y, w1.z, w1.w};
            #pragma unroll
            for (int i = 0; i < 8; i++)
                #pragma unroll
                for (int j = 0; j < 8; j++)
                    acc[i][j] = fmaf(xs[i], ws[j], acc[i][j]);
        }
        #pragma unroll
        for (int j = 0; j < 8; j++) {
            float4 h0 = make_float4(fmaxf(acc[0][j], 0.f), fmaxf(acc[1][j], 0.f),
                                    fmaxf(acc[2][j], 0.f), fmaxf(acc[3][j], 0.f));
            float4 h1 = make_float4(fmaxf(acc[4][j], 0.f), fmaxf(acc[5][j], 0.f),
                                    fmaxf(acc[6][j], 0.f), fmaxf(acc[7][j], 0.f));
            *(float4*)(sHt + (j0 + j) * S2 + n0) = h0;
            *(float4*)(sHt + (j0 + j) * S2 + n0 + 4) = h1;
        }
        __syncthreads();
        // stage 2: O[n][j] = sum_k Ht[k][n]*Wb[k][j] + b2[j]
        float o[8][8];
        #pragma unroll
        for (int j = 0; j < 8; j++) {
            float bj = sb2[j0 + j];
            #pragma unroll
            for (int i = 0; i < 8; i++) o[i][j] = bj;
        }
        #pragma unroll 4
        for (int k = 0; k < EMB; k++) {
            float4 h0 = *(float4*)(sHt + k * S2 + n0);
            float4 h1 = *(float4*)(sHt + k * S2 + n0 + 4);
            float4 w0 = *(float4*)(sWb + k * EMB + j0);
            float4 w1 = *(float4*)(sWb + k * EMB + j0 + 4);
            float hs[8] = {h0.x, h0.y, h0.z, h0.w, h1.x, h1.y, h1.z, h1.w};
            float ws[8] = {w0.x, w0.y, w0.z, w0.w, w1.x, w1.y, w1.z, w1.w};
            #pragma unroll
            for (int i = 0; i < 8; i++)
                #pragma unroll
                for (int j = 0; j < 8; j++)
                    o[i][j] = fmaf(hs[i], ws[j], o[i][j]);
        }
        // pooled epilogue: run-length over sorted batch, v4 reductions (2x)
        int cur = -1;
        float p[8];
        #pragma unroll
        for (int j = 0; j < 8; j++) p[j] = 0.f;
        #pragma unroll
        for (int i = 0; i < 8; i++) {
            long gn = n_base + n0 + i;
            if (gn < N) {
                int g = __ldg(batch + gn);
                if (g != cur) {
                    if (cur >= 0) {
                        red4(out + (long)cur * EMB + j0,     p[0], p[1], p[2], p[3]);
                        red4(out + (long)cur * EMB + j0 + 4, p[4], p[5], p[6], p[7]);
                    }
                    cur = g;
                    #pragma unroll
                    for (int j = 0; j < 8; j++) p[j] = 0.f;
                }
                #pragma unroll
                for (int j = 0; j < 8; j++) p[j] += o[i][j];
            }
        }
        if (cur >= 0) {
            red4(out + (long)cur * EMB + j0,     p[0], p[1], p[2], p[3]);
            red4(out + (long)cur * EMB + j0 + 4, p[4], p[5], p[6], p[7]);
        }
    }
}

// ---------------------------------------------------------------------------
__global__ void div_kernel(float* __restrict__ out, int total) {
    int idx = blockIdx.x * blockDim.x + threadIdx.x;
    if (idx < total) {
        int g = idx >> 7;
        int c = g_cnt[g];
        out[idx] *= (1.0f / (float)(c > 0 ? c : 1));
    }
}

// ---------------------------------------------------------------------------
extern "C" void kernel_launch(void* const* d_in, const int* in_sizes, int n_in,
                              void* d_out, int out_size) {
    const float* x     = (const float*)d_in[0];
    const float* ea    = (const float*)d_in[1];
    const int*   ei    = (const int*)  d_in[2];
    const int*   batch = (const int*)  d_in[3];
    const float* el1_w = (const float*)d_in[4];
    const float* el1_b = (const float*)d_in[5];
    const float* w1a   = (const float*)d_in[6];
    const float* b1a   = (const float*)d_in[7];
    const float* w1b   = (const float*)d_in[8];
    const float* b1b   = (const float*)d_in[9];
    const float* el2_w = (const float*)d_in[10];
    const float* el2_b = (const float*)d_in[11];
    const float* w2a   = (const float*)d_in[12];
    const float* b2a   = (const float*)d_in[13];
    const float* w2b   = (const float*)d_in[14];
    const float* b2b   = (const float*)d_in[15];

    int N = in_sizes[0] / ND;
    int E = in_sizes[1] / ED;
    float* out = (float*)d_out;
    const int* src = ei;
    const int* dst = ei + E;

    zero_all<<<2048, 256>>>(out, (long)out_size, N);
    count_kernel<<<(N + 255) / 256, 256>>>(batch, N);

    edge1_kernel<<<2048, 352>>>(x, ea, src, dst, el1_w, el1_b, E);

    int smem1 = (ND * S1 + ND * HD + HD * S1 + HD * HD + 2 * HD) * (int)sizeof(float);
    cudaFuncSetAttribute(mlp1_kernel, cudaFuncAttributeMaxDynamicSharedMemorySize, smem1);
    mlp1_kernel<<<148, 256, smem1>>>(x, w1a, b1a, w1b, b1b, N);

    edge2_kernel<<<2048, 256>>>(ea, src, dst, el2_w, el2_b, E);

    int smem2 = (HD * S2 + HD * EMB + EMB * S2 + EMB * EMB + 2 * EMB) * (int)sizeof(float);
    cudaFuncSetAttribute(mlp2_kernel, cudaFuncAttributeMaxDynamicSharedMemorySize, smem2);
    mlp2_kernel<<<148, 256, smem2>>>(w2a, b2a, w2b, b2b, batch, out, N);

    div_kernel<<<(out_size + 255) / 256, 256>>>(out, out_size);
}

// round 4
// speedup vs baseline: 2.0796x; 1.0011x over previous
#include <cuda_runtime.h>

#define ND 44
#define ED 12
#define HD 64
#define EMB 128
#define NMAX 500000
#define GMAX 16384

// Scratch (__device__ globals per allocation-free rule)
__device__ float g_agg1[(size_t)NMAX * ND];   // 88 MB
__device__ float g_h1  [(size_t)NMAX * HD];   // 128 MB
__device__ float g_agg2[(size_t)NMAX * HD];   // 128 MB
__device__ int   g_cnt [GMAX];

__device__ __forceinline__ void red4(float* p, float a, float b, float c, float d) {
    asm volatile("red.global.add.v4.f32 [%0], {%1,%2,%3,%4};"
                 :: "l"(p), "f"(a), "f"(b), "f"(c), "f"(d) : "memory");
}

// ---------------------------------------------------------------------------
__global__ void zero_all(float* __restrict__ out, long n_out, int N) {
    long idx = (long)blockIdx.x * blockDim.x + threadIdx.x;
    long st  = (long)gridDim.x * blockDim.x;
    float4 z = make_float4(0.f, 0.f, 0.f, 0.f);
    long n1 = (long)N * ND / 4, n2 = (long)N * HD / 4;
    float4* a1 = (float4*)g_agg1;
    float4* a2 = (float4*)g_agg2;
    float4* ov = (float4*)out;
    for (long i = idx; i < n1; i += st) a1[i] = z;
    for (long i = idx; i < n2; i += st) a2[i] = z;
    for (long i = idx; i < n_out / 4; i += st) ov[i] = z;
    for (long i = idx; i < GMAX; i += st) g_cnt[i] = 0;
}

__global__ void count_kernel(const int* __restrict__ batch, int N) {
    int i = blockIdx.x * blockDim.x + threadIdx.x;
    if (i < N) atomicAdd(&g_cnt[batch[i]], 1);
}

// ---------------------------------------------------------------------------
// Edge pass layer 1: 11 threads per edge, each owns a float4 feature chunk.
__global__ void __launch_bounds__(352) edge1_kernel(
    const float* __restrict__ x, const float* __restrict__ ea,
    const int* __restrict__ src, const int* __restrict__ dst,
    const float* __restrict__ W, const float* __restrict__ b, int E) {
    int t = threadIdx.x;
    int grp = t / 11;
    int c = t - grp * 11;          // chunk 0..10 (features 4c..4c+3)
    float w[ED][4];
    #pragma unroll
    for (int k = 0; k < ED; k++) {
        float4 v = *(const float4*)(W + k * ND + 4 * c);
        w[k][0] = v.x; w[k][1] = v.y; w[k][2] = v.z; w[k][3] = v.w;
    }
    float4 bias = *(const float4*)(b + 4 * c);
    for (long e = (long)blockIdx.x * 32 + grp; e < E; e += (long)gridDim.x * 32) {
        int s = __ldg(src + e), d = __ldg(dst + e);
        float4 xv = *(const float4*)(x + (long)s * ND + 4 * c);
        float4 e0 = *(const float4*)(ea + e * ED);
        float4 e1 = *(const float4*)(ea + e * ED + 4);
        float4 e2 = *(const float4*)(ea + e * ED + 8);
        float eav[ED] = {e0.x, e0.y, e0.z, e0.w, e1.x, e1.y, e1.z, e1.w,
                         e2.x, e2.y, e2.z, e2.w};
        float m0 = bias.x, m1 = bias.y, m2 = bias.z, m3 = bias.w;
        #pragma unroll
        for (int k = 0; k < ED; k++) {
            m0 = fmaf(eav[k], w[k][0], m0);
            m1 = fmaf(eav[k], w[k][1], m1);
            m2 = fmaf(eav[k], w[k][2], m2);
            m3 = fmaf(eav[k], w[k][3], m3);
        }
        m0 = fmaxf(m0 + xv.x, 0.f); m1 = fmaxf(m1 + xv.y, 0.f);
        m2 = fmaxf(m2 + xv.z, 0.f); m3 = fmaxf(m3 + xv.w, 0.f);
        if (fmaxf(fmaxf(m0, m1), fmaxf(m2, m3)) > 0.f)
            red4(g_agg1 + (long)d * ND + 4 * c, m0, m1, m2, m3);
    }
}

// Edge pass layer 2: 16 threads per edge (HD=64).
__global__ void __launch_bounds__(256) edge2_kernel(
    const float* __restrict__ ea,
    const int* __restrict__ src, const int* __restrict__ dst,
    const float* __restrict__ W, const float* __restrict__ b, int E) {
    int t = threadIdx.x;
    int grp = t >> 4;
    int c = t & 15;
    float w[ED][4];
    #pragma unroll
    for (int k = 0; k < ED; k++) {
        float4 v = *(const float4*)(W + k * HD + 4 * c);
        w[k][0] = v.x; w[k][1] = v.y; w[k][2] = v.z; w[k][3] = v.w;
    }
    float4 bias = *(const float4*)(b + 4 * c);
    for (long e = (long)blockIdx.x * 16 + grp; e < E; e += (long)gridDim.x * 16) {
        int s = __ldg(src + e), d = __ldg(dst + e);
        float4 hv = *(const float4*)(g_h1 + (long)s * HD + 4 * c);
        float4 e0 = *(const float4*)(ea + e * ED);
        float4 e1 = *(const float4*)(ea + e * ED + 4);
        float4 e2 = *(const float4*)(ea + e * ED + 8);
        float eav[ED] = {e0.x, e0.y, e0.z, e0.w, e1.x, e1.y, e1.z, e1.w,
                         e2.x, e2.y, e2.z, e2.w};
        float m0 = bias.x, m1 = bias.y, m2 = bias.z, m3 = bias.w;
        #pragma unroll
        for (int k = 0; k < ED; k++) {
            m0 = fmaf(eav[k], w[k][0], m0);
            m1 = fmaf(eav[k], w[k][1], m1);
            m2 = fmaf(eav[k], w[k][2], m2);
            m3 = fmaf(eav[k], w[k][3], m3);
        }
        m0 = fmaxf(m0 + hv.x, 0.f); m1 = fmaxf(m1 + hv.y, 0.f);
        m2 = fmaxf(m2 + hv.z, 0.f); m3 = fmaxf(m3 + hv.w, 0.f);
        if (fmaxf(fmaxf(m0, m1), fmaxf(m2, m3)) > 0.f)
            red4(g_agg2 + (long)d * HD + 4 * c, m0, m1, m2, m3);
    }
}

// ---------------------------------------------------------------------------
// MLP1: h1 = relu( relu((x+agg1)@Wa+ba) @ Wb + bb ).
// 256-node x 64-j tiles, 8x8 thread tiles (1.0 B LDS per FMA).
#define T1N 256
#define S1 260   // padded node-stride
__global__ void __launch_bounds__(256, 1) mlp1_kernel(
    const float* __restrict__ x,
    const float* __restrict__ Wa, const float* __restrict__ ba,
    const float* __restrict__ Wb, const float* __restrict__ bb, int N) {
    extern __shared__ float sm[];
    float* sXt = sm;                  // [44][260]
    float* sWa = sXt + ND * S1;       // [44][64]
    float* sHt = sWa + ND * HD;       // [64][260]  H transposed (k x n)
    float* sWb = sHt + HD * S1;       // [64][64]
    float* sb1 = sWb + HD * HD;
    float* sb2 = sb1 + HD;
    int t = threadIdx.x;
    for (int i = t; i < ND * HD; i += 256) sWa[i] = Wa[i];
    for (int i = t; i < HD * HD; i += 256) sWb[i] = Wb[i];
    if (t < HD) { sb1[t] = ba[t]; sb2[t] = bb[t]; }
    int tx = t & 7, ty = t >> 3;      // j0 = 8*tx (64), n0 = 8*ty (256)
    int j0 = 8 * tx, n0 = 8 * ty;
    long ntiles = (N + T1N - 1) / T1N;
    for (long tile = blockIdx.x; tile < ntiles; tile += gridDim.x) {
        long n_base = tile * T1N;
        __syncthreads();
        // stage X (transposed) : 256 nodes x 44 feats, float4 gmem reads
        for (int i = t; i < T1N * (ND / 4); i += 256) {
            int n = i / (ND / 4), c = i - n * (ND / 4);
            long gn = n_base + n;
            float4 v = make_float4(0.f, 0.f, 0.f, 0.f);
            if (gn < N) {
                float4 a = *(const float4*)(x + gn * ND + 4 * c);
                float4 bq = *(const float4*)(g_agg1 + gn * ND + 4 * c);
                v = make_float4(a.x + bq.x, a.y + bq.y, a.z + bq.z, a.w + bq.w);
            }
            sXt[(4 * c + 0) * S1 + n] = v.x;
            sXt[(4 * c + 1) * S1 + n] = v.y;
            sXt[(4 * c + 2) * S1 + n] = v.z;
            sXt[(4 * c + 3) * S1 + n] = v.w;
        }
        __syncthreads();
        // stage 1: Ht[j][n] = relu( sum_k Xt[k][n] * Wa[k][j] + b1[j] )
        float acc[8][8];
        #pragma unroll
        for (int j = 0; j < 8; j++) {
            float bj = sb1[j0 + j];
            #pragma unroll
            for (int i = 0; i < 8; i++) acc[i][j] = bj;
        }
        #pragma unroll 4
        for (int k = 0; k < ND; k++) {
            float4 x0 = *(float4*)(sXt + k * S1 + n0);
            float4 x1 = *(float4*)(sXt + k * S1 + n0 + 4);
            float4 w0 = *(float4*)(sWa + k * HD + j0);
            float4 w1 = *(float4*)(sWa + k * HD + j0 + 4);
            float xs[8] = {x0.x, x0.y, x0.z, x0.w, x1.x, x1.y, x1.z, x1.w};
            float ws[8] = {w0.x, w0.y, w0.z, w0.w, w1.x, w1.y, w1.z, w1.w};
            #pragma unroll
            for (int i = 0; i < 8; i++)
                #pragma unroll
                for (int j = 0; j < 8; j++)
                    acc[i][j] = fmaf(xs[i], ws[j], acc[i][j]);
        }
        #pragma unroll
        for (int j = 0; j < 8; j++) {
            float4 h0 = make_float4(fmaxf(acc[0][j], 0.f), fmaxf(acc[1][j], 0.f),
                                    fmaxf(acc[2][j], 0.f), fmaxf(acc[3][j], 0.f));
            float4 h1 = make_float4(fmaxf(acc[4][j], 0.f), fmaxf(acc[5][j], 0.f),
                                    fmaxf(acc[6][j], 0.f), fmaxf(acc[7][j], 0.f));
            *(float4*)(sHt + (j0 + j) * S1 + n0) = h0;
            *(float4*)(sHt + (j0 + j) * S1 + n0 + 4) = h1;
        }
        __syncthreads();
        // stage 2: O[n][j] = relu( sum_k Ht[k][n] * Wb[k][j] + b2[j] )
        float o[8][8];
        #pragma unroll
        for (int j = 0; j < 8; j++) {
            float bj = sb2[j0 + j];
            #pragma unroll
            for (int i = 0; i < 8; i++) o[i][j] = bj;
        }
        #pragma unroll 4
        for (int k = 0; k < HD; k++) {
            float4 h0 = *(float4*)(sHt + k * S1 + n0);
            float4 h1 = *(float4*)(sHt + k * S1 + n0 + 4);
            float4 w0 = *(float4*)(sWb + k * HD + j0);
            float4 w1 = *(float4*)(sWb + k * HD + j0 + 4);
            float hs[8] = {h0.x, h0.y, h0.z, h0.w, h1.x, h1.y, h1.z, h1.w};
            float ws[8] = {w0.x, w0.y, w0.z, w0.w, w1.x, w1.y, w1.z, w1.w};
            #pragma unroll
            for (int i = 0; i < 8; i++)
                #pragma unroll
                for (int j = 0; j < 8; j++)
                    o[i][j] = fmaf(hs[i], ws[j], o[i][j]);
        }
        #pragma unroll
        for (int i = 0; i < 8; i++) {
            long gn = n_base + n0 + i;
            if (gn < N) {
                float4 v0 = make_float4(fmaxf(o[i][0], 0.f), fmaxf(o[i][1], 0.f),
                                        fmaxf(o[i][2], 0.f), fmaxf(o[i][3], 0.f));
                float4 v1 = make_float4(fmaxf(o[i][4], 0.f), fmaxf(o[i][5], 0.f),
                                        fmaxf(o[i][6], 0.f), fmaxf(o[i][7], 0.f));
                *(float4*)(g_h1 + gn * HD + j0) = v0;
                *(float4*)(g_h1 + gn * HD + j0 + 4) = v1;
            }
        }
    }
}

// ---------------------------------------------------------------------------
// MLP2 + pooling: 128-node x 128-j tiles, 8x8 thread tiles.
#define T2N 128
#define S2 132
__global__ void __launch_bounds__(256, 1) mlp2_kernel(
    const float* __restrict__ Wa, const float* __restrict__ ba,
    const float* __restrict__ Wb, const float* __restrict__ bb,
    const int* __restrict__ batch, float* __restrict__ out, int N) {
    extern __shared__ float sm[];
    float* sXt = sm;                  // [64][132]
    float* sWa = sXt + HD * S2;       // [64][128]
    float* sHt = sWa + HD * EMB;      // [128][132]  (k x n)
    float* sWb = sHt + EMB * S2;      // [128][128]
    float* sb1 = sWb + EMB * EMB;
    float* sb2 = sb1 + EMB;
    int t = threadIdx.x;
    for (int i = t; i < HD * EMB; i += 256) sWa[i] = Wa[i];
    for (int i = t; i < EMB * EMB; i += 256) sWb[i] = Wb[i];
    if (t < EMB) { sb1[t] = ba[t]; sb2[t] = bb[t]; }
    int tx = t & 15, ty = t >> 4;     // j0 = 8*tx (128), n0 = 8*ty (128)
    int j0 = 8 * tx, n0 = 8 * ty;
    long ntiles = (N + T2N - 1) / T2N;
    for (long tile = blockIdx.x; tile < ntiles; tile += gridDim.x) {
        long n_base = tile * T2N;
        __syncthreads();
        for (int i = t; i < T2N * (HD / 4); i += 256) {
            int n = i >> 4, c = i & 15;
            long gn = n_base + n;
            float4 v = make_float4(0.f, 0.f, 0.f, 0.f);
            if (gn < N) {
                float4 a = *(const float4*)(g_h1 + gn * HD + 4 * c);
                float4 bq = *(const float4*)(g_agg2 + gn * HD + 4 * c);
                v = make_float4(a.x + bq.x, a.y + bq.y, a.z + bq.z, a.w + bq.w);
            }
            sXt[(4 * c + 0) * S2 + n] = v.x;
            sXt[(4 * c + 1) * S2 + n] = v.y;
            sXt[(4 * c + 2) * S2 + n] = v.z;
            sXt[(4 * c + 3) * S2 + n] = v.w;
        }
        __syncthreads();
        // stage 1: Ht[j][n] = relu( sum_k Xt[k][n]*Wa[k][j] + b1[j] )
        float acc[8][8];
        #pragma unroll
        for (int j = 0; j < 8; j++) {
            float bj = sb1[j0 + j];
            #pragma unroll
            for (int i = 0; i < 8; i++) acc[i][j] = bj;
        }
        #pragma unroll 4
        for (int k = 0; k < HD; k++) {
            float4 x0 = *(float4*)(sXt + k * S2 + n0);
            float4 x1 = *(float4*)(sXt + k * S2 + n0 + 4);
            float4 w0 = *(float4*)(sWa + k * EMB + j0);
            float4 w1 = *(float4*)(sWa + k * EMB + j0 + 4);
            float xs[8] = {x0.x, x0.y, x0.z, x0.w, x1.x, x1.y, x1.z, x1.w};
            float ws[8] = {w0.x, w0.y, w0.z, w0.w, w1.x, w1.y, w1.z, w1.w};
            #pragma unroll
            for (int i = 0; i < 8; i++)
                #pragma unroll
                for (int j = 0; j < 8; j++)
                    acc[i][j] = fmaf(xs[i], ws[j], acc[i][j]);
        }
        #pragma unroll
        for (int j = 0; j < 8; j++) {
            float4 h0 = make_float4(fmaxf(acc[0][j], 0.f), fmaxf(acc[1][j], 0.f),
                                    fmaxf(acc[2][j], 0.f), fmaxf(acc[3][j], 0.f));
            float4 h1 = make_float4(fmaxf(acc[4][j], 0.f), fmaxf(acc[5][j], 0.f),
                                    fmaxf(acc[6][j], 0.f), fmaxf(acc[7][j], 0.f));
            *(float4*)(sHt + (j0 + j) * S2 + n0) = h0;
            *(float4*)(sHt + (j0 + j) * S2 + n0 + 4) = h1;
        }
        __syncthreads();
        // stage 2: O[n][j] = sum_k Ht[k][n]*Wb[k][j] + b2[j]
        float o[8][8];
        #pragma unroll
        for (int j = 0; j < 8; j++) {
            float bj = sb2[j0 + j];
            #pragma unroll
            for (int i = 0; i < 8; i++) o[i][j] = bj;
        }
        #pragma unroll 4
        for (int k = 0; k < EMB; k++) {
            float4 h0 = *(float4*)(sHt + k * S2 + n0);
            float4 h1 = *(float4*)(sHt + k * S2 + n0 + 4);
            float4 w0 = *(float4*)(sWb + k * EMB + j0);
            float4 w1 = *(float4*)(sWb + k * EMB + j0 + 4);
            float hs[8] = {h0.x, h0.y, h0.z, h0.w, h1.x, h1.y, h1.z, h1.w};
            float ws[8] = {w0.x, w0.y, w0.z, w0.w, w1.x, w1.y, w1.z, w1.w};
            #pragma unroll
            for (int i = 0; i < 8; i++)
                #pragma unroll
                for (int j = 0; j < 8; j++)
                    o[i][j] = fmaf(hs[i], ws[j], o[i][j]);
        }
        // pooled epilogue: run-length over sorted batch, v4 reductions (2x)
        int cur = -1;
        float p[8];
        #pragma unroll
        for (int j = 0; j < 8; j++) p[j] = 0.f;
        #pragma unroll
        for (int i = 0; i < 8; i++) {
            long gn = n_base + n0 + i;
            if (gn < N) {
                int g = __ldg(batch + gn);
                if (g != cur) {
                    if (cur >= 0) {
                        red4(out + (long)cur * EMB + j0,     p[0], p[1], p[2], p[3]);
                        red4(out + (long)cur * EMB + j0 + 4, p[4], p[5], p[6], p[7]);
                    }
                    cur = g;
                    #pragma unroll
                    for (int j = 0; j < 8; j++) p[j] = 0.f;
                }
                #pragma unroll
                for (int j = 0; j < 8; j++) p[j] += o[i][j];
            }
        }
        if (cur >= 0) {
            red4(out + (long)cur * EMB + j0,     p[0], p[1], p[2], p[3]);
            red4(out + (long)cur * EMB + j0 + 4, p[4], p[5], p[6], p[7]);
        }
    }
}

// ---------------------------------------------------------------------------
__global__ void div_kernel(float* __restrict__ out, int total) {
    int idx = blockIdx.x * blockDim.x + threadIdx.x;
    if (idx < total) {
        int g = idx >> 7;
        int c = g_cnt[g];
        out[idx] *= (1.0f / (float)(c > 0 ? c : 1));
    }
}

// ---------------------------------------------------------------------------
extern "C" void kernel_launch(void* const* d_in, const int* in_sizes, int n_in,
                              void* d_out, int out_size) {
    const float* x     = (const float*)d_in[0];
    const float* ea    = (const float*)d_in[1];
    const int*   ei    = (const int*)  d_in[2];
    const int*   batch = (const int*)  d_in[3];
    const float* el1_w = (const float*)d_in[4];
    const float* el1_b = (const float*)d_in[5];
    const float* w1a   = (const float*)d_in[6];
    const float* b1a   = (const float*)d_in[7];
    const float* w1b   = (const float*)d_in[8];
    const float* b1b   = (const float*)d_in[9];
    const float* el2_w = (const float*)d_in[10];
    const float* el2_b = (const float*)d_in[11];
    const float* w2a   = (const float*)d_in[12];
    const float* b2a   = (const float*)d_in[13];
    const float* w2b   = (const float*)d_in[14];
    const float* b2b   = (const float*)d_in[15];

    int N = in_sizes[0] / ND;
    int E = in_sizes[1] / ED;
    float* out = (float*)d_out;
    const int* src = ei;
    const int* dst = ei + E;

    zero_all<<<2048, 256>>>(out, (long)out_size, N);
    count_kernel<<<(N + 255) / 256, 256>>>(batch, N);

    edge1_kernel<<<2048, 352>>>(x, ea, src, dst, el1_w, el1_b, E);

    int smem1 = (ND * S1 + ND * HD + HD * S1 + HD * HD + 2 * HD) * (int)sizeof(float);
    cudaFuncSetAttribute(mlp1_kernel, cudaFuncAttributeMaxDynamicSharedMemorySize, smem1);
    mlp1_kernel<<<148, 256, smem1>>>(x, w1a, b1a, w1b, b1b, N);

    edge2_kernel<<<2048, 256>>>(ea, src, dst, el2_w, el2_b, E);

    int smem2 = (HD * S2 + HD * EMB + EMB * S2 + EMB * EMB + 2 * EMB) * (int)sizeof(float);
    cudaFuncSetAttribute(mlp2_kernel, cudaFuncAttributeMaxDynamicSharedMemorySize, smem2);
    mlp2_kernel<<<148, 256, smem2>>>(w2a, b2a, w2b, b2b, batch, out, N);

    div_kernel<<<(out_size + 255) / 256, 256>>>(out, out_size);
}

// round 5
// speedup vs baseline: 2.1216x; 1.0202x over previous
#include <cuda_runtime.h>
#include <cstdint>

#define ND 44
#define ED 12
#define HD 64
#define EMB 128
#define NMAX 500000
#define GMAX 16384

// Scratch (__device__ globals per allocation-free rule)
__device__ float g_agg1[(size_t)NMAX * ND];   // 88 MB
__device__ float g_h1  [(size_t)NMAX * HD];   // 128 MB
__device__ float g_agg2[(size_t)NMAX * HD];   // 128 MB
__device__ int   g_cnt [GMAX];

__device__ __forceinline__ void red4(float* p, float a, float b, float c, float d) {
    asm volatile("red.global.add.v4.f32 [%0], {%1,%2,%3,%4};"
                 :: "l"(p), "f"(a), "f"(b), "f"(c), "f"(d) : "memory");
}
// packed fp32x2 helpers (FFMA2 path; exact fp32 semantics)
__device__ __forceinline__ uint64_t f2pk(float lo, float hi) {
    uint64_t r; asm("mov.b64 %0,{%1,%2};" : "=l"(r) : "f"(lo), "f"(hi)); return r;
}
__device__ __forceinline__ void f2un(uint64_t v, float& lo, float& hi) {
    asm("mov.b64 {%0,%1},%2;" : "=f"(lo), "=f"(hi) : "l"(v));
}
__device__ __forceinline__ uint64_t ffma2(uint64_t a, uint64_t b, uint64_t c) {
    uint64_t d; asm("fma.rn.f32x2 %0,%1,%2,%3;" : "=l"(d) : "l"(a), "l"(b), "l"(c)); return d;
}

// ---------------------------------------------------------------------------
__global__ void zero_all(float* __restrict__ out, long n_out, int N) {
    long idx = (long)blockIdx.x * blockDim.x + threadIdx.x;
    long st  = (long)gridDim.x * blockDim.x;
    float4 z = make_float4(0.f, 0.f, 0.f, 0.f);
    long n1 = (long)N * ND / 4, n2 = (long)N * HD / 4;
    float4* a1 = (float4*)g_agg1;
    float4* a2 = (float4*)g_agg2;
    float4* ov = (float4*)out;
    for (long i = idx; i < n1; i += st) a1[i] = z;
    for (long i = idx; i < n2; i += st) a2[i] = z;
    for (long i = idx; i < n_out / 4; i += st) ov[i] = z;
    for (long i = idx; i < GMAX; i += st) g_cnt[i] = 0;
}

__global__ void count_kernel(const int* __restrict__ batch, int N) {
    int i = blockIdx.x * blockDim.x + threadIdx.x;
    if (i < N) atomicAdd(&g_cnt[batch[i]], 1);
}

// ---------------------------------------------------------------------------
// Edge pass layer 1: 11 threads per edge, each owns a float4 feature chunk.
__global__ void __launch_bounds__(352) edge1_kernel(
    const float* __restrict__ x, const float* __restrict__ ea,
    const int* __restrict__ src, const int* __restrict__ dst,
    const float* __restrict__ W, const float* __restrict__ b, int E) {
    int t = threadIdx.x;
    int grp = t / 11;
    int c = t - grp * 11;
    float w[ED][4];
    #pragma unroll
    for (int k = 0; k < ED; k++) {
        float4 v = *(const float4*)(W + k * ND + 4 * c);
        w[k][0] = v.x; w[k][1] = v.y; w[k][2] = v.z; w[k][3] = v.w;
    }
    float4 bias = *(const float4*)(b + 4 * c);
    for (long e = (long)blockIdx.x * 32 + grp; e < E; e += (long)gridDim.x * 32) {
        int s = __ldg(src + e), d = __ldg(dst + e);
        float4 xv = *(const float4*)(x + (long)s * ND + 4 * c);
        float4 e0 = *(const float4*)(ea + e * ED);
        float4 e1 = *(const float4*)(ea + e * ED + 4);
        float4 e2 = *(const float4*)(ea + e * ED + 8);
        float eav[ED] = {e0.x, e0.y, e0.z, e0.w, e1.x, e1.y, e1.z, e1.w,
                         e2.x, e2.y, e2.z, e2.w};
        float m0 = bias.x, m1 = bias.y, m2 = bias.z, m3 = bias.w;
        #pragma unroll
        for (int k = 0; k < ED; k++) {
            m0 = fmaf(eav[k], w[k][0], m0);
            m1 = fmaf(eav[k], w[k][1], m1);
            m2 = fmaf(eav[k], w[k][2], m2);
            m3 = fmaf(eav[k], w[k][3], m3);
        }
        m0 = fmaxf(m0 + xv.x, 0.f); m1 = fmaxf(m1 + xv.y, 0.f);
        m2 = fmaxf(m2 + xv.z, 0.f); m3 = fmaxf(m3 + xv.w, 0.f);
        if (fmaxf(fmaxf(m0, m1), fmaxf(m2, m3)) > 0.f)
            red4(g_agg1 + (long)d * ND + 4 * c, m0, m1, m2, m3);
    }
}

// Edge pass layer 2: 16 threads per edge (HD=64).
__global__ void __launch_bounds__(256) edge2_kernel(
    const float* __restrict__ ea,
    const int* __restrict__ src, const int* __restrict__ dst,
    const float* __restrict__ W, const float* __restrict__ b, int E) {
    int t = threadIdx.x;
    int grp = t >> 4;
    int c = t & 15;
    float w[ED][4];
    #pragma unroll
    for (int k = 0; k < ED; k++) {
        float4 v = *(const float4*)(W + k * HD + 4 * c);
        w[k][0] = v.x; w[k][1] = v.y; w[k][2] = v.z; w[k][3] = v.w;
    }
    float4 bias = *(const float4*)(b + 4 * c);
    for (long e = (long)blockIdx.x * 16 + grp; e < E; e += (long)gridDim.x * 16) {
        int s = __ldg(src + e), d = __ldg(dst + e);
        float4 hv = *(const float4*)(g_h1 + (long)s * HD + 4 * c);
        float4 e0 = *(const float4*)(ea + e * ED);
        float4 e1 = *(const float4*)(ea + e * ED + 4);
        float4 e2 = *(const float4*)(ea + e * ED + 8);
        float eav[ED] = {e0.x, e0.y, e0.z, e0.w, e1.x, e1.y, e1.z, e1.w,
                         e2.x, e2.y, e2.z, e2.w};
        float m0 = bias.x, m1 = bias.y, m2 = bias.z, m3 = bias.w;
        #pragma unroll
        for (int k = 0; k < ED; k++) {
            m0 = fmaf(eav[k], w[k][0], m0);
            m1 = fmaf(eav[k], w[k][1], m1);
            m2 = fmaf(eav[k], w[k][2], m2);
            m3 = fmaf(eav[k], w[k][3], m3);
        }
        m0 = fmaxf(m0 + hv.x, 0.f); m1 = fmaxf(m1 + hv.y, 0.f);
        m2 = fmaxf(m2 + hv.z, 0.f); m3 = fmaxf(m3 + hv.w, 0.f);
        if (fmaxf(fmaxf(m0, m1), fmaxf(m2, m3)) > 0.f)
            red4(g_agg2 + (long)d * HD + 4 * c, m0, m1, m2, m3);
    }
}

// ---------------------------------------------------------------------------
// MLP1: h1 = relu( relu((x+agg1)@Wa+ba) @ Wb + bb ).
// 256-node x 64-j tiles, 8x8 thread tiles, FFMA2 (packed j-pairs).
#define T1N 256
#define S1 260
__global__ void __launch_bounds__(256, 1) mlp1_kernel(
    const float* __restrict__ x,
    const float* __restrict__ Wa, const float* __restrict__ ba,
    const float* __restrict__ Wb, const float* __restrict__ bb, int N) {
    extern __shared__ float sm[];
    float* sXt = sm;                  // [44][260]
    float* sWa = sXt + ND * S1;       // [44][64]
    float* sHt = sWa + ND * HD;       // [64][260]
    float* sWb = sHt + HD * S1;       // [64][64]
    float* sb1 = sWb + HD * HD;
    float* sb2 = sb1 + HD;
    int t = threadIdx.x;
    for (int i = t; i < ND * HD; i += 256) sWa[i] = Wa[i];
    for (int i = t; i < HD * HD; i += 256) sWb[i] = Wb[i];
    if (t < HD) { sb1[t] = ba[t]; sb2[t] = bb[t]; }
    int tx = t & 7, ty = t >> 3;
    int j0 = 8 * tx, n0 = 8 * ty;
    long ntiles = (N + T1N - 1) / T1N;
    for (long tile = blockIdx.x; tile < ntiles; tile += gridDim.x) {
        long n_base = tile * T1N;
        __syncthreads();
        for (int i = t; i < T1N * (ND / 4); i += 256) {
            int n = i / (ND / 4), c = i - n * (ND / 4);
            long gn = n_base + n;
            float4 v = make_float4(0.f, 0.f, 0.f, 0.f);
            if (gn < N) {
                float4 a = *(const float4*)(x + gn * ND + 4 * c);
                float4 bq = *(const float4*)(g_agg1 + gn * ND + 4 * c);
                v = make_float4(a.x + bq.x, a.y + bq.y, a.z + bq.z, a.w + bq.w);
            }
            sXt[(4 * c + 0) * S1 + n] = v.x;
            sXt[(4 * c + 1) * S1 + n] = v.y;
            sXt[(4 * c + 2) * S1 + n] = v.z;
            sXt[(4 * c + 3) * S1 + n] = v.w;
        }
        __syncthreads();
        // stage 1: packed acc over j-pairs
        uint64_t acc2[8][4];
        #pragma unroll
        for (int jp = 0; jp < 4; jp++) {
            uint64_t bp = f2pk(sb1[j0 + 2 * jp], sb1[j0 + 2 * jp + 1]);
            #pragma unroll
            for (int i = 0; i < 8; i++) acc2[i][jp] = bp;
        }
        #pragma unroll 4
        for (int k = 0; k < ND; k++) {
            float4 x0 = *(float4*)(sXt + k * S1 + n0);
            float4 x1 = *(float4*)(sXt + k * S1 + n0 + 4);
            ulonglong2 wA = *(ulonglong2*)(sWa + k * HD + j0);
            ulonglong2 wB = *(ulonglong2*)(sWa + k * HD + j0 + 4);
            uint64_t wp[4] = {wA.x, wA.y, wB.x, wB.y};
            float xs[8] = {x0.x, x0.y, x0.z, x0.w, x1.x, x1.y, x1.z, x1.w};
            #pragma unroll
            for (int i = 0; i < 8; i++) {
                uint64_t xp = f2pk(xs[i], xs[i]);
                #pragma unroll
                for (int jp = 0; jp < 4; jp++)
                    acc2[i][jp] = ffma2(xp, wp[jp], acc2[i][jp]);
            }
        }
        float hv[8][8];
        #pragma unroll
        for (int i = 0; i < 8; i++)
            #pragma unroll
            for (int jp = 0; jp < 4; jp++) {
                float lo, hi; f2un(acc2[i][jp], lo, hi);
                hv[i][2 * jp]     = fmaxf(lo, 0.f);
                hv[i][2 * jp + 1] = fmaxf(hi, 0.f);
            }
        #pragma unroll
        for (int j = 0; j < 8; j++) {
            *(float4*)(sHt + (j0 + j) * S1 + n0) =
                make_float4(hv[0][j], hv[1][j], hv[2][j], hv[3][j]);
            *(float4*)(sHt + (j0 + j) * S1 + n0 + 4) =
                make_float4(hv[4][j], hv[5][j], hv[6][j], hv[7][j]);
        }
        __syncthreads();
        // stage 2
        uint64_t o2[8][4];
        #pragma unroll
        for (int jp = 0; jp < 4; jp++) {
            uint64_t bp = f2pk(sb2[j0 + 2 * jp], sb2[j0 + 2 * jp + 1]);
            #pragma unroll
            for (int i = 0; i < 8; i++) o2[i][jp] = bp;
        }
        #pragma unroll 4
        for (int k = 0; k < HD; k++) {
            float4 h0 = *(float4*)(sHt + k * S1 + n0);
            float4 h1 = *(float4*)(sHt + k * S1 + n0 + 4);
            ulonglong2 wA = *(ulonglong2*)(sWb + k * HD + j0);
            ulonglong2 wB = *(ulonglong2*)(sWb + k * HD + j0 + 4);
            uint64_t wp[4] = {wA.x, wA.y, wB.x, wB.y};
            float hs[8] = {h0.x, h0.y, h0.z, h0.w, h1.x, h1.y, h1.z, h1.w};
            #pragma unroll
            for (int i = 0; i < 8; i++) {
                uint64_t hp = f2pk(hs[i], hs[i]);
                #pragma unroll
                for (int jp = 0; jp < 4; jp++)
                    o2[i][jp] = ffma2(hp, wp[jp], o2[i][jp]);
            }
        }
        #pragma unroll
        for (int i = 0; i < 8; i++) {
            long gn = n_base + n0 + i;
            if (gn < N) {
                float o[8];
                #pragma unroll
                for (int jp = 0; jp < 4; jp++) {
                    float lo, hi; f2un(o2[i][jp], lo, hi);
                    o[2 * jp]     = fmaxf(lo, 0.f);
                    o[2 * jp + 1] = fmaxf(hi, 0.f);
                }
                *(float4*)(g_h1 + gn * HD + j0) = make_float4(o[0], o[1], o[2], o[3]);
                *(float4*)(g_h1 + gn * HD + j0 + 4) = make_float4(o[4], o[5], o[6], o[7]);
            }
        }
    }
}

// ---------------------------------------------------------------------------
// MLP2 + pooling: 128-node x 128-j tiles, 8x8 thread tiles, FFMA2.
#define T2N 128
#define S2 132
__global__ void __launch_bounds__(256, 1) mlp2_kernel(
    const float* __restrict__ Wa, const float* __restrict__ ba,
    const float* __restrict__ Wb, const float* __restrict__ bb,
    const int* __restrict__ batch, float* __restrict__ out, int N) {
    extern __shared__ float sm[];
    float* sXt = sm;                  // [64][132]
    float* sWa = sXt + HD * S2;       // [64][128]
    float* sHt = sWa + HD * EMB;      // [128][132]
    float* sWb = sHt + EMB * S2;      // [128][128]
    float* sb1 = sWb + EMB * EMB;
    float* sb2 = sb1 + EMB;
    int t = threadIdx.x;
    for (int i = t; i < HD * EMB; i += 256) sWa[i] = Wa[i];
    for (int i = t; i < EMB * EMB; i += 256) sWb[i] = Wb[i];
    if (t < EMB) { sb1[t] = ba[t]; sb2[t] = bb[t]; }
    int tx = t & 15, ty = t >> 4;
    int j0 = 8 * tx, n0 = 8 * ty;
    long ntiles = (N + T2N - 1) / T2N;
    for (long tile = blockIdx.x; tile < ntiles; tile += gridDim.x) {
        long n_base = tile * T2N;
        __syncthreads();
        for (int i = t; i < T2N * (HD / 4); i += 256) {
            int n = i >> 4, c = i & 15;
            long gn = n_base + n;
            float4 v = make_float4(0.f, 0.f, 0.f, 0.f);
            if (gn < N) {
                float4 a = *(const float4*)(g_h1 + gn * HD + 4 * c);
                float4 bq = *(const float4*)(g_agg2 + gn * HD + 4 * c);
                v = make_float4(a.x + bq.x, a.y + bq.y, a.z + bq.z, a.w + bq.w);
            }
            sXt[(4 * c + 0) * S2 + n] = v.x;
            sXt[(4 * c + 1) * S2 + n] = v.y;
            sXt[(4 * c + 2) * S2 + n] = v.z;
            sXt[(4 * c + 3) * S2 + n] = v.w;
        }
        __syncthreads();
        // stage 1
        uint64_t acc2[8][4];
        #pragma unroll
        for (int jp = 0; jp < 4; jp++) {
            uint64_t bp = f2pk(sb1[j0 + 2 * jp], sb1[j0 + 2 * jp + 1]);
            #pragma unroll
            for (int i = 0; i < 8; i++) acc2[i][jp] = bp;
        }
        #pragma unroll 4
        for (int k = 0; k < HD; k++) {
            float4 x0 = *(float4*)(sXt + k * S2 + n0);
            float4 x1 = *(float4*)(sXt + k * S2 + n0 + 4);
            ulonglong2 wA = *(ulonglong2*)(sWa + k * EMB + j0);
            ulonglong2 wB = *(ulonglong2*)(sWa + k * EMB + j0 + 4);
            uint64_t wp[4] = {wA.x, wA.y, wB.x, wB.y};
            float xs[8] = {x0.x, x0.y, x0.z, x0.w, x1.x, x1.y, x1.z, x1.w};
            #pragma unroll
            for (int i = 0; i < 8; i++) {
                uint64_t xp = f2pk(xs[i], xs[i]);
                #pragma unroll
                for (int jp = 0; jp < 4; jp++)
                    acc2[i][jp] = ffma2(xp, wp[jp], acc2[i][jp]);
            }
        }
        float hv[8][8];
        #pragma unroll
        for (int i = 0; i < 8; i++)
            #pragma unroll
            for (int jp = 0; jp < 4; jp++) {
                float lo, hi; f2un(acc2[i][jp], lo, hi);
                hv[i][2 * jp]     = fmaxf(lo, 0.f);
                hv[i][2 * jp + 1] = fmaxf(hi, 0.f);
            }
        #pragma unroll
        for (int j = 0; j < 8; j++) {
            *(float4*)(sHt + (j0 + j) * S2 + n0) =
                make_float4(hv[0][j], hv[1][j], hv[2][j], hv[3][j]);
            *(float4*)(sHt + (j0 + j) * S2 + n0 + 4) =
                make_float4(hv[4][j], hv[5][j], hv[6][j], hv[7][j]);
        }
        __syncthreads();
        // stage 2
        uint64_t o2[8][4];
        #pragma unroll
        for (int jp = 0; jp < 4; jp++) {
            uint64_t bp = f2pk(sb2[j0 + 2 * jp], sb2[j0 + 2 * jp + 1]);
            #pragma unroll
            for (int i = 0; i < 8; i++) o2[i][jp] = bp;
        }
        #pragma unroll 4
        for (int k = 0; k < EMB; k++) {
            float4 h0 = *(float4*)(sHt + k * S2 + n0);
            float4 h1 = *(float4*)(sHt + k * S2 + n0 + 4);
            ulonglong2 wA = *(ulonglong2*)(sWb + k * EMB + j0);
            ulonglong2 wB = *(ulonglong2*)(sWb + k * EMB + j0 + 4);
            uint64_t wp[4] = {wA.x, wA.y, wB.x, wB.y};
            float hs[8] = {h0.x, h0.y, h0.z, h0.w, h1.x, h1.y, h1.z, h1.w};
            #pragma unroll
            for (int i = 0; i < 8; i++) {
                uint64_t hp = f2pk(hs[i], hs[i]);
                #pragma unroll
                for (int jp = 0; jp < 4; jp++)
                    o2[i][jp] = ffma2(hp, wp[jp], o2[i][jp]);
            }
        }
        float o[8][8];
        #pragma unroll
        for (int i = 0; i < 8; i++)
            #pragma unroll
            for (int jp = 0; jp < 4; jp++)
                f2un(o2[i][jp], o[i][2 * jp], o[i][2 * jp + 1]);
        // pooled epilogue: run-length over sorted batch, v4 reductions (2x)
        int cur = -1;
        float p[8];
        #pragma unroll
        for (int j = 0; j < 8; j++) p[j] = 0.f;
        #pragma unroll
        for (int i = 0; i < 8; i++) {
            long gn = n_base + n0 + i;
            if (gn < N) {
                int g = __ldg(batch + gn);
                if (g != cur) {
                    if (cur >= 0) {
                        red4(out + (long)cur * EMB + j0,     p[0], p[1], p[2], p[3]);
                        red4(out + (long)cur * EMB + j0 + 4, p[4], p[5], p[6], p[7]);
                    }
                    cur = g;
                    #pragma unroll
                    for (int j = 0; j < 8; j++) p[j] = 0.f;
                }
                #pragma unroll
                for (int j = 0; j < 8; j++) p[j] += o[i][j];
            }
        }
        if (cur >= 0) {
            red4(out + (long)cur * EMB + j0,     p[0], p[1], p[2], p[3]);
            red4(out + (long)cur * EMB + j0 + 4, p[4], p[5], p[6], p[7]);
        }
    }
}

// ---------------------------------------------------------------------------
__global__ void div_kernel(float* __restrict__ out, int total) {
    int idx = blockIdx.x * blockDim.x + threadIdx.x;
    if (idx < total) {
        int g = idx >> 7;
        int c = g_cnt[g];
        out[idx] *= (1.0f / (float)(c > 0 ? c : 1));
    }
}

// ---------------------------------------------------------------------------
extern "C" void kernel_launch(void* const* d_in, const int* in_sizes, int n_in,
                              void* d_out, int out_size) {
    const float* x     = (const float*)d_in[0];
    const float* ea    = (const float*)d_in[1];
    const int*   ei    = (const int*)  d_in[2];
    const int*   batch = (const int*)  d_in[3];
    const float* el1_w = (const float*)d_in[4];
    const float* el1_b = (const float*)d_in[5];
    const float* w1a   = (const float*)d_in[6];
    const float* b1a   = (const float*)d_in[7];
    const float* w1b   = (const float*)d_in[8];
    const float* b1b   = (const float*)d_in[9];
    const float* el2_w = (const float*)d_in[10];
    const float* el2_b = (const float*)d_in[11];
    const float* w2a   = (const float*)d_in[12];
    const float* b2a   = (const float*)d_in[13];
    const float* w2b   = (const float*)d_in[14];
    const float* b2b   = (const float*)d_in[15];

    int N = in_sizes[0] / ND;
    int E = in_sizes[1] / ED;
    float* out = (float*)d_out;
    const int* src = ei;
    const int* dst = ei + E;

    zero_all<<<2048, 256>>>(out, (long)out_size, N);
    count_kernel<<<(N + 255) / 256, 256>>>(batch, N);

    edge1_kernel<<<2048, 352>>>(x, ea, src, dst, el1_w, el1_b, E);

    int smem1 = (ND * S1 + ND * HD + HD * S1 + HD * HD + 2 * HD) * (int)sizeof(float);
    cudaFuncSetAttribute(mlp1_kernel, cudaFuncAttributeMaxDynamicSharedMemorySize, smem1);
    mlp1_kernel<<<148, 256, smem1>>>(x, w1a, b1a, w1b, b1b, N);

    edge2_kernel<<<2048, 256>>>(ea, src, dst, el2_w, el2_b, E);

    int smem2 = (HD * S2 + HD * EMB + EMB * S2 + EMB * EMB + 2 * EMB) * (int)sizeof(float);
    cudaFuncSetAttribute(mlp2_kernel, cudaFuncAttributeMaxDynamicSharedMemorySize, smem2);
    mlp2_kernel<<<148, 256, smem2>>>(w2a, b2a, w2b, b2b, batch, out, N);

    div_kernel<<<(out_size + 255) / 256, 256>>>(out, out_size);
}

// round 13
// speedup vs baseline: 2.2651x; 1.0677x over previous
#include <cuda_runtime.h>
#include <cuda_bf16.h>
#include <cstdint>

#define ND 44
#define ED 12
#define HD 64
#define EMB 128
#define NMAX 500000
#define GMAX 16384

// Scratch (__device__ globals per allocation-free rule)
__device__ float g_agg1[(size_t)NMAX * ND];   // 88 MB
__device__ float g_h1  [(size_t)NMAX * HD];   // 128 MB
__device__ float g_agg2[(size_t)NMAX * HD];   // 128 MB
__device__ int   g_cnt [GMAX];

__device__ __forceinline__ void red4(float* p, float a, float b, float c, float d) {
    asm volatile("red.global.add.v4.f32 [%0], {%1,%2,%3,%4};"
                 :: "l"(p), "f"(a), "f"(b), "f"(c), "f"(d) : "memory");
}
// packed fp32x2 helpers (FFMA2 path; exact fp32 semantics)
__device__ __forceinline__ uint64_t f2pk(float lo, float hi) {
    uint64_t r; asm("mov.b64 %0,{%1,%2};" : "=l"(r) : "f"(lo), "f"(hi)); return r;
}
__device__ __forceinline__ void f2un(uint64_t v, float& lo, float& hi) {
    asm("mov.b64 {%0,%1},%2;" : "=f"(lo), "=f"(hi) : "l"(v));
}
__device__ __forceinline__ uint64_t ffma2(uint64_t a, uint64_t b, uint64_t c) {
    uint64_t d; asm("fma.rn.f32x2 %0,%1,%2,%3;" : "=l"(d) : "l"(a), "l"(b), "l"(c)); return d;
}
// split two fp32 into packed bf16 hi/lo words (lo element in low half)
__device__ __forceinline__ void split2(float v0, float v1, uint32_t& hi, uint32_t& lo) {
    __nv_bfloat16 h0 = __float2bfloat16(v0), h1 = __float2bfloat16(v1);
    float r0 = v0 - __bfloat162float(h0), r1 = v1 - __bfloat162float(h1);
    __nv_bfloat16 l0 = __float2bfloat16(r0), l1 = __float2bfloat16(r1);
    hi = ((uint32_t)__bfloat16_as_ushort(h1) << 16) | __bfloat16_as_ushort(h0);
    lo = ((uint32_t)__bfloat16_as_ushort(l1) << 16) | __bfloat16_as_ushort(l0);
}
__device__ __forceinline__ void mma16816(float* c, uint32_t a0, uint32_t a1,
                                         uint32_t a2, uint32_t a3,
                                         uint32_t b0, uint32_t b1) {
    asm volatile(
        "mma.sync.aligned.m16n8k16.row.col.f32.bf16.bf16.f32 "
        "{%0,%1,%2,%3}, {%4,%5,%6,%7}, {%8,%9}, {%0,%1,%2,%3};"
        : "+f"(c[0]), "+f"(c[1]), "+f"(c[2]), "+f"(c[3])
        : "r"(a0), "r"(a1), "r"(a2), "r"(a3), "r"(b0), "r"(b1));
}

// ---------------------------------------------------------------------------
__global__ void zero_all(float* __restrict__ out, long n_out, int N) {
    long idx = (long)blockIdx.x * blockDim.x + threadIdx.x;
    long st  = (long)gridDim.x * blockDim.x;
    float4 z = make_float4(0.f, 0.f, 0.f, 0.f);
    long n1 = (long)N * ND / 4, n2 = (long)N * HD / 4;
    float4* a1 = (float4*)g_agg1;
    float4* a2 = (float4*)g_agg2;
    float4* ov = (float4*)out;
    for (long i = idx; i < n1; i += st) a1[i] = z;
    for (long i = idx; i < n2; i += st) a2[i] = z;
    for (long i = idx; i < n_out / 4; i += st) ov[i] = z;
    for (long i = idx; i < GMAX; i += st) g_cnt[i] = 0;
}

__global__ void count_kernel(const int* __restrict__ batch, int N) {
    int i = blockIdx.x * blockDim.x + threadIdx.x;
    if (i < N) atomicAdd(&g_cnt[batch[i]], 1);
}

// ---------------------------------------------------------------------------
// Edge pass layer 1: 11 threads per edge, each owns a float4 feature chunk.
__global__ void __launch_bounds__(352) edge1_kernel(
    const float* __restrict__ x, const float* __restrict__ ea,
    const int* __restrict__ src, const int* __restrict__ dst,
    const float* __restrict__ W, const float* __restrict__ b, int E) {
    int t = threadIdx.x;
    int grp = t / 11;
    int c = t - grp * 11;
    float w[ED][4];
    #pragma unroll
    for (int k = 0; k < ED; k++) {
        float4 v = *(const float4*)(W + k * ND + 4 * c);
        w[k][0] = v.x; w[k][1] = v.y; w[k][2] = v.z; w[k][3] = v.w;
    }
    float4 bias = *(const float4*)(b + 4 * c);
    for (long e = (long)blockIdx.x * 32 + grp; e < E; e += (long)gridDim.x * 32) {
        int s = __ldg(src + e), d = __ldg(dst + e);
        float4 xv = *(const float4*)(x + (long)s * ND + 4 * c);
        float4 e0 = *(const float4*)(ea + e * ED);
        float4 e1 = *(const float4*)(ea + e * ED + 4);
        float4 e2 = *(const float4*)(ea + e * ED + 8);
        float eav[ED] = {e0.x, e0.y, e0.z, e0.w, e1.x, e1.y, e1.z, e1.w,
                         e2.x, e2.y, e2.z, e2.w};
        float m0 = bias.x, m1 = bias.y, m2 = bias.z, m3 = bias.w;
        #pragma unroll
        for (int k = 0; k < ED; k++) {
            m0 = fmaf(eav[k], w[k][0], m0);
            m1 = fmaf(eav[k], w[k][1], m1);
            m2 = fmaf(eav[k], w[k][2], m2);
            m3 = fmaf(eav[k], w[k][3], m3);
        }
        m0 = fmaxf(m0 + xv.x, 0.f); m1 = fmaxf(m1 + xv.y, 0.f);
        m2 = fmaxf(m2 + xv.z, 0.f); m3 = fmaxf(m3 + xv.w, 0.f);
        if (fmaxf(fmaxf(m0, m1), fmaxf(m2, m3)) > 0.f)
            red4(g_agg1 + (long)d * ND + 4 * c, m0, m1, m2, m3);
    }
}

// Edge pass layer 2: 16 threads per edge (HD=64).
__global__ void __launch_bounds__(256) edge2_kernel(
    const float* __restrict__ ea,
    const int* __restrict__ src, const int* __restrict__ dst,
    const float* __restrict__ W, const float* __restrict__ b, int E) {
    int t = threadIdx.x;
    int grp = t >> 4;
    int c = t & 15;
    float w[ED][4];
    #pragma unroll
    for (int k = 0; k < ED; k++) {
        float4 v = *(const float4*)(W + k * HD + 4 * c);
        w[k][0] = v.x; w[k][1] = v.y; w[k][2] = v.z; w[k][3] = v.w;
    }
    float4 bias = *(const float4*)(b + 4 * c);
    for (long e = (long)blockIdx.x * 16 + grp; e < E; e += (long)gridDim.x * 16) {
        int s = __ldg(src + e), d = __ldg(dst + e);
        float4 hv = *(const float4*)(g_h1 + (long)s * HD + 4 * c);
        float4 e0 = *(const float4*)(ea + e * ED);
        float4 e1 = *(const float4*)(ea + e * ED + 4);
        float4 e2 = *(const float4*)(ea + e * ED + 8);
        float eav[ED] = {e0.x, e0.y, e0.z, e0.w, e1.x, e1.y, e1.z, e1.w,
                         e2.x, e2.y, e2.z, e2.w};
        float m0 = bias.x, m1 = bias.y, m2 = bias.z, m3 = bias.w;
        #pragma unroll
        for (int k = 0; k < ED; k++) {
            m0 = fmaf(eav[k], w[k][0], m0);
            m1 = fmaf(eav[k], w[k][1], m1);
            m2 = fmaf(eav[k], w[k][2], m2);
            m3 = fmaf(eav[k], w[k][3], m3);
        }
        m0 = fmaxf(m0 + hv.x, 0.f); m1 = fmaxf(m1 + hv.y, 0.f);
        m2 = fmaxf(m2 + hv.z, 0.f); m3 = fmaxf(m3 + hv.w, 0.f);
        if (fmaxf(fmaxf(m0, m1), fmaxf(m2, m3)) > 0.f)
            red4(g_agg2 + (long)d * HD + 4 * c, m0, m1, m2, m3);
    }
}

// ---------------------------------------------------------------------------
// MLP1 (unchanged, FFMA2): 256-node x 64-j tiles, 8x8 thread tiles.
#define T1N 256
#define S1 260
__global__ void __launch_bounds__(256, 1) mlp1_kernel(
    const float* __restrict__ x,
    const float* __restrict__ Wa, const float* __restrict__ ba,
    const float* __restrict__ Wb, const float* __restrict__ bb, int N) {
    extern __shared__ float sm[];
    float* sXt = sm;
    float* sWa = sXt + ND * S1;
    float* sHt = sWa + ND * HD;
    float* sWb = sHt + HD * S1;
    float* sb1 = sWb + HD * HD;
    float* sb2 = sb1 + HD;
    int t = threadIdx.x;
    for (int i = t; i < ND * HD; i += 256) sWa[i] = Wa[i];
    for (int i = t; i < HD * HD; i += 256) sWb[i] = Wb[i];
    if (t < HD) { sb1[t] = ba[t]; sb2[t] = bb[t]; }
    int tx = t & 7, ty = t >> 3;
    int j0 = 8 * tx, n0 = 8 * ty;
    long ntiles = (N + T1N - 1) / T1N;
    for (long tile = blockIdx.x; tile < ntiles; tile += gridDim.x) {
        long n_base = tile * T1N;
        __syncthreads();
        for (int i = t; i < T1N * (ND / 4); i += 256) {
            int n = i / (ND / 4), c = i - n * (ND / 4);
            long gn = n_base + n;
            float4 v = make_float4(0.f, 0.f, 0.f, 0.f);
            if (gn < N) {
                float4 a = *(const float4*)(x + gn * ND + 4 * c);
                float4 bq = *(const float4*)(g_agg1 + gn * ND + 4 * c);
                v = make_float4(a.x + bq.x, a.y + bq.y, a.z + bq.z, a.w + bq.w);
            }
            sXt[(4 * c + 0) * S1 + n] = v.x;
            sXt[(4 * c + 1) * S1 + n] = v.y;
            sXt[(4 * c + 2) * S1 + n] = v.z;
            sXt[(4 * c + 3) * S1 + n] = v.w;
        }
        __syncthreads();
        uint64_t acc2[8][4];
        #pragma unroll
        for (int jp = 0; jp < 4; jp++) {
            uint64_t bp = f2pk(sb1[j0 + 2 * jp], sb1[j0 + 2 * jp + 1]);
            #pragma unroll
            for (int i = 0; i < 8; i++) acc2[i][jp] = bp;
        }
        #pragma unroll 4
        for (int k = 0; k < ND; k++) {
            float4 x0 = *(float4*)(sXt + k * S1 + n0);
            float4 x1 = *(float4*)(sXt + k * S1 + n0 + 4);
            ulonglong2 wA = *(ulonglong2*)(sWa + k * HD + j0);
            ulonglong2 wB = *(ulonglong2*)(sWa + k * HD + j0 + 4);
            uint64_t wp[4] = {wA.x, wA.y, wB.x, wB.y};
            float xs[8] = {x0.x, x0.y, x0.z, x0.w, x1.x, x1.y, x1.z, x1.w};
            #pragma unroll
            for (int i = 0; i < 8; i++) {
                uint64_t xp = f2pk(xs[i], xs[i]);
                #pragma unroll
                for (int jp = 0; jp < 4; jp++)
                    acc2[i][jp] = ffma2(xp, wp[jp], acc2[i][jp]);
            }
        }
        float hv[8][8];
        #pragma unroll
        for (int i = 0; i < 8; i++)
            #pragma unroll
            for (int jp = 0; jp < 4; jp++) {
                float lo, hi; f2un(acc2[i][jp], lo, hi);
                hv[i][2 * jp]     = fmaxf(lo, 0.f);
                hv[i][2 * jp + 1] = fmaxf(hi, 0.f);
            }
        #pragma unroll
        for (int j = 0; j < 8; j++) {
            *(float4*)(sHt + (j0 + j) * S1 + n0) =
                make_float4(hv[0][j], hv[1][j], hv[2][j], hv[3][j]);
            *(float4*)(sHt + (j0 + j) * S1 + n0 + 4) =
                make_float4(hv[4][j], hv[5][j], hv[6][j], hv[7][j]);
        }
        __syncthreads();
        uint64_t o2[8][4];
        #pragma unroll
        for (int jp = 0; jp < 4; jp++) {
            uint64_t bp = f2pk(sb2[j0 + 2 * jp], sb2[j0 + 2 * jp + 1]);
            #pragma unroll
            for (int i = 0; i < 8; i++) o2[i][jp] = bp;
        }
        #pragma unroll 4
        for (int k = 0; k < HD; k++) {
            float4 h0 = *(float4*)(sHt + k * S1 + n0);
            float4 h1 = *(float4*)(sHt + k * S1 + n0 + 4);
            ulonglong2 wA = *(ulonglong2*)(sWb + k * HD + j0);
            ulonglong2 wB = *(ulonglong2*)(sWb + k * HD + j0 + 4);
            uint64_t wp[4] = {wA.x, wA.y, wB.x, wB.y};
            float hs[8] = {h0.x, h0.y, h0.z, h0.w, h1.x, h1.y, h1.z, h1.w};
            #pragma unroll
            for (int i = 0; i < 8; i++) {
                uint64_t hp = f2pk(hs[i], hs[i]);
                #pragma unroll
                for (int jp = 0; jp < 4; jp++)
                    o2[i][jp] = ffma2(hp, wp[jp], o2[i][jp]);
            }
        }
        #pragma unroll
        for (int i = 0; i < 8; i++) {
            long gn = n_base + n0 + i;
            if (gn < N) {
                float o[8];
                #pragma unroll
                for (int jp = 0; jp < 4; jp++) {
                    float lo, hi; f2un(o2[i][jp], lo, hi);
                    o[2 * jp]     = fmaxf(lo, 0.f);
                    o[2 * jp + 1] = fmaxf(hi, 0.f);
                }
                *(float4*)(g_h1 + gn * HD + j0) = make_float4(o[0], o[1], o[2], o[3]);
                *(float4*)(g_h1 + gn * HD + j0 + 4) = make_float4(o[4], o[5], o[6], o[7]);
            }
        }
    }
}

// ---------------------------------------------------------------------------
// MLP2 via mma.sync (m16n8k16 bf16, 3-term split) + fused pooling.
// 128-node x 128-j tiles, 256 threads = 8 warps, warp w owns rows 16w..16w+15.
// smem byte offsets (all 16B aligned):
#define MB1   0        // b1 floats [128]
#define MB2   512      // b2 floats [128]
#define MXH   1024     // X hi bf16 [128][72]  (stride 144 B)
#define MXL   19456
#define MW1H  37888    // W1^T hi bf16 [128j][72k]
#define MW1L  56320
#define MW2H  74752    // W2^T hi bf16 [128j][136k] (stride 272 B)
#define MW2L  109568
#define MHH   144384   // H hi bf16 [128][136]; also reused as O float [128][132]
#define MHL   179200
#define MTOT  214016
#define XS 144         // X/W1 row stride bytes
#define HS 272         // H/W2 row stride bytes
#define OS 132         // O row stride floats

__global__ void __launch_bounds__(256, 1) mlp2_mma(
    const float* __restrict__ Wa, const float* __restrict__ ba,
    const float* __restrict__ Wb, const float* __restrict__ bb,
    const int* __restrict__ batch, float* __restrict__ out, int N) {
    extern __shared__ __align__(16) char smem[];
    float* b1s = (float*)(smem + MB1);
    float* b2s = (float*)(smem + MB2);
    int t = threadIdx.x;
    int lane = t & 31, wid = t >> 5;
    int g = lane >> 2, tq = lane & 3;
    int m0 = 16 * wid;

    if (t < 128) { b1s[t] = ba[t]; b2s[t] = bb[t]; }
    // ---- stage weights transposed [j][k] as bf16 hi/lo, once ----
    {
        int j = t >> 1, h = t & 1;
        for (int k = 32 * h; k < 32 * h + 32; k += 2) {        // W1: K=64
            uint32_t hi, lo;
            split2(Wa[k * EMB + j], Wa[(k + 1) * EMB + j], hi, lo);
            *(uint32_t*)(smem + MW1H + j * XS + k * 2) = hi;
            *(uint32_t*)(smem + MW1L + j * XS + k * 2) = lo;
        }
        for (int k = 64 * h; k < 64 * h + 64; k += 2) {        // W2: K=128
            uint32_t hi, lo;
            split2(Wb[k * EMB + j], Wb[(k + 1) * EMB + j], hi, lo);
            *(uint32_t*)(smem + MW2H + j * HS + k * 2) = hi;
            *(uint32_t*)(smem + MW2L + j * HS + k * 2) = lo;
        }
    }
    __syncthreads();

    int px = t & 15, py = t >> 4;       // pooling: j0 = 8*px, rows 8*py..
    int j0p = 8 * px;

    long ntiles = ((long)N + 127) >> 7;
    for (long tile = blockIdx.x; tile < ntiles; tile += gridDim.x) {
        long nb = tile << 7;
        __syncthreads();    // protect X/H/O regions from previous iteration
        // ---- stage X = h1 + agg2 -> bf16 hi/lo, row = t>>1, half = t&1 ----
        {
            int row = t >> 1, h = t & 1;
            long gn = nb + row;
            if (gn < N) {
                #pragma unroll 8
                for (int p = 0; p < 16; p++) {
                    int k = 32 * h + 2 * p;
                    float2 a = *(const float2*)(g_h1 + gn * HD + k);
                    float2 b = *(const float2*)(g_agg2 + gn * HD + k);
                    uint32_t hi, lo;
                    split2(a.x + b.x, a.y + b.y, hi, lo);
                    *(uint32_t*)(smem + MXH + row * XS + k * 2) = hi;
                    *(uint32_t*)(smem + MXL + row * XS + k * 2) = lo;
                }
            } else {
                #pragma unroll 8
                for (int p = 0; p < 16; p++) {
                    int k = 32 * h + 2 * p;
                    *(uint32_t*)(smem + MXH + row * XS + k * 2) = 0u;
                    *(uint32_t*)(smem + MXL + row * XS + k * 2) = 0u;
                }
            }
        }
        __syncthreads();
        // ---- stage 1: C1[128x128] = X[128x64] @ W1^T, 3-term bf16 ----
        float acc[16][4];
        #pragma unroll
        for (int nt = 0; nt < 16; nt++)
            #pragma unroll
            for (int i = 0; i < 4; i++) acc[nt][i] = 0.f;
        #pragma unroll
        for (int ks = 0; ks < 4; ks++) {
            int k0 = 16 * ks;
            const char* rH = smem + MXH + (m0 + g) * XS + k0 * 2;
            const char* rL = smem + MXL + (m0 + g) * XS + k0 * 2;
            uint32_t ah0 = *(uint32_t*)(rH + 4 * tq);
            uint32_t ah1 = *(uint32_t*)(rH + 8 * XS + 4 * tq);
            uint32_t ah2 = *(uint32_t*)(rH + 4 * tq + 16);
            uint32_t ah3 = *(uint32_t*)(rH + 8 * XS + 4 * tq + 16);
            uint32_t al0 = *(uint32_t*)(rL + 4 * tq);
            uint32_t al1 = *(uint32_t*)(rL + 8 * XS + 4 * tq);
            uint32_t al2 = *(uint32_t*)(rL + 4 * tq + 16);
            uint32_t al3 = *(uint32_t*)(rL + 8 * XS + 4 * tq + 16);
            #pragma unroll
            for (int nt = 0; nt < 16; nt++) {
                const char* wH = smem + MW1H + (8 * nt + g) * XS + k0 * 2;
                const char* wL = smem + MW1L + (8 * nt + g) * XS + k0 * 2;
                uint32_t bh0 = *(uint32_t*)(wH + 4 * tq);
                uint32_t bh1 = *(uint32_t*)(wH + 4 * tq + 16);
                uint32_t bl0 = *(uint32_t*)(wL + 4 * tq);
                uint32_t bl1 = *(uint32_t*)(wL + 4 * tq + 16);
                mma16816(acc[nt], ah0, ah1, ah2, ah3, bh0, bh1);
                mma16816(acc[nt], ah0, ah1, ah2, ah3, bl0, bl1);
                mma16816(acc[nt], al0, al1, al2, al3, bh0, bh1);
            }
        }
        // ---- H = relu(C1 + b1) -> bf16 hi/lo (own rows only) ----
        #pragma unroll
        for (int nt = 0; nt < 16; nt++) {
            int col = 8 * nt + 2 * tq;
            float v0 = fmaxf(acc[nt][0] + b1s[col], 0.f);
            float v1 = fmaxf(acc[nt][1] + b1s[col + 1], 0.f);
            float v2 = fmaxf(acc[nt][2] + b1s[col], 0.f);
            float v3 = fmaxf(acc[nt][3] + b1s[col + 1], 0.f);
            uint32_t hi, lo;
            split2(v0, v1, hi, lo);
            *(uint32_t*)(smem + MHH + (m0 + g) * HS + col * 2) = hi;
            *(uint32_t*)(smem + MHL + (m0 + g) * HS + col * 2) = lo;
            split2(v2, v3, hi, lo);
            *(uint32_t*)(smem + MHH + (m0 + g + 8) * HS + col * 2) = hi;
            *(uint32_t*)(smem + MHL + (m0 + g + 8) * HS + col * 2) = lo;
        }
        __syncwarp();   // warp consumes only its own H rows
        // ---- stage 2: C2[128x128] = H[128x128] @ W2^T, 3-term bf16 ----
        #pragma unroll
        for (int nt = 0; nt < 16; nt++)
            #pragma unroll
            for (int i = 0; i < 4; i++) acc[nt][i] = 0.f;
        #pragma unroll
        for (int ks = 0; ks < 8; ks++) {
            int k0 = 16 * ks;
            const char* rH = smem + MHH + (m0 + g) * HS + k0 * 2;
            const char* rL = smem + MHL + (m0 + g) * HS + k0 * 2;
            uint32_t ah0 = *(uint32_t*)(rH + 4 * tq);
            uint32_t ah1 = *(uint32_t*)(rH + 8 * HS + 4 * tq);
            uint32_t ah2 = *(uint32_t*)(rH + 4 * tq + 16);
            uint32_t ah3 = *(uint32_t*)(rH + 8 * HS + 4 * tq + 16);
            uint32_t al0 = *(uint32_t*)(rL + 4 * tq);
            uint32_t al1 = *(uint32_t*)(rL + 8 * HS + 4 * tq);
            uint32_t al2 = *(uint32_t*)(rL + 4 * tq + 16);
            uint32_t al3 = *(uint32_t*)(rL + 8 * HS + 4 * tq + 16);
            #pragma unroll
            for (int nt = 0; nt < 16; nt++) {
                const char* wH = smem + MW2H + (8 * nt + g) * HS + k0 * 2;
                const char* wL = smem + MW2L + (8 * nt + g) * HS + k0 * 2;
                uint32_t bh0 = *(uint32_t*)(wH + 4 * tq);
                uint32_t bh1 = *(uint32_t*)(wH + 4 * tq + 16);
                uint32_t bl0 = *(uint32_t*)(wL + 4 * tq);
                uint32_t bl1 = *(uint32_t*)(wL + 4 * tq + 16);
                mma16816(acc[nt], ah0, ah1, ah2, ah3, bh0, bh1);
                mma16816(acc[nt], ah0, ah1, ah2, ah3, bl0, bl1);
                mma16816(acc[nt], al0, al1, al2, al3, bh0, bh1);
            }
        }
        __syncthreads();    // all H reads done before O overwrites the region
        // ---- O = C2 + b2 into smem (reuse H region) ----
        float* O = (float*)(smem + MHH);
        #pragma unroll
        for (int nt = 0; nt < 16; nt++) {
            int col = 8 * nt + 2 * tq;
            O[(m0 + g) * OS + col]         = acc[nt][0] + b2s[col];
            O[(m0 + g) * OS + col + 1]     = acc[nt][1] + b2s[col + 1];
            O[(m0 + g + 8) * OS + col]     = acc[nt][2] + b2s[col];
            O[(m0 + g + 8) * OS + col + 1] = acc[nt][3] + b2s[col + 1];
        }
        __syncthreads();
        // ---- pooled epilogue: run-length over sorted batch, v4 reductions ----
        {
            int cur = -1;
            float p[8];
            #pragma unroll
            for (int j = 0; j < 8; j++) p[j] = 0.f;
            for (int r = py * 8; r < py * 8 + 8; r++) {
                long gn = nb + r;
                if (gn >= N) break;
                int gg = __ldg(batch + gn);
                if (gg != cur) {
                    if (cur >= 0) {
                        red4(out + (long)cur * EMB + j0p,     p[0], p[1], p[2], p[3]);
                        red4(out + (long)cur * EMB + j0p + 4, p[4], p[5], p[6], p[7]);
                    }
                    cur = gg;
                    #pragma unroll
                    for (int j = 0; j < 8; j++) p[j] = 0.f;
                }
                #pragma unroll
                for (int j = 0; j < 8; j++) p[j] += O[r * OS + j0p + j];
            }
            if (cur >= 0) {
                red4(out + (long)cur * EMB + j0p,     p[0], p[1], p[2], p[3]);
                red4(out + (long)cur * EMB + j0p + 4, p[4], p[5], p[6], p[7]);
            }
        }
    }
}

// ---------------------------------------------------------------------------
__global__ void div_kernel(float* __restrict__ out, int total) {
    int idx = blockIdx.x * blockDim.x + threadIdx.x;
    if (idx < total) {
        int g = idx >> 7;
        int c = g_cnt[g];
        out[idx] *= (1.0f / (float)(c > 0 ? c : 1));
    }
}

// ---------------------------------------------------------------------------
extern "C" void kernel_launch(void* const* d_in, const int* in_sizes, int n_in,
                              void* d_out, int out_size) {
    const float* x     = (const float*)d_in[0];
    const float* ea    = (const float*)d_in[1];
    const int*   ei    = (const int*)  d_in[2];
    const int*   batch = (const int*)  d_in[3];
    const float* el1_w = (const float*)d_in[4];
    const float* el1_b = (const float*)d_in[5];
    const float* w1a   = (const float*)d_in[6];
    const float* b1a   = (const float*)d_in[7];
    const float* w1b   = (const float*)d_in[8];
    const float* b1b   = (const float*)d_in[9];
    const float* el2_w = (const float*)d_in[10];
    const float* el2_b = (const float*)d_in[11];
    const float* w2a   = (const float*)d_in[12];
    const float* b2a   = (const float*)d_in[13];
    const float* w2b   = (const float*)d_in[14];
    const float* b2b   = (const float*)d_in[15];

    int N = in_sizes[0] / ND;
    int E = in_sizes[1] / ED;
    float* out = (float*)d_out;
    const int* src = ei;
    const int* dst = ei + E;

    zero_all<<<2048, 256>>>(out, (long)out_size, N);
    count_kernel<<<(N + 255) / 256, 256>>>(batch, N);

    edge1_kernel<<<2048, 352>>>(x, ea, src, dst, el1_w, el1_b, E);

    int smem1 = (ND * S1 + ND * HD + HD * S1 + HD * HD + 2 * HD) * (int)sizeof(float);
    cudaFuncSetAttribute(mlp1_kernel, cudaFuncAttributeMaxDynamicSharedMemorySize, smem1);
    mlp1_kernel<<<148, 256, smem1>>>(x, w1a, b1a, w1b, b1b, N);

    edge2_kernel<<<2048, 256>>>(ea, src, dst, el2_w, el2_b, E);

    cudaFuncSetAttribute(mlp2_mma, cudaFuncAttributeMaxDynamicSharedMemorySize, MTOT);
    mlp2_mma<<<148, 256, MTOT>>>(w2a, b2a, w2b, b2b, batch, out, N);

    div_kernel<<<(out_size + 255) / 256, 256>>>(out, out_size);
}

// round 14
// speedup vs baseline: 2.5364x; 1.1198x over previous
#include <cuda_runtime.h>
#include <cuda_bf16.h>
#include <cstdint>

#define ND 44
#define ED 12
#define HD 64
#define EMB 128
#define NMAX 500000
#define GMAX 16384

// Scratch (__device__ globals per allocation-free rule)
__device__ float g_agg1[(size_t)NMAX * ND];   // 88 MB
__device__ float g_h1  [(size_t)NMAX * HD];   // 128 MB
__device__ float g_agg2[(size_t)NMAX * HD];   // 128 MB
__device__ int   g_cnt [GMAX];

__device__ __forceinline__ void red4(float* p, float a, float b, float c, float d) {
    asm volatile("red.global.add.v4.f32 [%0], {%1,%2,%3,%4};"
                 :: "l"(p), "f"(a), "f"(b), "f"(c), "f"(d) : "memory");
}
// split two fp32 into packed bf16 hi/lo words (lo element in low half)
__device__ __forceinline__ void split2(float v0, float v1, uint32_t& hi, uint32_t& lo) {
    __nv_bfloat16 h0 = __float2bfloat16(v0), h1 = __float2bfloat16(v1);
    float r0 = v0 - __bfloat162float(h0), r1 = v1 - __bfloat162float(h1);
    __nv_bfloat16 l0 = __float2bfloat16(r0), l1 = __float2bfloat16(r1);
    hi = ((uint32_t)__bfloat16_as_ushort(h1) << 16) | __bfloat16_as_ushort(h0);
    lo = ((uint32_t)__bfloat16_as_ushort(l1) << 16) | __bfloat16_as_ushort(l0);
}
__device__ __forceinline__ void mma16816(float* c, uint32_t a0, uint32_t a1,
                                         uint32_t a2, uint32_t a3,
                                         uint32_t b0, uint32_t b1) {
    asm volatile(
        "mma.sync.aligned.m16n8k16.row.col.f32.bf16.bf16.f32 "
        "{%0,%1,%2,%3}, {%4,%5,%6,%7}, {%8,%9}, {%0,%1,%2,%3};"
        : "+f"(c[0]), "+f"(c[1]), "+f"(c[2]), "+f"(c[3])
        : "r"(a0), "r"(a1), "r"(a2), "r"(a3), "r"(b0), "r"(b1));
}

// ---------------------------------------------------------------------------
__global__ void zero_all(float* __restrict__ out, long n_out, int N) {
    long idx = (long)blockIdx.x * blockDim.x + threadIdx.x;
    long st  = (long)gridDim.x * blockDim.x;
    float4 z = make_float4(0.f, 0.f, 0.f, 0.f);
    long n1 = (long)N * ND / 4, n2 = (long)N * HD / 4;
    float4* a1 = (float4*)g_agg1;
    float4* a2 = (float4*)g_agg2;
    float4* ov = (float4*)out;
    for (long i = idx; i < n1; i += st) a1[i] = z;
    for (long i = idx; i < n2; i += st) a2[i] = z;
    for (long i = idx; i < n_out / 4; i += st) ov[i] = z;
    for (long i = idx; i < GMAX; i += st) g_cnt[i] = 0;
}

__global__ void count_kernel(const int* __restrict__ batch, int N) {
    int i = blockIdx.x * blockDim.x + threadIdx.x;
    if (i < N) atomicAdd(&g_cnt[batch[i]], 1);
}

// ---------------------------------------------------------------------------
// Edge pass layer 1: 11 threads per edge, each owns a float4 feature chunk.
__global__ void __launch_bounds__(352) edge1_kernel(
    const float* __restrict__ x, const float* __restrict__ ea,
    const int* __restrict__ src, const int* __restrict__ dst,
    const float* __restrict__ W, const float* __restrict__ b, int E) {
    int t = threadIdx.x;
    int grp = t / 11;
    int c = t - grp * 11;
    float w[ED][4];
    #pragma unroll
    for (int k = 0; k < ED; k++) {
        float4 v = *(const float4*)(W + k * ND + 4 * c);
        w[k][0] = v.x; w[k][1] = v.y; w[k][2] = v.z; w[k][3] = v.w;
    }
    float4 bias = *(const float4*)(b + 4 * c);
    for (long e = (long)blockIdx.x * 32 + grp; e < E; e += (long)gridDim.x * 32) {
        int s = __ldg(src + e), d = __ldg(dst + e);
        float4 xv = *(const float4*)(x + (long)s * ND + 4 * c);
        float4 e0 = *(const float4*)(ea + e * ED);
        float4 e1 = *(const float4*)(ea + e * ED + 4);
        float4 e2 = *(const float4*)(ea + e * ED + 8);
        float eav[ED] = {e0.x, e0.y, e0.z, e0.w, e1.x, e1.y, e1.z, e1.w,
                         e2.x, e2.y, e2.z, e2.w};
        float m0 = bias.x, m1 = bias.y, m2 = bias.z, m3 = bias.w;
        #pragma unroll
        for (int k = 0; k < ED; k++) {
            m0 = fmaf(eav[k], w[k][0], m0);
            m1 = fmaf(eav[k], w[k][1], m1);
            m2 = fmaf(eav[k], w[k][2], m2);
            m3 = fmaf(eav[k], w[k][3], m3);
        }
        m0 = fmaxf(m0 + xv.x, 0.f); m1 = fmaxf(m1 + xv.y, 0.f);
        m2 = fmaxf(m2 + xv.z, 0.f); m3 = fmaxf(m3 + xv.w, 0.f);
        if (fmaxf(fmaxf(m0, m1), fmaxf(m2, m3)) > 0.f)
            red4(g_agg1 + (long)d * ND + 4 * c, m0, m1, m2, m3);
    }
}

// Edge pass layer 2: 16 threads per edge (HD=64).
__global__ void __launch_bounds__(256) edge2_kernel(
    const float* __restrict__ ea,
    const int* __restrict__ src, const int* __restrict__ dst,
    const float* __restrict__ W, const float* __restrict__ b, int E) {
    int t = threadIdx.x;
    int grp = t >> 4;
    int c = t & 15;
    float w[ED][4];
    #pragma unroll
    for (int k = 0; k < ED; k++) {
        float4 v = *(const float4*)(W + k * HD + 4 * c);
        w[k][0] = v.x; w[k][1] = v.y; w[k][2] = v.z; w[k][3] = v.w;
    }
    float4 bias = *(const float4*)(b + 4 * c);
    for (long e = (long)blockIdx.x * 16 + grp; e < E; e += (long)gridDim.x * 16) {
        int s = __ldg(src + e), d = __ldg(dst + e);
        float4 hv = *(const float4*)(g_h1 + (long)s * HD + 4 * c);
        float4 e0 = *(const float4*)(ea + e * ED);
        float4 e1 = *(const float4*)(ea + e * ED + 4);
        float4 e2 = *(const float4*)(ea + e * ED + 8);
        float eav[ED] = {e0.x, e0.y, e0.z, e0.w, e1.x, e1.y, e1.z, e1.w,
                         e2.x, e2.y, e2.z, e2.w};
        float m0 = bias.x, m1 = bias.y, m2 = bias.z, m3 = bias.w;
        #pragma unroll
        for (int k = 0; k < ED; k++) {
            m0 = fmaf(eav[k], w[k][0], m0);
            m1 = fmaf(eav[k], w[k][1], m1);
            m2 = fmaf(eav[k], w[k][2], m2);
            m3 = fmaf(eav[k], w[k][3], m3);
        }
        m0 = fmaxf(m0 + hv.x, 0.f); m1 = fmaxf(m1 + hv.y, 0.f);
        m2 = fmaxf(m2 + hv.z, 0.f); m3 = fmaxf(m3 + hv.w, 0.f);
        if (fmaxf(fmaxf(m0, m1), fmaxf(m2, m3)) > 0.f)
            red4(g_agg2 + (long)d * HD + 4 * c, m0, m1, m2, m3);
    }
}

// ---------------------------------------------------------------------------
// MLP1 via mma.sync (m16n8k16 bf16, 3-term split).
// h1 = relu( relu((x+agg1)@Wa+ba) @ Wb + bb ), 128-node tiles, K padded 44->48.
#define P1B1  0       // b1 floats [64]
#define P1B2  256     // b2 floats [64]
#define P1XH  512     // X hi bf16 [128][56]  (stride 112 B)
#define P1XL  14848
#define P1W1H 29184   // W1^T hi bf16 [64 j][56 k] (stride 112 B)
#define P1W1L 36352
#define P1W2H 43520   // W2^T hi bf16 [64 j][72 k] (stride 144 B)
#define P1W2L 52736
#define P1HH  61952   // H hi bf16 [128][72] (stride 144 B)
#define P1HL  80384
#define P1TOT 98816
#define P1XS  112
#define P1HS  144

__global__ void __launch_bounds__(256, 2) mlp1_mma(
    const float* __restrict__ x,
    const float* __restrict__ Wa, const float* __restrict__ ba,
    const float* __restrict__ Wb, const float* __restrict__ bb, int N) {
    extern __shared__ __align__(16) char smem[];
    float* b1s = (float*)(smem + P1B1);
    float* b2s = (float*)(smem + P1B2);
    int t = threadIdx.x;
    int lane = t & 31, wid = t >> 5;
    int g = lane >> 2, tq = lane & 3;
    int m0 = 16 * wid;

    if (t < 64) { b1s[t] = ba[t]; b2s[t] = bb[t]; }
    // ---- stage weights transposed [j][k] as bf16 hi/lo, once ----
    if (t < 128) {
        int j = t >> 1, h = t & 1;
        #pragma unroll
        for (int p = 0; p < 11; p++) {               // W1: K=44 (22 per half)
            int k = 22 * h + 2 * p;
            uint32_t hi, lo;
            split2(Wa[k * HD + j], Wa[(k + 1) * HD + j], hi, lo);
            *(uint32_t*)(smem + P1W1H + j * P1XS + k * 2) = hi;
            *(uint32_t*)(smem + P1W1L + j * P1XS + k * 2) = lo;
        }
        if (h) {                                     // pad k=44..47
            *(uint32_t*)(smem + P1W1H + j * P1XS + 88) = 0u;
            *(uint32_t*)(smem + P1W1H + j * P1XS + 92) = 0u;
            *(uint32_t*)(smem + P1W1L + j * P1XS + 88) = 0u;
            *(uint32_t*)(smem + P1W1L + j * P1XS + 92) = 0u;
        }
        #pragma unroll
        for (int p = 0; p < 16; p++) {               // W2: K=64
            int k = 32 * h + 2 * p;
            uint32_t hi, lo;
            split2(Wb[k * HD + j], Wb[(k + 1) * HD + j], hi, lo);
            *(uint32_t*)(smem + P1W2H + j * P1HS + k * 2) = hi;
            *(uint32_t*)(smem + P1W2L + j * P1HS + k * 2) = lo;
        }
    }
    __syncthreads();

    long ntiles = ((long)N + 127) >> 7;
    for (long tile = blockIdx.x; tile < ntiles; tile += gridDim.x) {
        long nb = tile << 7;
        __syncthreads();    // protect X/H regions from previous iteration
        // ---- stage X = x + agg1 -> bf16 hi/lo (row = t>>1, half = t&1) ----
        {
            int row = t >> 1, h = t & 1;
            long gn = nb + row;
            if (gn < N) {
                #pragma unroll
                for (int p = 0; p < 11; p++) {
                    int k = 22 * h + 2 * p;
                    float2 a = *(const float2*)(x + gn * ND + k);
                    float2 b = *(const float2*)(g_agg1 + gn * ND + k);
                    uint32_t hi, lo;
                    split2(a.x + b.x, a.y + b.y, hi, lo);
                    *(uint32_t*)(smem + P1XH + row * P1XS + k * 2) = hi;
                    *(uint32_t*)(smem + P1XL + row * P1XS + k * 2) = lo;
                }
            } else {
                #pragma unroll
                for (int p = 0; p < 11; p++) {
                    int k = 22 * h + 2 * p;
                    *(uint32_t*)(smem + P1XH + row * P1XS + k * 2) = 0u;
                    *(uint32_t*)(smem + P1XL + row * P1XS + k * 2) = 0u;
                }
            }
            if (h) {                                 // pad k=44..47
                *(uint32_t*)(smem + P1XH + row * P1XS + 88) = 0u;
                *(uint32_t*)(smem + P1XH + row * P1XS + 92) = 0u;
                *(uint32_t*)(smem + P1XL + row * P1XS + 88) = 0u;
                *(uint32_t*)(smem + P1XL + row * P1XS + 92) = 0u;
            }
        }
        __syncthreads();
        // ---- stage 1: C1[128x64] = X[128x48] @ W1^T, 3-term bf16 ----
        float acc[8][4];
        #pragma unroll
        for (int nt = 0; nt < 8; nt++)
            #pragma unroll
            for (int i = 0; i < 4; i++) acc[nt][i] = 0.f;
        #pragma unroll
        for (int ks = 0; ks < 3; ks++) {
            int k0 = 16 * ks;
            const char* rH = smem + P1XH + (m0 + g) * P1XS + k0 * 2;
            const char* rL = smem + P1XL + (m0 + g) * P1XS + k0 * 2;
            uint32_t ah0 = *(uint32_t*)(rH + 4 * tq);
            uint32_t ah1 = *(uint32_t*)(rH + 8 * P1XS + 4 * tq);
            uint32_t ah2 = *(uint32_t*)(rH + 4 * tq + 16);
            uint32_t ah3 = *(uint32_t*)(rH + 8 * P1XS + 4 * tq + 16);
            uint32_t al0 = *(uint32_t*)(rL + 4 * tq);
            uint32_t al1 = *(uint32_t*)(rL + 8 * P1XS + 4 * tq);
            uint32_t al2 = *(uint32_t*)(rL + 4 * tq + 16);
            uint32_t al3 = *(uint32_t*)(rL + 8 * P1XS + 4 * tq + 16);
            #pragma unroll
            for (int nt = 0; nt < 8; nt++) {
                const char* wH = smem + P1W1H + (8 * nt + g) * P1XS + k0 * 2;
                const char* wL = smem + P1W1L + (8 * nt + g) * P1XS + k0 * 2;
                uint32_t bh0 = *(uint32_t*)(wH + 4 * tq);
                uint32_t bh1 = *(uint32_t*)(wH + 4 * tq + 16);
                uint32_t bl0 = *(uint32_t*)(wL + 4 * tq);
                uint32_t bl1 = *(uint32_t*)(wL + 4 * tq + 16);
                mma16816(acc[nt], ah0, ah1, ah2, ah3, bh0, bh1);
                mma16816(acc[nt], ah0, ah1, ah2, ah3, bl0, bl1);
                mma16816(acc[nt], al0, al1, al2, al3, bh0, bh1);
            }
        }
        // ---- H = relu(C1 + b1) -> bf16 hi/lo (own rows only) ----
        #pragma unroll
        for (int nt = 0; nt < 8; nt++) {
            int col = 8 * nt + 2 * tq;
            float v0 = fmaxf(acc[nt][0] + b1s[col], 0.f);
            float v1 = fmaxf(acc[nt][1] + b1s[col + 1], 0.f);
            float v2 = fmaxf(acc[nt][2] + b1s[col], 0.f);
            float v3 = fmaxf(acc[nt][3] + b1s[col + 1], 0.f);
            uint32_t hi, lo;
            split2(v0, v1, hi, lo);
            *(uint32_t*)(smem + P1HH + (m0 + g) * P1HS + col * 2) = hi;
            *(uint32_t*)(smem + P1HL + (m0 + g) * P1HS + col * 2) = lo;
            split2(v2, v3, hi, lo);
            *(uint32_t*)(smem + P1HH + (m0 + g + 8) * P1HS + col * 2) = hi;
            *(uint32_t*)(smem + P1HL + (m0 + g + 8) * P1HS + col * 2) = lo;
        }
        __syncwarp();   // warp consumes only its own H rows
        // ---- stage 2: C2[128x64] = H[128x64] @ W2^T, 3-term bf16 ----
        #pragma unroll
        for (int nt = 0; nt < 8; nt++)
            #pragma unroll
            for (int i = 0; i < 4; i++) acc[nt][i] = 0.f;
        #pragma unroll
        for (int ks = 0; ks < 4; ks++) {
            int k0 = 16 * ks;
            const char* rH = smem + P1HH + (m0 + g) * P1HS + k0 * 2;
            const char* rL = smem + P1HL + (m0 + g) * P1HS + k0 * 2;
            uint32_t ah0 = *(uint32_t*)(rH + 4 * tq);
            uint32_t ah1 = *(uint32_t*)(rH + 8 * P1HS + 4 * tq);
            uint32_t ah2 = *(uint32_t*)(rH + 4 * tq + 16);
            uint32_t ah3 = *(uint32_t*)(rH + 8 * P1HS + 4 * tq + 16);
            uint32_t al0 = *(uint32_t*)(rL + 4 * tq);
            uint32_t al1 = *(uint32_t*)(rL + 8 * P1HS + 4 * tq);
            uint32_t al2 = *(uint32_t*)(rL + 4 * tq + 16);
            uint32_t al3 = *(uint32_t*)(rL + 8 * P1HS + 4 * tq + 16);
            #pragma unroll
            for (int nt = 0; nt < 8; nt++) {
                const char* wH = smem + P1W2H + (8 * nt + g) * P1HS + k0 * 2;
                const char* wL = smem + P1W2L + (8 * nt + g) * P1HS + k0 * 2;
                uint32_t bh0 = *(uint32_t*)(wH + 4 * tq);
                uint32_t bh1 = *(uint32_t*)(wH + 4 * tq + 16);
                uint32_t bl0 = *(uint32_t*)(wL + 4 * tq);
                uint32_t bl1 = *(uint32_t*)(wL + 4 * tq + 16);
                mma16816(acc[nt], ah0, ah1, ah2, ah3, bh0, bh1);
                mma16816(acc[nt], ah0, ah1, ah2, ah3, bl0, bl1);
                mma16816(acc[nt], al0, al1, al2, al3, bh0, bh1);
            }
        }
        // ---- outer relu + direct store to g_h1 (float2 per fragment half) ----
        {
            long gn0 = nb + m0 + g, gn1 = gn0 + 8;
            #pragma unroll
            for (int nt = 0; nt < 8; nt++) {
                int col = 8 * nt + 2 * tq;
                if (gn0 < N) {
                    float2 v = make_float2(fmaxf(acc[nt][0] + b2s[col], 0.f),
                                           fmaxf(acc[nt][1] + b2s[col + 1], 0.f));
                    *(float2*)(g_h1 + gn0 * HD + col) = v;
                }
                if (gn1 < N) {
                    float2 v = make_float2(fmaxf(acc[nt][2] + b2s[col], 0.f),
                                           fmaxf(acc[nt][3] + b2s[col + 1], 0.f));
                    *(float2*)(g_h1 + gn1 * HD + col) = v;
                }
            }
        }
    }
}

// ---------------------------------------------------------------------------
// MLP2 via mma.sync (m16n8k16 bf16, 3-term split) + fused pooling.
#define MB1   0        // b1 floats [128]
#define MB2   512      // b2 floats [128]
#define MXH   1024     // X hi bf16 [128][72]  (stride 144 B)
#define MXL   19456
#define MW1H  37888    // W1^T hi bf16 [128j][72k]
#define MW1L  56320
#define MW2H  74752    // W2^T hi bf16 [128j][136k] (stride 272 B)
#define MW2L  109568
#define MHH   144384   // H hi bf16 [128][136]; also reused as O float [128][132]
#define MHL   179200
#define MTOT  214016
#define XS 144         // X/W1 row stride bytes
#define HS 272         // H/W2 row stride bytes
#define OS 132         // O row stride floats

__global__ void __launch_bounds__(256, 1) mlp2_mma(
    const float* __restrict__ Wa, const float* __restrict__ ba,
    const float* __restrict__ Wb, const float* __restrict__ bb,
    const int* __restrict__ batch, float* __restrict__ out, int N) {
    extern __shared__ __align__(16) char smem[];
    float* b1s = (float*)(smem + MB1);
    float* b2s = (float*)(smem + MB2);
    int t = threadIdx.x;
    int lane = t & 31, wid = t >> 5;
    int g = lane >> 2, tq = lane & 3;
    int m0 = 16 * wid;

    if (t < 128) { b1s[t] = ba[t]; b2s[t] = bb[t]; }
    // ---- stage weights transposed [j][k] as bf16 hi/lo, once ----
    {
        int j = t >> 1, h = t & 1;
        for (int k = 32 * h; k < 32 * h + 32; k += 2) {        // W1: K=64
            uint32_t hi, lo;
            split2(Wa[k * EMB + j], Wa[(k + 1) * EMB + j], hi, lo);
            *(uint32_t*)(smem + MW1H + j * XS + k * 2) = hi;
            *(uint32_t*)(smem + MW1L + j * XS + k * 2) = lo;
        }
        for (int k = 64 * h; k < 64 * h + 64; k += 2) {        // W2: K=128
            uint32_t hi, lo;
            split2(Wb[k * EMB + j], Wb[(k + 1) * EMB + j], hi, lo);
            *(uint32_t*)(smem + MW2H + j * HS + k * 2) = hi;
            *(uint32_t*)(smem + MW2L + j * HS + k * 2) = lo;
        }
    }
    __syncthreads();

    int px = t & 15, py = t >> 4;       // pooling: j0 = 8*px, rows 8*py..
    int j0p = 8 * px;

    long ntiles = ((long)N + 127) >> 7;
    for (long tile = blockIdx.x; tile < ntiles; tile += gridDim.x) {
        long nb = tile << 7;
        __syncthreads();    // protect X/H/O regions from previous iteration
        // ---- stage X = h1 + agg2 -> bf16 hi/lo, row = t>>1, half = t&1 ----
        {
            int row = t >> 1, h = t & 1;
            long gn = nb + row;
            if (gn < N) {
                #pragma unroll 8
                for (int p = 0; p < 16; p++) {
                    int k = 32 * h + 2 * p;
                    float2 a = *(const float2*)(g_h1 + gn * HD + k);
                    float2 b = *(const float2*)(g_agg2 + gn * HD + k);
                    uint32_t hi, lo;
                    split2(a.x + b.x, a.y + b.y, hi, lo);
                    *(uint32_t*)(smem + MXH + row * XS + k * 2) = hi;
                    *(uint32_t*)(smem + MXL + row * XS + k * 2) = lo;
                }
            } else {
                #pragma unroll 8
                for (int p = 0; p < 16; p++) {
                    int k = 32 * h + 2 * p;
                    *(uint32_t*)(smem + MXH + row * XS + k * 2) = 0u;
                    *(uint32_t*)(smem + MXL + row * XS + k * 2) = 0u;
                }
            }
        }
        __syncthreads();
        // ---- stage 1: C1[128x128] = X[128x64] @ W1^T, 3-term bf16 ----
        float acc[16][4];
        #pragma unroll
        for (int nt = 0; nt < 16; nt++)
            #pragma unroll
            for (int i = 0; i < 4; i++) acc[nt][i] = 0.f;
        #pragma unroll
        for (int ks = 0; ks < 4; ks++) {
            int k0 = 16 * ks;
            const char* rH = smem + MXH + (m0 + g) * XS + k0 * 2;
            const char* rL = smem + MXL + (m0 + g) * XS + k0 * 2;
            uint32_t ah0 = *(uint32_t*)(rH + 4 * tq);
            uint32_t ah1 = *(uint32_t*)(rH + 8 * XS + 4 * tq);
            uint32_t ah2 = *(uint32_t*)(rH + 4 * tq + 16);
            uint32_t ah3 = *(uint32_t*)(rH + 8 * XS + 4 * tq + 16);
            uint32_t al0 = *(uint32_t*)(rL + 4 * tq);
            uint32_t al1 = *(uint32_t*)(rL + 8 * XS + 4 * tq);
            uint32_t al2 = *(uint32_t*)(rL + 4 * tq + 16);
            uint32_t al3 = *(uint32_t*)(rL + 8 * XS + 4 * tq + 16);
            #pragma unroll
            for (int nt = 0; nt < 16; nt++) {
                const char* wH = smem + MW1H + (8 * nt + g) * XS + k0 * 2;
                const char* wL = smem + MW1L + (8 * nt + g) * XS + k0 * 2;
                uint32_t bh0 = *(uint32_t*)(wH + 4 * tq);
                uint32_t bh1 = *(uint32_t*)(wH + 4 * tq + 16);
                uint32_t bl0 = *(uint32_t*)(wL + 4 * tq);
                uint32_t bl1 = *(uint32_t*)(wL + 4 * tq + 16);
                mma16816(acc[nt], ah0, ah1, ah2, ah3, bh0, bh1);
                mma16816(acc[nt], ah0, ah1, ah2, ah3, bl0, bl1);
                mma16816(acc[nt], al0, al1, al2, al3, bh0, bh1);
            }
        }
        // ---- H = relu(C1 + b1) -> bf16 hi/lo (own rows only) ----
        #pragma unroll
        for (int nt = 0; nt < 16; nt++) {
            int col = 8 * nt + 2 * tq;
            float v0 = fmaxf(acc[nt][0] + b1s[col], 0.f);
            float v1 = fmaxf(acc[nt][1] + b1s[col + 1], 0.f);
            float v2 = fmaxf(acc[nt][2] + b1s[col], 0.f);
            float v3 = fmaxf(acc[nt][3] + b1s[col + 1], 0.f);
            uint32_t hi, lo;
            split2(v0, v1, hi, lo);
            *(uint32_t*)(smem + MHH + (m0 + g) * HS + col * 2) = hi;
            *(uint32_t*)(smem + MHL + (m0 + g) * HS + col * 2) = lo;
            split2(v2, v3, hi, lo);
            *(uint32_t*)(smem + MHH + (m0 + g + 8) * HS + col * 2) = hi;
            *(uint32_t*)(smem + MHL + (m0 + g + 8) * HS + col * 2) = lo;
        }
        __syncwarp();   // warp consumes only its own H rows
        // ---- stage 2: C2[128x128] = H[128x128] @ W2^T, 3-term bf16 ----
        #pragma unroll
        for (int nt = 0; nt < 16; nt++)
            #pragma unroll
            for (int i = 0; i < 4; i++) acc[nt][i] = 0.f;
        #pragma unroll
        for (int ks = 0; ks < 8; ks++) {
            int k0 = 16 * ks;
            const char* rH = smem + MHH + (m0 + g) * HS + k0 * 2;
            const char* rL = smem + MHL + (m0 + g) * HS + k0 * 2;
            uint32_t ah0 = *(uint32_t*)(rH + 4 * tq);
            uint32_t ah1 = *(uint32_t*)(rH + 8 * HS + 4 * tq);
            uint32_t ah2 = *(uint32_t*)(rH + 4 * tq + 16);
            uint32_t ah3 = *(uint32_t*)(rH + 8 * HS + 4 * tq + 16);
            uint32_t al0 = *(uint32_t*)(rL + 4 * tq);
            uint32_t al1 = *(uint32_t*)(rL + 8 * HS + 4 * tq);
            uint32_t al2 = *(uint32_t*)(rL + 4 * tq + 16);
            uint32_t al3 = *(uint32_t*)(rL + 8 * HS + 4 * tq + 16);
            #pragma unroll
            for (int nt = 0; nt < 16; nt++) {
                const char* wH = smem + MW2H + (8 * nt + g) * HS + k0 * 2;
                const char* wL = smem + MW2L + (8 * nt + g) * HS + k0 * 2;
                uint32_t bh0 = *(uint32_t*)(wH + 4 * tq);
                uint32_t bh1 = *(uint32_t*)(wH + 4 * tq + 16);
                uint32_t bl0 = *(uint32_t*)(wL + 4 * tq);
                uint32_t bl1 = *(uint32_t*)(wL + 4 * tq + 16);
                mma16816(acc[nt], ah0, ah1, ah2, ah3, bh0, bh1);
                mma16816(acc[nt], ah0, ah1, ah2, ah3, bl0, bl1);
                mma16816(acc[nt], al0, al1, al2, al3, bh0, bh1);
            }
        }
        __syncthreads();    // all H reads done before O overwrites the region
        // ---- O = C2 + b2 into smem (reuse H region) ----
        float* O = (float*)(smem + MHH);
        #pragma unroll
        for (int nt = 0; nt < 16; nt++) {
            int col = 8 * nt + 2 * tq;
            O[(m0 + g) * OS + col]         = acc[nt][0] + b2s[col];
            O[(m0 + g) * OS + col + 1]     = acc[nt][1] + b2s[col + 1];
            O[(m0 + g + 8) * OS + col]     = acc[nt][2] + b2s[col];
            O[(m0 + g + 8) * OS + col + 1] = acc[nt][3] + b2s[col + 1];
        }
        __syncthreads();
        // ---- pooled epilogue: run-length over sorted batch, v4 reductions ----
        {
            int cur = -1;
            float p[8];
            #pragma unroll
            for (int j = 0; j < 8; j++) p[j] = 0.f;
            for (int r = py * 8; r < py * 8 + 8; r++) {
                long gn = nb + r;
                if (gn >= N) break;
                int gg = __ldg(batch + gn);
                if (gg != cur) {
                    if (cur >= 0) {
                        red4(out + (long)cur * EMB + j0p,     p[0], p[1], p[2], p[3]);
                        red4(out + (long)cur * EMB + j0p + 4, p[4], p[5], p[6], p[7]);
                    }
                    cur = gg;
                    #pragma unroll
                    for (int j = 0; j < 8; j++) p[j] = 0.f;
                }
                #pragma unroll
                for (int j = 0; j < 8; j++) p[j] += O[r * OS + j0p + j];
            }
            if (cur >= 0) {
                red4(out + (long)cur * EMB + j0p,     p[0], p[1], p[2], p[3]);
                red4(out + (long)cur * EMB + j0p + 4, p[4], p[5], p[6], p[7]);
            }
        }
    }
}

// ---------------------------------------------------------------------------
__global__ void div_kernel(float* __restrict__ out, int total) {
    int idx = blockIdx.x * blockDim.x + threadIdx.x;
    if (idx < total) {
        int g = idx >> 7;
        int c = g_cnt[g];
        out[idx] *= (1.0f / (float)(c > 0 ? c : 1));
    }
}

// ---------------------------------------------------------------------------
extern "C" void kernel_launch(void* const* d_in, const int* in_sizes, int n_in,
                              void* d_out, int out_size) {
    const float* x     = (const float*)d_in[0];
    const float* ea    = (const float*)d_in[1];
    const int*   ei    = (const int*)  d_in[2];
    const int*   batch = (const int*)  d_in[3];
    const float* el1_w = (const float*)d_in[4];
    const float* el1_b = (const float*)d_in[5];
    const float* w1a   = (const float*)d_in[6];
    const float* b1a   = (const float*)d_in[7];
    const float* w1b   = (const float*)d_in[8];
    const float* b1b   = (const float*)d_in[9];
    const float* el2_w = (const float*)d_in[10];
    const float* el2_b = (const float*)d_in[11];
    const float* w2a   = (const float*)d_in[12];
    const float* b2a   = (const float*)d_in[13];
    const float* w2b   = (const float*)d_in[14];
    const float* b2b   = (const float*)d_in[15];

    int N = in_sizes[0] / ND;
    int E = in_sizes[1] / ED;
    float* out = (float*)d_out;
    const int* src = ei;
    const int* dst = ei + E;

    zero_all<<<2048, 256>>>(out, (long)out_size, N);
    count_kernel<<<(N + 255) / 256, 256>>>(batch, N);

    edge1_kernel<<<2048, 352>>>(x, ea, src, dst, el1_w, el1_b, E);

    cudaFuncSetAttribute(mlp1_mma, cudaFuncAttributeMaxDynamicSharedMemorySize, P1TOT);
    mlp1_mma<<<296, 256, P1TOT>>>(x, w1a, b1a, w1b, b1b, N);

    edge2_kernel<<<2048, 256>>>(ea, src, dst, el2_w, el2_b, E);

    cudaFuncSetAttribute(mlp2_mma, cudaFuncAttributeMaxDynamicSharedMemorySize, MTOT);
    mlp2_mma<<<148, 256, MTOT>>>(w2a, b2a, w2b, b2b, batch, out, N);

    div_kernel<<<(out_size + 255) / 256, 256>>>(out, out_size);
}

// round 15
// speedup vs baseline: 2.6075x; 1.0280x over previous
#include <cuda_runtime.h>
#include <cuda_bf16.h>
#include <cstdint>

#define ND 44
#define ED 12
#define HD 64
#define EMB 128
#define NMAX 500000
#define GMAX 16384

// Scratch (allocation-free rule: __device__ globals)
__device__ float g_agg1[(size_t)NMAX * ND];
__device__ float g_h1  [(size_t)NMAX * HD];
__device__ float g_agg2[(size_t)NMAX * HD];
__device__ int   g_cnt [GMAX];

__device__ __forceinline__ void red4(float* p, float a, float b, float c, float d) {
    asm volatile("red.global.add.v4.f32 [%0], {%1,%2,%3,%4};"
                 :: "l"(p), "f"(a), "f"(b), "f"(c), "f"(d) : "memory");
}
__device__ __forceinline__ uint32_t smem_u32(const void* p) {
    uint32_t a;
    asm("{ .reg .u64 t; cvta.to.shared.u64 t, %1; cvt.u32.u64 %0, t; }" : "=r"(a) : "l"(p));
    return a;
}
// split two fp32 into packed bf16 hi/lo words (lo element in low half)
__device__ __forceinline__ void split2(float v0, float v1, uint32_t& hi, uint32_t& lo) {
    __nv_bfloat16 h0 = __float2bfloat16(v0), h1 = __float2bfloat16(v1);
    float r0 = v0 - __bfloat162float(h0), r1 = v1 - __bfloat162float(h1);
    __nv_bfloat16 l0 = __float2bfloat16(r0), l1 = __float2bfloat16(r1);
    hi = ((uint32_t)__bfloat16_as_ushort(h1) << 16) | __bfloat16_as_ushort(h0);
    lo = ((uint32_t)__bfloat16_as_ushort(l1) << 16) | __bfloat16_as_ushort(l0);
}
__device__ __forceinline__ void mma16816(float* c, uint32_t a0, uint32_t a1,
                                         uint32_t a2, uint32_t a3,
                                         uint32_t b0, uint32_t b1) {
    asm volatile(
        "mma.sync.aligned.m16n8k16.row.col.f32.bf16.bf16.f32 "
        "{%0,%1,%2,%3}, {%4,%5,%6,%7}, {%8,%9}, {%0,%1,%2,%3};"
        : "+f"(c[0]), "+f"(c[1]), "+f"(c[2]), "+f"(c[3])
        : "r"(a0), "r"(a1), "r"(a2), "r"(a3), "r"(b0), "r"(b1));
}
__device__ __forceinline__ void ldsm4(uint32_t& r0, uint32_t& r1, uint32_t& r2,
                                      uint32_t& r3, uint32_t addr) {
    asm volatile("ldmatrix.sync.aligned.m8n8.x4.shared.b16 {%0,%1,%2,%3}, [%4];"
                 : "=r"(r0), "=r"(r1), "=r"(r2), "=r"(r3) : "r"(addr));
}
__device__ __forceinline__ void stsm4(uint32_t addr, uint32_t r0, uint32_t r1,
                                      uint32_t r2, uint32_t r3) {
    asm volatile("stmatrix.sync.aligned.m8n8.x4.shared.b16 [%0], {%1,%2,%3,%4};"
                 :: "r"(addr), "r"(r0), "r"(r1), "r"(r2), "r"(r3) : "memory");
}

// ---------------------------------------------------------------------------
__global__ void zero_all(float* __restrict__ out, long n_out, int N) {
    long idx = (long)blockIdx.x * blockDim.x + threadIdx.x;
    long st  = (long)gridDim.x * blockDim.x;
    float4 z = make_float4(0.f, 0.f, 0.f, 0.f);
    long n1 = (long)N * ND / 4, n2 = (long)N * HD / 4;
    float4* a1 = (float4*)g_agg1;
    float4* a2 = (float4*)g_agg2;
    float4* ov = (float4*)out;
    for (long i = idx; i < n1; i += st) a1[i] = z;
    for (long i = idx; i < n2; i += st) a2[i] = z;
    for (long i = idx; i < n_out / 4; i += st) ov[i] = z;
    for (long i = idx; i < GMAX; i += st) g_cnt[i] = 0;
}

__global__ void count_kernel(const int* __restrict__ batch, int N) {
    int i = blockIdx.x * blockDim.x + threadIdx.x;
    if (i < N) atomicAdd(&g_cnt[batch[i]], 1);
}

// ---------------------------------------------------------------------------
// Edge pass layer 1: 11 threads per edge, each owns a float4 feature chunk.
__global__ void __launch_bounds__(352) edge1_kernel(
    const float* __restrict__ x, const float* __restrict__ ea,
    const int* __restrict__ src, const int* __restrict__ dst,
    const float* __restrict__ W, const float* __restrict__ b, int E) {
    int t = threadIdx.x;
    int grp = t / 11;
    int c = t - grp * 11;
    float w[ED][4];
    #pragma unroll
    for (int k = 0; k < ED; k++) {
        float4 v = *(const float4*)(W + k * ND + 4 * c);
        w[k][0] = v.x; w[k][1] = v.y; w[k][2] = v.z; w[k][3] = v.w;
    }
    float4 bias = *(const float4*)(b + 4 * c);
    for (long e = (long)blockIdx.x * 32 + grp; e < E; e += (long)gridDim.x * 32) {
        int s = __ldg(src + e), d = __ldg(dst + e);
        float4 xv = *(const float4*)(x + (long)s * ND + 4 * c);
        float4 e0 = *(const float4*)(ea + e * ED);
        float4 e1 = *(const float4*)(ea + e * ED + 4);
        float4 e2 = *(const float4*)(ea + e * ED + 8);
        float eav[ED] = {e0.x, e0.y, e0.z, e0.w, e1.x, e1.y, e1.z, e1.w,
                         e2.x, e2.y, e2.z, e2.w};
        float m0 = bias.x, m1 = bias.y, m2 = bias.z, m3 = bias.w;
        #pragma unroll
        for (int k = 0; k < ED; k++) {
            m0 = fmaf(eav[k], w[k][0], m0);
            m1 = fmaf(eav[k], w[k][1], m1);
            m2 = fmaf(eav[k], w[k][2], m2);
            m3 = fmaf(eav[k], w[k][3], m3);
        }
        m0 = fmaxf(m0 + xv.x, 0.f); m1 = fmaxf(m1 + xv.y, 0.f);
        m2 = fmaxf(m2 + xv.z, 0.f); m3 = fmaxf(m3 + xv.w, 0.f);
        if (fmaxf(fmaxf(m0, m1), fmaxf(m2, m3)) > 0.f)
            red4(g_agg1 + (long)d * ND + 4 * c, m0, m1, m2, m3);
    }
}

// Edge pass layer 2: 16 threads per edge (HD=64).
__global__ void __launch_bounds__(256) edge2_kernel(
    const float* __restrict__ ea,
    const int* __restrict__ src, const int* __restrict__ dst,
    const float* __restrict__ W, const float* __restrict__ b, int E) {
    int t = threadIdx.x;
    int grp = t >> 4;
    int c = t & 15;
    float w[ED][4];
    #pragma unroll
    for (int k = 0; k < ED; k++) {
        float4 v = *(const float4*)(W + k * HD + 4 * c);
        w[k][0] = v.x; w[k][1] = v.y; w[k][2] = v.z; w[k][3] = v.w;
    }
    float4 bias = *(const float4*)(b + 4 * c);
    for (long e = (long)blockIdx.x * 16 + grp; e < E; e += (long)gridDim.x * 16) {
        int s = __ldg(src + e), d = __ldg(dst + e);
        float4 hv = *(const float4*)(g_h1 + (long)s * HD + 4 * c);
        float4 e0 = *(const float4*)(ea + e * ED);
        float4 e1 = *(const float4*)(ea + e * ED + 4);
        float4 e2 = *(const float4*)(ea + e * ED + 8);
        float eav[ED] = {e0.x, e0.y, e0.z, e0.w, e1.x, e1.y, e1.z, e1.w,
                         e2.x, e2.y, e2.z, e2.w};
        float m0 = bias.x, m1 = bias.y, m2 = bias.z, m3 = bias.w;
        #pragma unroll
        for (int k = 0; k < ED; k++) {
            m0 = fmaf(eav[k], w[k][0], m0);
            m1 = fmaf(eav[k], w[k][1], m1);
            m2 = fmaf(eav[k], w[k][2], m2);
            m3 = fmaf(eav[k], w[k][3], m3);
        }
        m0 = fmaxf(m0 + hv.x, 0.f); m1 = fmaxf(m1 + hv.y, 0.f);
        m2 = fmaxf(m2 + hv.z, 0.f); m3 = fmaxf(m3 + hv.w, 0.f);
        if (fmaxf(fmaxf(m0, m1), fmaxf(m2, m3)) > 0.f)
            red4(g_agg2 + (long)d * HD + 4 * c, m0, m1, m2, m3);
    }
}

// ---------------------------------------------------------------------------
// MLP1 via mma.sync + ldmatrix/stmatrix. 128-node tiles, K padded 44->48.
#define P1B1  0
#define P1B2  256
#define P1XH  512     // X hi bf16 [128][56] (stride 112 B)
#define P1XL  14848
#define P1W1H 29184   // W1^T hi bf16 [64][56]
#define P1W1L 36352
#define P1W2H 43520   // W2^T hi bf16 [64][72] (stride 144 B)
#define P1W2L 52736
#define P1HH  61952   // H hi bf16 [128][72]
#define P1HL  80384
#define P1TOT 98816
#define P1XS  112
#define P1HS  144

__global__ void __launch_bounds__(256, 2) mlp1_mma(
    const float* __restrict__ x,
    const float* __restrict__ Wa, const float* __restrict__ ba,
    const float* __restrict__ Wb, const float* __restrict__ bb, int N) {
    extern __shared__ __align__(16) char smem[];
    uint32_t sbase = smem_u32(smem);
    float* b1s = (float*)(smem + P1B1);
    float* b2s = (float*)(smem + P1B2);
    int t = threadIdx.x;
    int lane = t & 31, wid = t >> 5;
    int g = lane >> 2, tq = lane & 3;
    int m0 = 16 * wid;
    int lr = lane & 7, q = lane >> 3;

    if (t < 64) { b1s[t] = ba[t]; b2s[t] = bb[t]; }
    if (t < 128) {
        int j = t >> 1, h = t & 1;
        #pragma unroll
        for (int p = 0; p < 11; p++) {               // W1: K=44
            int k = 22 * h + 2 * p;
            uint32_t hi, lo;
            split2(Wa[k * HD + j], Wa[(k + 1) * HD + j], hi, lo);
            *(uint32_t*)(smem + P1W1H + j * P1XS + k * 2) = hi;
            *(uint32_t*)(smem + P1W1L + j * P1XS + k * 2) = lo;
        }
        if (h) {
            *(uint32_t*)(smem + P1W1H + j * P1XS + 88) = 0u;
            *(uint32_t*)(smem + P1W1H + j * P1XS + 92) = 0u;
            *(uint32_t*)(smem + P1W1L + j * P1XS + 88) = 0u;
            *(uint32_t*)(smem + P1W1L + j * P1XS + 92) = 0u;
        }
        #pragma unroll
        for (int p = 0; p < 16; p++) {               // W2: K=64
            int k = 32 * h + 2 * p;
            uint32_t hi, lo;
            split2(Wb[k * HD + j], Wb[(k + 1) * HD + j], hi, lo);
            *(uint32_t*)(smem + P1W2H + j * P1HS + k * 2) = hi;
            *(uint32_t*)(smem + P1W2L + j * P1HS + k * 2) = lo;
        }
    }
    __syncthreads();

    // per-lane ldmatrix/stmatrix bases
    int arow = m0 + (q & 1) * 8 + lr;         // A pattern: row half by q&1, k half by q>>1
    int brow = (q >> 1) * 8 + lr;             // B pattern: row half by q>>1, k half by q&1
    uint32_t aXH = sbase + P1XH + arow * P1XS + (q >> 1) * 16;
    uint32_t aXL = sbase + P1XL + arow * P1XS + (q >> 1) * 16;
    uint32_t aHH = sbase + P1HH + arow * P1HS + (q >> 1) * 16;
    uint32_t aHL = sbase + P1HL + arow * P1HS + (q >> 1) * 16;
    uint32_t bW1H = sbase + P1W1H + brow * P1XS + (q & 1) * 16;
    uint32_t bW1L = sbase + P1W1L + brow * P1XS + (q & 1) * 16;
    uint32_t bW2H = sbase + P1W2H + brow * P1HS + (q & 1) * 16;
    uint32_t bW2L = sbase + P1W2L + brow * P1HS + (q & 1) * 16;

    long ntiles = ((long)N + 127) >> 7;
    for (long tile = blockIdx.x; tile < ntiles; tile += gridDim.x) {
        long nb = tile << 7;
        __syncthreads();
        // stage X = x + agg1 -> bf16 hi/lo
        {
            int row = t >> 1, h = t & 1;
            long gn = nb + row;
            if (gn < N) {
                #pragma unroll
                for (int p = 0; p < 11; p++) {
                    int k = 22 * h + 2 * p;
                    float2 a = *(const float2*)(x + gn * ND + k);
                    float2 b = *(const float2*)(g_agg1 + gn * ND + k);
                    uint32_t hi, lo;
                    split2(a.x + b.x, a.y + b.y, hi, lo);
                    *(uint32_t*)(smem + P1XH + row * P1XS + k * 2) = hi;
                    *(uint32_t*)(smem + P1XL + row * P1XS + k * 2) = lo;
                }
            } else {
                #pragma unroll
                for (int p = 0; p < 11; p++) {
                    int k = 22 * h + 2 * p;
                    *(uint32_t*)(smem + P1XH + row * P1XS + k * 2) = 0u;
                    *(uint32_t*)(smem + P1XL + row * P1XS + k * 2) = 0u;
                }
            }
            if (h) {
                *(uint32_t*)(smem + P1XH + row * P1XS + 88) = 0u;
                *(uint32_t*)(smem + P1XH + row * P1XS + 92) = 0u;
                *(uint32_t*)(smem + P1XL + row * P1XS + 88) = 0u;
                *(uint32_t*)(smem + P1XL + row * P1XS + 92) = 0u;
            }
        }
        __syncthreads();
        // stage 1: C1[128x64] = X[128x48] @ W1^T (3-term)
        float acc[8][4];
        #pragma unroll
        for (int nt = 0; nt < 8; nt++)
            #pragma unroll
            for (int i = 0; i < 4; i++) acc[nt][i] = 0.f;
        #pragma unroll
        for (int ks = 0; ks < 3; ks++) {
            uint32_t ah0, ah1, ah2, ah3, al0, al1, al2, al3;
            ldsm4(ah0, ah1, ah2, ah3, aXH + ks * 32);
            ldsm4(al0, al1, al2, al3, aXL + ks * 32);
            #pragma unroll
            for (int p = 0; p < 4; p++) {
                uint32_t bh0, bh1, bh2, bh3, bl0, bl1, bl2, bl3;
                ldsm4(bh0, bh1, bh2, bh3, bW1H + p * (16 * P1XS) + ks * 32);
                ldsm4(bl0, bl1, bl2, bl3, bW1L + p * (16 * P1XS) + ks * 32);
                mma16816(acc[2 * p],     ah0, ah1, ah2, ah3, bh0, bh1);
                mma16816(acc[2 * p],     ah0, ah1, ah2, ah3, bl0, bl1);
                mma16816(acc[2 * p],     al0, al1, al2, al3, bh0, bh1);
                mma16816(acc[2 * p + 1], ah0, ah1, ah2, ah3, bh2, bh3);
                mma16816(acc[2 * p + 1], ah0, ah1, ah2, ah3, bl2, bl3);
                mma16816(acc[2 * p + 1], al0, al1, al2, al3, bh2, bh3);
            }
        }
        // H = relu(C1+b1) -> bf16 hi/lo via stmatrix (nt pairs)
        #pragma unroll
        for (int p = 0; p < 4; p++) {
            uint32_t hiA, loA, hiB, loB, hiC, loC, hiD, loD;
            int colE = 16 * p + 2 * tq, colO = colE + 8;
            split2(fmaxf(acc[2*p][0] + b1s[colE], 0.f),
                   fmaxf(acc[2*p][1] + b1s[colE + 1], 0.f), hiA, loA);
            split2(fmaxf(acc[2*p][2] + b1s[colE], 0.f),
                   fmaxf(acc[2*p][3] + b1s[colE + 1], 0.f), hiB, loB);
            split2(fmaxf(acc[2*p+1][0] + b1s[colO], 0.f),
                   fmaxf(acc[2*p+1][1] + b1s[colO + 1], 0.f), hiC, loC);
            split2(fmaxf(acc[2*p+1][2] + b1s[colO], 0.f),
                   fmaxf(acc[2*p+1][3] + b1s[colO + 1], 0.f), hiD, loD);
            stsm4(aHH + p * 32, hiA, hiB, hiC, hiD);
            stsm4(aHL + p * 32, loA, loB, loC, loD);
        }
        __syncwarp();
        // stage 2: C2[128x64] = H[128x64] @ W2^T (3-term)
        #pragma unroll
        for (int nt = 0; nt < 8; nt++)
            #pragma unroll
            for (int i = 0; i < 4; i++) acc[nt][i] = 0.f;
        #pragma unroll
        for (int ks = 0; ks < 4; ks++) {
            uint32_t ah0, ah1, ah2, ah3, al0, al1, al2, al3;
            ldsm4(ah0, ah1, ah2, ah3, aHH + ks * 32);
            ldsm4(al0, al1, al2, al3, aHL + ks * 32);
            #pragma unroll
            for (int p = 0; p < 4; p++) {
                uint32_t bh0, bh1, bh2, bh3, bl0, bl1, bl2, bl3;
                ldsm4(bh0, bh1, bh2, bh3, bW2H + p * (16 * P1HS) + ks * 32);
                ldsm4(bl0, bl1, bl2, bl3, bW2L + p * (16 * P1HS) + ks * 32);
                mma16816(acc[2 * p],     ah0, ah1, ah2, ah3, bh0, bh1);
                mma16816(acc[2 * p],     ah0, ah1, ah2, ah3, bl0, bl1);
                mma16816(acc[2 * p],     al0, al1, al2, al3, bh0, bh1);
                mma16816(acc[2 * p + 1], ah0, ah1, ah2, ah3, bh2, bh3);
                mma16816(acc[2 * p + 1], ah0, ah1, ah2, ah3, bl2, bl3);
                mma16816(acc[2 * p + 1], al0, al1, al2, al3, bh2, bh3);
            }
        }
        // outer relu + direct store to g_h1
        {
            long gn0 = nb + m0 + g, gn1 = gn0 + 8;
            #pragma unroll
            for (int nt = 0; nt < 8; nt++) {
                int col = 8 * nt + 2 * tq;
                if (gn0 < N) {
                    float2 v = make_float2(fmaxf(acc[nt][0] + b2s[col], 0.f),
                                           fmaxf(acc[nt][1] + b2s[col + 1], 0.f));
                    *(float2*)(g_h1 + gn0 * HD + col) = v;
                }
                if (gn1 < N) {
                    float2 v = make_float2(fmaxf(acc[nt][2] + b2s[col], 0.f),
                                           fmaxf(acc[nt][3] + b2s[col + 1], 0.f));
                    *(float2*)(g_h1 + gn1 * HD + col) = v;
                }
            }
        }
    }
}

// ---------------------------------------------------------------------------
// MLP2 via mma.sync + ldmatrix/stmatrix + fused pooling.
#define MB1   0
#define MB2   512
#define MXH   1024     // X hi bf16 [128][72] (stride 144 B)
#define MXL   19456
#define MW1H  37888    // W1^T hi bf16 [128][72]
#define MW1L  56320
#define MW2H  74752    // W2^T hi bf16 [128][136] (stride 272 B)
#define MW2L  109568
#define MHH   144384   // H hi bf16 [128][136]; reused as O float [128][132]
#define MHL   179200
#define MTOT  214016
#define XS 144
#define HS 272
#define OS 132

__global__ void __launch_bounds__(256, 1) mlp2_mma(
    const float* __restrict__ Wa, const float* __restrict__ ba,
    const float* __restrict__ Wb, const float* __restrict__ bb,
    const int* __restrict__ batch, float* __restrict__ out, int N) {
    extern __shared__ __align__(16) char smem[];
    uint32_t sbase = smem_u32(smem);
    float* b1s = (float*)(smem + MB1);
    float* b2s = (float*)(smem + MB2);
    int t = threadIdx.x;
    int lane = t & 31, wid = t >> 5;
    int g = lane >> 2, tq = lane & 3;
    int m0 = 16 * wid;
    int lr = lane & 7, q = lane >> 3;

    if (t < 128) { b1s[t] = ba[t]; b2s[t] = bb[t]; }
    {
        int j = t >> 1, h = t & 1;
        for (int k = 32 * h; k < 32 * h + 32; k += 2) {        // W1: K=64
            uint32_t hi, lo;
            split2(Wa[k * EMB + j], Wa[(k + 1) * EMB + j], hi, lo);
            *(uint32_t*)(smem + MW1H + j * XS + k * 2) = hi;
            *(uint32_t*)(smem + MW1L + j * XS + k * 2) = lo;
        }
        for (int k = 64 * h; k < 64 * h + 64; k += 2) {        // W2: K=128
            uint32_t hi, lo;
            split2(Wb[k * EMB + j], Wb[(k + 1) * EMB + j], hi, lo);
            *(uint32_t*)(smem + MW2H + j * HS + k * 2) = hi;
            *(uint32_t*)(smem + MW2L + j * HS + k * 2) = lo;
        }
    }
    __syncthreads();

    int arow = m0 + (q & 1) * 8 + lr;
    int brow = (q >> 1) * 8 + lr;
    uint32_t aXHa = sbase + MXH + arow * XS + (q >> 1) * 16;
    uint32_t aXLa = sbase + MXL + arow * XS + (q >> 1) * 16;
    uint32_t aHHa = sbase + MHH + arow * HS + (q >> 1) * 16;
    uint32_t aHLa = sbase + MHL + arow * HS + (q >> 1) * 16;
    uint32_t bW1Ha = sbase + MW1H + brow * XS + (q & 1) * 16;
    uint32_t bW1La = sbase + MW1L + brow * XS + (q & 1) * 16;
    uint32_t bW2Ha = sbase + MW2H + brow * HS + (q & 1) * 16;
    uint32_t bW2La = sbase + MW2L + brow * HS + (q & 1) * 16;

    int px = t & 15, py = t >> 4;
    int j0p = 8 * px;

    long ntiles = ((long)N + 127) >> 7;
    for (long tile = blockIdx.x; tile < ntiles; tile += gridDim.x) {
        long nb = tile << 7;
        __syncthreads();
        // stage X = h1 + agg2 -> bf16 hi/lo
        {
            int row = t >> 1, h = t & 1;
            long gn = nb + row;
            if (gn < N) {
                #pragma unroll 8
                for (int p = 0; p < 16; p++) {
                    int k = 32 * h + 2 * p;
                    float2 a = *(const float2*)(g_h1 + gn * HD + k);
                    float2 b = *(const float2*)(g_agg2 + gn * HD + k);
                    uint32_t hi, lo;
                    split2(a.x + b.x, a.y + b.y, hi, lo);
                    *(uint32_t*)(smem + MXH + row * XS + k * 2) = hi;
                    *(uint32_t*)(smem + MXL + row * XS + k * 2) = lo;
                }
            } else {
                #pragma unroll 8
                for (int p = 0; p < 16; p++) {
                    int k = 32 * h + 2 * p;
                    *(uint32_t*)(smem + MXH + row * XS + k * 2) = 0u;
                    *(uint32_t*)(smem + MXL + row * XS + k * 2) = 0u;
                }
            }
        }
        __syncthreads();
        // stage 1: C1[128x128] = X[128x64] @ W1^T (3-term)
        float acc[16][4];
        #pragma unroll
        for (int nt = 0; nt < 16; nt++)
            #pragma unroll
            for (int i = 0; i < 4; i++) acc[nt][i] = 0.f;
        #pragma unroll
        for (int ks = 0; ks < 4; ks++) {
            uint32_t ah0, ah1, ah2, ah3, al0, al1, al2, al3;
            ldsm4(ah0, ah1, ah2, ah3, aXHa + ks * 32);
            ldsm4(al0, al1, al2, al3, aXLa + ks * 32);
            #pragma unroll
            for (int p = 0; p < 8; p++) {
                uint32_t bh0, bh1, bh2, bh3, bl0, bl1, bl2, bl3;
                ldsm4(bh0, bh1, bh2, bh3, bW1Ha + p * (16 * XS) + ks * 32);
                ldsm4(bl0, bl1, bl2, bl3, bW1La + p * (16 * XS) + ks * 32);
                mma16816(acc[2 * p],     ah0, ah1, ah2, ah3, bh0, bh1);
                mma16816(acc[2 * p],     ah0, ah1, ah2, ah3, bl0, bl1);
                mma16816(acc[2 * p],     al0, al1, al2, al3, bh0, bh1);
                mma16816(acc[2 * p + 1], ah0, ah1, ah2, ah3, bh2, bh3);
                mma16816(acc[2 * p + 1], ah0, ah1, ah2, ah3, bl2, bl3);
                mma16816(acc[2 * p + 1], al0, al1, al2, al3, bh2, bh3);
            }
        }
        // H = relu(C1+b1) -> bf16 hi/lo via stmatrix
        #pragma unroll
        for (int p = 0; p < 8; p++) {
            uint32_t hiA, loA, hiB, loB, hiC, loC, hiD, loD;
            int colE = 16 * p + 2 * tq, colO = colE + 8;
            split2(fmaxf(acc[2*p][0] + b1s[colE], 0.f),
                   fmaxf(acc[2*p][1] + b1s[colE + 1], 0.f), hiA, loA);
            split2(fmaxf(acc[2*p][2] + b1s[colE], 0.f),
                   fmaxf(acc[2*p][3] + b1s[colE + 1], 0.f), hiB, loB);
            split2(fmaxf(acc[2*p+1][0] + b1s[colO], 0.f),
                   fmaxf(acc[2*p+1][1] + b1s[colO + 1], 0.f), hiC, loC);
            split2(fmaxf(acc[2*p+1][2] + b1s[colO], 0.f),
                   fmaxf(acc[2*p+1][3] + b1s[colO + 1], 0.f), hiD, loD);
            stsm4(aHHa + p * 32, hiA, hiB, hiC, hiD);
            stsm4(aHLa + p * 32, loA, loB, loC, loD);
        }
        __syncwarp();
        // stage 2: C2[128x128] = H[128x128] @ W2^T (3-term)
        #pragma unroll
        for (int nt = 0; nt < 16; nt++)
            #pragma unroll
            for (int i = 0; i < 4; i++) acc[nt][i] = 0.f;
        #pragma unroll
        for (int ks = 0; ks < 8; ks++) {
            uint32_t ah0, ah1, ah2, ah3, al0, al1, al2, al3;
            ldsm4(ah0, ah1, ah2, ah3, aHHa + ks * 32);
            ldsm4(al0, al1, al2, al3, aHLa + ks * 32);
            #pragma unroll
            for (int p = 0; p < 8; p++) {
                uint32_t bh0, bh1, bh2, bh3, bl0, bl1, bl2, bl3;
                ldsm4(bh0, bh1, bh2, bh3, bW2Ha + p * (16 * HS) + ks * 32);
                ldsm4(bl0, bl1, bl2, bl3, bW2La + p * (16 * HS) + ks * 32);
                mma16816(acc[2 * p],     ah0, ah1, ah2, ah3, bh0, bh1);
                mma16816(acc[2 * p],     ah0, ah1, ah2, ah3, bl0, bl1);
                mma16816(acc[2 * p],     al0, al1, al2, al3, bh0, bh1);
                mma16816(acc[2 * p + 1], ah0, ah1, ah2, ah3, bh2, bh3);
                mma16816(acc[2 * p + 1], ah0, ah1, ah2, ah3, bl2, bl3);
                mma16816(acc[2 * p + 1], al0, al1, al2, al3, bh2, bh3);
            }
        }
        __syncthreads();
        // O = C2 + b2 into smem (reuse H region)
        float* O = (float*)(smem + MHH);
        #pragma unroll
        for (int nt = 0; nt < 16; nt++) {
            int col = 8 * nt + 2 * tq;
            O[(m0 + g) * OS + col]         = acc[nt][0] + b2s[col];
            O[(m0 + g) * OS + col + 1]     = acc[nt][1] + b2s[col + 1];
            O[(m0 + g + 8) * OS + col]     = acc[nt][2] + b2s[col];
            O[(m0 + g + 8) * OS + col + 1] = acc[nt][3] + b2s[col + 1];
        }
        __syncthreads();
        // pooled epilogue
        {
            int cur = -1;
            float p[8];
            #pragma unroll
            for (int j = 0; j < 8; j++) p[j] = 0.f;
            for (int r = py * 8; r < py * 8 + 8; r++) {
                long gn = nb + r;
                if (gn >= N) break;
                int gg = __ldg(batch + gn);
                if (gg != cur) {
                    if (cur >= 0) {
                        red4(out + (long)cur * EMB + j0p,     p[0], p[1], p[2], p[3]);
                        red4(out + (long)cur * EMB + j0p + 4, p[4], p[5], p[6], p[7]);
                    }
                    cur = gg;
                    #pragma unroll
                    for (int j = 0; j < 8; j++) p[j] = 0.f;
                }
                #pragma unroll
                for (int j = 0; j < 8; j++) p[j] += O[r * OS + j0p + j];
            }
            if (cur >= 0) {
                red4(out + (long)cur * EMB + j0p,     p[0], p[1], p[2], p[3]);
                red4(out + (long)cur * EMB + j0p + 4, p[4], p[5], p[6], p[7]);
            }
        }
    }
}

// ---------------------------------------------------------------------------
__global__ void div_kernel(float* __restrict__ out, int total) {
    int idx = blockIdx.x * blockDim.x + threadIdx.x;
    if (idx < total) {
        int g = idx >> 7;
        int c = g_cnt[g];
        out[idx] *= (1.0f / (float)(c > 0 ? c : 1));
    }
}

// ---------------------------------------------------------------------------
extern "C" void kernel_launch(void* const* d_in, const int* in_sizes, int n_in,
                              void* d_out, int out_size) {
    const float* x     = (const float*)d_in[0];
    const float* ea    = (const float*)d_in[1];
    const int*   ei    = (const int*)  d_in[2];
    const int*   batch = (const int*)  d_in[3];
    const float* el1_w = (const float*)d_in[4];
    const float* el1_b = (const float*)d_in[5];
    const float* w1a   = (const float*)d_in[6];
    const float* b1a   = (const float*)d_in[7];
    const float* w1b   = (const float*)d_in[8];
    const float* b1b   = (const float*)d_in[9];
    const float* el2_w = (const float*)d_in[10];
    const float* el2_b = (const float*)d_in[11];
    const float* w2a   = (const float*)d_in[12];
    const float* b2a   = (const float*)d_in[13];
    const float* w2b   = (const float*)d_in[14];
    const float* b2b   = (const float*)d_in[15];

    int N = in_sizes[0] / ND;
    int E = in_sizes[1] / ED;
    float* out = (float*)d_out;
    const int* src = ei;
    const int* dst = ei + E;

    zero_all<<<2048, 256>>>(out, (long)out_size, N);
    count_kernel<<<(N + 255) / 256, 256>>>(batch, N);

    edge1_kernel<<<2048, 352>>>(x, ea, src, dst, el1_w, el1_b, E);

    cudaFuncSetAttribute(mlp1_mma, cudaFuncAttributeMaxDynamicSharedMemorySize, P1TOT);
    mlp1_mma<<<296, 256, P1TOT>>>(x, w1a, b1a, w1b, b1b, N);

    edge2_kernel<<<2048, 256>>>(ea, src, dst, el2_w, el2_b, E);

    cudaFuncSetAttribute(mlp2_mma, cudaFuncAttributeMaxDynamicSharedMemorySize, MTOT);
    mlp2_mma<<<148, 256, MTOT>>>(w2a, b2a, w2b, b2b, batch, out, N);

    div_kernel<<<(out_size + 255) / 256, 256>>>(out, out_size);
}

// round 16
// speedup vs baseline: 2.6656x; 1.0223x over previous
#include <cuda_runtime.h>
#include <cuda_bf16.h>
#include <cstdint>

#define ND 44
#define ED 12
#define HD 64
#define EMB 128
#define NMAX 500000
#define GMAX 16384

// Scratch (allocation-free rule: __device__ globals)
__device__ float g_agg1[(size_t)NMAX * ND];
__device__ float g_h1  [(size_t)NMAX * HD];
__device__ float g_agg2[(size_t)NMAX * HD];
__device__ int   g_cnt [GMAX];

__device__ __forceinline__ void red4(float* p, float a, float b, float c, float d) {
    asm volatile("red.global.add.v4.f32 [%0], {%1,%2,%3,%4};"
                 :: "l"(p), "f"(a), "f"(b), "f"(c), "f"(d) : "memory");
}
__device__ __forceinline__ uint32_t smem_u32(const void* p) {
    uint32_t a;
    asm("{ .reg .u64 t; cvta.to.shared.u64 t, %1; cvt.u32.u64 %0, t; }" : "=r"(a) : "l"(p));
    return a;
}
// split two fp32 into packed bf16 hi/lo words (lo element in low half)
__device__ __forceinline__ void split2(float v0, float v1, uint32_t& hi, uint32_t& lo) {
    __nv_bfloat16 h0 = __float2bfloat16(v0), h1 = __float2bfloat16(v1);
    float r0 = v0 - __bfloat162float(h0), r1 = v1 - __bfloat162float(h1);
    __nv_bfloat16 l0 = __float2bfloat16(r0), l1 = __float2bfloat16(r1);
    hi = ((uint32_t)__bfloat16_as_ushort(h1) << 16) | __bfloat16_as_ushort(h0);
    lo = ((uint32_t)__bfloat16_as_ushort(l1) << 16) | __bfloat16_as_ushort(l0);
}
__device__ __forceinline__ void mma16816(float* c, uint32_t a0, uint32_t a1,
                                         uint32_t a2, uint32_t a3,
                                         uint32_t b0, uint32_t b1) {
    asm volatile(
        "mma.sync.aligned.m16n8k16.row.col.f32.bf16.bf16.f32 "
        "{%0,%1,%2,%3}, {%4,%5,%6,%7}, {%8,%9}, {%0,%1,%2,%3};"
        : "+f"(c[0]), "+f"(c[1]), "+f"(c[2]), "+f"(c[3])
        : "r"(a0), "r"(a1), "r"(a2), "r"(a3), "r"(b0), "r"(b1));
}
__device__ __forceinline__ void ldsm4(uint32_t& r0, uint32_t& r1, uint32_t& r2,
                                      uint32_t& r3, uint32_t addr) {
    asm volatile("ldmatrix.sync.aligned.m8n8.x4.shared.b16 {%0,%1,%2,%3}, [%4];"
                 : "=r"(r0), "=r"(r1), "=r"(r2), "=r"(r3) : "r"(addr));
}
__device__ __forceinline__ void stsm4(uint32_t addr, uint32_t r0, uint32_t r1,
                                      uint32_t r2, uint32_t r3) {
    asm volatile("stmatrix.sync.aligned.m8n8.x4.shared.b16 [%0], {%1,%2,%3,%4};"
                 :: "r"(addr), "r"(r0), "r"(r1), "r"(r2), "r"(r3) : "memory");
}

// ---------------------------------------------------------------------------
__global__ void zero_all(float* __restrict__ out, long n_out, int N) {
    long idx = (long)blockIdx.x * blockDim.x + threadIdx.x;
    long st  = (long)gridDim.x * blockDim.x;
    float4 z = make_float4(0.f, 0.f, 0.f, 0.f);
    long n1 = (long)N * ND / 4, n2 = (long)N * HD / 4;
    float4* a1 = (float4*)g_agg1;
    float4* a2 = (float4*)g_agg2;
    float4* ov = (float4*)out;
    for (long i = idx; i < n1; i += st) a1[i] = z;
    for (long i = idx; i < n2; i += st) a2[i] = z;
    for (long i = idx; i < n_out / 4; i += st) ov[i] = z;
    for (long i = idx; i < GMAX; i += st) g_cnt[i] = 0;
}

__global__ void count_kernel(const int* __restrict__ batch, int N) {
    int i = blockIdx.x * blockDim.x + threadIdx.x;
    if (i < N) atomicAdd(&g_cnt[batch[i]], 1);
}

// ---------------------------------------------------------------------------
// Edge pass layer 1: 11 threads per edge, each owns a float4 feature chunk.
__global__ void __launch_bounds__(352) edge1_kernel(
    const float* __restrict__ x, const float* __restrict__ ea,
    const int* __restrict__ src, const int* __restrict__ dst,
    const float* __restrict__ W, const float* __restrict__ b, int E) {
    int t = threadIdx.x;
    int grp = t / 11;
    int c = t - grp * 11;
    float w[ED][4];
    #pragma unroll
    for (int k = 0; k < ED; k++) {
        float4 v = *(const float4*)(W + k * ND + 4 * c);
        w[k][0] = v.x; w[k][1] = v.y; w[k][2] = v.z; w[k][3] = v.w;
    }
    float4 bias = *(const float4*)(b + 4 * c);
    for (long e = (long)blockIdx.x * 32 + grp; e < E; e += (long)gridDim.x * 32) {
        int s = __ldg(src + e), d = __ldg(dst + e);
        float4 xv = *(const float4*)(x + (long)s * ND + 4 * c);
        float4 e0 = *(const float4*)(ea + e * ED);
        float4 e1 = *(const float4*)(ea + e * ED + 4);
        float4 e2 = *(const float4*)(ea + e * ED + 8);
        float eav[ED] = {e0.x, e0.y, e0.z, e0.w, e1.x, e1.y, e1.z, e1.w,
                         e2.x, e2.y, e2.z, e2.w};
        float m0 = bias.x, m1 = bias.y, m2 = bias.z, m3 = bias.w;
        #pragma unroll
        for (int k = 0; k < ED; k++) {
            m0 = fmaf(eav[k], w[k][0], m0);
            m1 = fmaf(eav[k], w[k][1], m1);
            m2 = fmaf(eav[k], w[k][2], m2);
            m3 = fmaf(eav[k], w[k][3], m3);
        }
        m0 = fmaxf(m0 + xv.x, 0.f); m1 = fmaxf(m1 + xv.y, 0.f);
        m2 = fmaxf(m2 + xv.z, 0.f); m3 = fmaxf(m3 + xv.w, 0.f);
        if (fmaxf(fmaxf(m0, m1), fmaxf(m2, m3)) > 0.f)
            red4(g_agg1 + (long)d * ND + 4 * c, m0, m1, m2, m3);
    }
}

// Edge pass layer 2: 16 threads per edge (HD=64).
__global__ void __launch_bounds__(256) edge2_kernel(
    const float* __restrict__ ea,
    const int* __restrict__ src, const int* __restrict__ dst,
    const float* __restrict__ W, const float* __restrict__ b, int E) {
    int t = threadIdx.x;
    int grp = t >> 4;
    int c = t & 15;
    float w[ED][4];
    #pragma unroll
    for (int k = 0; k < ED; k++) {
        float4 v = *(const float4*)(W + k * HD + 4 * c);
        w[k][0] = v.x; w[k][1] = v.y; w[k][2] = v.z; w[k][3] = v.w;
    }
    float4 bias = *(const float4*)(b + 4 * c);
    for (long e = (long)blockIdx.x * 16 + grp; e < E; e += (long)gridDim.x * 16) {
        int s = __ldg(src + e), d = __ldg(dst + e);
        float4 hv = *(const float4*)(g_h1 + (long)s * HD + 4 * c);
        float4 e0 = *(const float4*)(ea + e * ED);
        float4 e1 = *(const float4*)(ea + e * ED + 4);
        float4 e2 = *(const float4*)(ea + e * ED + 8);
        float eav[ED] = {e0.x, e0.y, e0.z, e0.w, e1.x, e1.y, e1.z, e1.w,
                         e2.x, e2.y, e2.z, e2.w};
        float m0 = bias.x, m1 = bias.y, m2 = bias.z, m3 = bias.w;
        #pragma unroll
        for (int k = 0; k < ED; k++) {
            m0 = fmaf(eav[k], w[k][0], m0);
            m1 = fmaf(eav[k], w[k][1], m1);
            m2 = fmaf(eav[k], w[k][2], m2);
            m3 = fmaf(eav[k], w[k][3], m3);
        }
        m0 = fmaxf(m0 + hv.x, 0.f); m1 = fmaxf(m1 + hv.y, 0.f);
        m2 = fmaxf(m2 + hv.z, 0.f); m3 = fmaxf(m3 + hv.w, 0.f);
        if (fmaxf(fmaxf(m0, m1), fmaxf(m2, m3)) > 0.f)
            red4(g_agg2 + (long)d * HD + 4 * c, m0, m1, m2, m3);
    }
}

// ---------------------------------------------------------------------------
// MLP1 via mma.sync + ldmatrix/stmatrix. 128-node tiles, K padded 44->48.
// 512 threads = 16 warps: rowg = wid&7 (16 rows), colg = wid>>3 (32 of 64 cols).
#define P1B1  0
#define P1B2  256
#define P1XH  512     // X hi bf16 [128][56] (stride 112 B)
#define P1XL  14848
#define P1W1H 29184   // W1^T hi bf16 [64][56]
#define P1W1L 36352
#define P1W2H 43520   // W2^T hi bf16 [64][72] (stride 144 B)
#define P1W2L 52736
#define P1HH  61952   // H hi bf16 [128][72]
#define P1HL  80384
#define P1TOT 98816
#define P1XS  112
#define P1HS  144

__global__ void __launch_bounds__(512, 2) mlp1_mma(
    const float* __restrict__ x,
    const float* __restrict__ Wa, const float* __restrict__ ba,
    const float* __restrict__ Wb, const float* __restrict__ bb, int N) {
    extern __shared__ __align__(16) char smem[];
    uint32_t sbase = smem_u32(smem);
    float* b1s = (float*)(smem + P1B1);
    float* b2s = (float*)(smem + P1B2);
    int t = threadIdx.x;
    int lane = t & 31, wid = t >> 5;
    int g = lane >> 2, tq = lane & 3;
    int rowg = wid & 7, colg = wid >> 3;
    int m0 = 16 * rowg;
    int jbase = 32 * colg;
    int lr = lane & 7, q = lane >> 3;

    if (t < 64) { b1s[t] = ba[t]; b2s[t] = bb[t]; }
    if (t < 128) {
        int j = t >> 1, h = t & 1;
        #pragma unroll
        for (int p = 0; p < 11; p++) {               // W1: K=44
            int k = 22 * h + 2 * p;
            uint32_t hi, lo;
            split2(Wa[k * HD + j], Wa[(k + 1) * HD + j], hi, lo);
            *(uint32_t*)(smem + P1W1H + j * P1XS + k * 2) = hi;
            *(uint32_t*)(smem + P1W1L + j * P1XS + k * 2) = lo;
        }
        if (h) {
            *(uint32_t*)(smem + P1W1H + j * P1XS + 88) = 0u;
            *(uint32_t*)(smem + P1W1H + j * P1XS + 92) = 0u;
            *(uint32_t*)(smem + P1W1L + j * P1XS + 88) = 0u;
            *(uint32_t*)(smem + P1W1L + j * P1XS + 92) = 0u;
        }
        #pragma unroll
        for (int p = 0; p < 16; p++) {               // W2: K=64
            int k = 32 * h + 2 * p;
            uint32_t hi, lo;
            split2(Wb[k * HD + j], Wb[(k + 1) * HD + j], hi, lo);
            *(uint32_t*)(smem + P1W2H + j * P1HS + k * 2) = hi;
            *(uint32_t*)(smem + P1W2L + j * P1HS + k * 2) = lo;
        }
    }
    __syncthreads();

    // per-lane ldmatrix/stmatrix bases
    int arow = m0 + (q & 1) * 8 + lr;
    int brow = (q >> 1) * 8 + lr;
    uint32_t aXH = sbase + P1XH + arow * P1XS + (q >> 1) * 16;
    uint32_t aXL = sbase + P1XL + arow * P1XS + (q >> 1) * 16;
    uint32_t aHH = sbase + P1HH + arow * P1HS + (q >> 1) * 16;
    uint32_t aHL = sbase + P1HL + arow * P1HS + (q >> 1) * 16;
    uint32_t bW1H = sbase + P1W1H + (jbase + brow) * P1XS + (q & 1) * 16;
    uint32_t bW1L = sbase + P1W1L + (jbase + brow) * P1XS + (q & 1) * 16;
    uint32_t bW2H = sbase + P1W2H + (jbase + brow) * P1HS + (q & 1) * 16;
    uint32_t bW2L = sbase + P1W2L + (jbase + brow) * P1HS + (q & 1) * 16;

    long ntiles = ((long)N + 127) >> 7;
    for (long tile = blockIdx.x; tile < ntiles; tile += gridDim.x) {
        long nb = tile << 7;
        __syncthreads();
        // stage X = x + agg1 -> bf16 hi/lo (row = t>>2, quarter = t&3)
        {
            int row = t >> 2, sub = t & 3;
            long gn = nb + row;
            int npair = (sub < 3) ? 6 : 4;
            int kb = 12 * sub;
            if (gn < N) {
                #pragma unroll
                for (int p = 0; p < 6; p++) {
                    if (p >= npair) break;
                    int k = kb + 2 * p;
                    float2 a = *(const float2*)(x + gn * ND + k);
                    float2 b = *(const float2*)(g_agg1 + gn * ND + k);
                    uint32_t hi, lo;
                    split2(a.x + b.x, a.y + b.y, hi, lo);
                    *(uint32_t*)(smem + P1XH + row * P1XS + k * 2) = hi;
                    *(uint32_t*)(smem + P1XL + row * P1XS + k * 2) = lo;
                }
            } else {
                #pragma unroll
                for (int p = 0; p < 6; p++) {
                    if (p >= npair) break;
                    int k = kb + 2 * p;
                    *(uint32_t*)(smem + P1XH + row * P1XS + k * 2) = 0u;
                    *(uint32_t*)(smem + P1XL + row * P1XS + k * 2) = 0u;
                }
            }
            if (sub == 3) {                          // pad k=44..47
                *(uint32_t*)(smem + P1XH + row * P1XS + 88) = 0u;
                *(uint32_t*)(smem + P1XH + row * P1XS + 92) = 0u;
                *(uint32_t*)(smem + P1XL + row * P1XS + 88) = 0u;
                *(uint32_t*)(smem + P1XL + row * P1XS + 92) = 0u;
            }
        }
        __syncthreads();
        // stage 1: C1[16 x 32-window] = X @ W1^T (3-term)
        float acc[4][4];
        #pragma unroll
        for (int nt = 0; nt < 4; nt++)
            #pragma unroll
            for (int i = 0; i < 4; i++) acc[nt][i] = 0.f;
        #pragma unroll
        for (int ks = 0; ks < 3; ks++) {
            uint32_t ah0, ah1, ah2, ah3, al0, al1, al2, al3;
            ldsm4(ah0, ah1, ah2, ah3, aXH + ks * 32);
            ldsm4(al0, al1, al2, al3, aXL + ks * 32);
            #pragma unroll
            for (int p = 0; p < 2; p++) {
                uint32_t bh0, bh1, bh2, bh3, bl0, bl1, bl2, bl3;
                ldsm4(bh0, bh1, bh2, bh3, bW1H + p * (16 * P1XS) + ks * 32);
                ldsm4(bl0, bl1, bl2, bl3, bW1L + p * (16 * P1XS) + ks * 32);
                mma16816(acc[2 * p],     ah0, ah1, ah2, ah3, bh0, bh1);
                mma16816(acc[2 * p],     ah0, ah1, ah2, ah3, bl0, bl1);
                mma16816(acc[2 * p],     al0, al1, al2, al3, bh0, bh1);
                mma16816(acc[2 * p + 1], ah0, ah1, ah2, ah3, bh2, bh3);
                mma16816(acc[2 * p + 1], ah0, ah1, ah2, ah3, bl2, bl3);
                mma16816(acc[2 * p + 1], al0, al1, al2, al3, bh2, bh3);
            }
        }
        // H = relu(C1+b1) -> bf16 hi/lo via stmatrix (col window jbase..+32)
        #pragma unroll
        for (int p = 0; p < 2; p++) {
            uint32_t hiA, loA, hiB, loB, hiC, loC, hiD, loD;
            int colE = jbase + 16 * p + 2 * tq, colO = colE + 8;
            split2(fmaxf(acc[2*p][0] + b1s[colE], 0.f),
                   fmaxf(acc[2*p][1] + b1s[colE + 1], 0.f), hiA, loA);
            split2(fmaxf(acc[2*p][2] + b1s[colE], 0.f),
                   fmaxf(acc[2*p][3] + b1s[colE + 1], 0.f), hiB, loB);
            split2(fmaxf(acc[2*p+1][0] + b1s[colO], 0.f),
                   fmaxf(acc[2*p+1][1] + b1s[colO + 1], 0.f), hiC, loC);
            split2(fmaxf(acc[2*p+1][2] + b1s[colO], 0.f),
                   fmaxf(acc[2*p+1][3] + b1s[colO + 1], 0.f), hiD, loD);
            stsm4(aHH + jbase * 2 + p * 32, hiA, hiB, hiC, hiD);
            stsm4(aHL + jbase * 2 + p * 32, loA, loB, loC, loD);
        }
        __syncthreads();   // stage2 A reads H cols written by both col-groups
        // stage 2: C2[16 x 32-window] = H[*, 0..64] @ W2^T (3-term)
        #pragma unroll
        for (int nt = 0; nt < 4; nt++)
            #pragma unroll
            for (int i = 0; i < 4; i++) acc[nt][i] = 0.f;
        #pragma unroll
        for (int ks = 0; ks < 4; ks++) {
            uint32_t ah0, ah1, ah2, ah3, al0, al1, al2, al3;
            ldsm4(ah0, ah1, ah2, ah3, aHH + ks * 32);
            ldsm4(al0, al1, al2, al3, aHL + ks * 32);
            #pragma unroll
            for (int p = 0; p < 2; p++) {
                uint32_t bh0, bh1, bh2, bh3, bl0, bl1, bl2, bl3;
                ldsm4(bh0, bh1, bh2, bh3, bW2H + p * (16 * P1HS) + ks * 32);
                ldsm4(bl0, bl1, bl2, bl3, bW2L + p * (16 * P1HS) + ks * 32);
                mma16816(acc[2 * p],     ah0, ah1, ah2, ah3, bh0, bh1);
                mma16816(acc[2 * p],     ah0, ah1, ah2, ah3, bl0, bl1);
                mma16816(acc[2 * p],     al0, al1, al2, al3, bh0, bh1);
                mma16816(acc[2 * p + 1], ah0, ah1, ah2, ah3, bh2, bh3);
                mma16816(acc[2 * p + 1], ah0, ah1, ah2, ah3, bl2, bl3);
                mma16816(acc[2 * p + 1], al0, al1, al2, al3, bh2, bh3);
            }
        }
        // outer relu + direct store to g_h1 (col window jbase..+32)
        {
            long gn0 = nb + m0 + g, gn1 = gn0 + 8;
            #pragma unroll
            for (int nt = 0; nt < 4; nt++) {
                int col = jbase + 8 * nt + 2 * tq;
                if (gn0 < N) {
                    float2 v = make_float2(fmaxf(acc[nt][0] + b2s[col], 0.f),
                                           fmaxf(acc[nt][1] + b2s[col + 1], 0.f));
                    *(float2*)(g_h1 + gn0 * HD + col) = v;
                }
                if (gn1 < N) {
                    float2 v = make_float2(fmaxf(acc[nt][2] + b2s[col], 0.f),
                                           fmaxf(acc[nt][3] + b2s[col + 1], 0.f));
                    *(float2*)(g_h1 + gn1 * HD + col) = v;
                }
            }
        }
    }
}

// ---------------------------------------------------------------------------
// MLP2 via mma.sync + ldmatrix/stmatrix + fused pooling.
// 512 threads = 16 warps: rowg = wid&7 (16 rows), colg = wid>>3 (64 of 128 cols).
#define MB1   0
#define MB2   512
#define MXH   1024     // X hi bf16 [128][72] (stride 144 B)
#define MXL   19456
#define MW1H  37888    // W1^T hi bf16 [128][72]
#define MW1L  56320
#define MW2H  74752    // W2^T hi bf16 [128][136] (stride 272 B)
#define MW2L  109568
#define MHH   144384   // H hi bf16 [128][136]; reused as O float [128][132]
#define MHL   179200
#define MTOT  214016
#define XS 144
#define HS 272
#define OS 132

__global__ void __launch_bounds__(512, 1) mlp2_mma(
    const float* __restrict__ Wa, const float* __restrict__ ba,
    const float* __restrict__ Wb, const float* __restrict__ bb,
    const int* __restrict__ batch, float* __restrict__ out, int N) {
    extern __shared__ __align__(16) char smem[];
    uint32_t sbase = smem_u32(smem);
    float* b1s = (float*)(smem + MB1);
    float* b2s = (float*)(smem + MB2);
    int t = threadIdx.x;
    int lane = t & 31, wid = t >> 5;
    int g = lane >> 2, tq = lane & 3;
    int rowg = wid & 7, colg = wid >> 3;
    int m0 = 16 * rowg;
    int jbase = 64 * colg;
    int lr = lane & 7, q = lane >> 3;

    if (t < 128) { b1s[t] = ba[t]; b2s[t] = bb[t]; }
    if (t < 256) {
        int j = t >> 1, h = t & 1;
        for (int k = 32 * h; k < 32 * h + 32; k += 2) {        // W1: K=64
            uint32_t hi, lo;
            split2(Wa[k * EMB + j], Wa[(k + 1) * EMB + j], hi, lo);
            *(uint32_t*)(smem + MW1H + j * XS + k * 2) = hi;
            *(uint32_t*)(smem + MW1L + j * XS + k * 2) = lo;
        }
        for (int k = 64 * h; k < 64 * h + 64; k += 2) {        // W2: K=128
            uint32_t hi, lo;
            split2(Wb[k * EMB + j], Wb[(k + 1) * EMB + j], hi, lo);
            *(uint32_t*)(smem + MW2H + j * HS + k * 2) = hi;
            *(uint32_t*)(smem + MW2L + j * HS + k * 2) = lo;
        }
    }
    __syncthreads();

    int arow = m0 + (q & 1) * 8 + lr;
    int brow = (q >> 1) * 8 + lr;
    uint32_t aXHa = sbase + MXH + arow * XS + (q >> 1) * 16;
    uint32_t aXLa = sbase + MXL + arow * XS + (q >> 1) * 16;
    uint32_t aHHa = sbase + MHH + arow * HS + (q >> 1) * 16;
    uint32_t aHLa = sbase + MHL + arow * HS + (q >> 1) * 16;
    uint32_t bW1Ha = sbase + MW1H + (jbase + brow) * XS + (q & 1) * 16;
    uint32_t bW1La = sbase + MW1L + (jbase + brow) * XS + (q & 1) * 16;
    uint32_t bW2Ha = sbase + MW2H + (jbase + brow) * HS + (q & 1) * 16;
    uint32_t bW2La = sbase + MW2L + (jbase + brow) * HS + (q & 1) * 16;

    int px = t & 15, py = t >> 4;     // pooling: j0 = 8*px, rows 4 per py
    int j0p = 8 * px;

    long ntiles = ((long)N + 127) >> 7;
    for (long tile = blockIdx.x; tile < ntiles; tile += gridDim.x) {
        long nb = tile << 7;
        __syncthreads();
        // stage X = h1 + agg2 -> bf16 hi/lo (row = t>>2, quarter = t&3)
        {
            int row = t >> 2, sub = t & 3;
            long gn = nb + row;
            int kb = 16 * sub;
            if (gn < N) {
                #pragma unroll
                for (int p = 0; p < 8; p++) {
                    int k = kb + 2 * p;
                    float2 a = *(const float2*)(g_h1 + gn * HD + k);
                    float2 b = *(const float2*)(g_agg2 + gn * HD + k);
                    uint32_t hi, lo;
                    split2(a.x + b.x, a.y + b.y, hi, lo);
                    *(uint32_t*)(smem + MXH + row * XS + k * 2) = hi;
                    *(uint32_t*)(smem + MXL + row * XS + k * 2) = lo;
                }
            } else {
                #pragma unroll
                for (int p = 0; p < 8; p++) {
                    int k = kb + 2 * p;
                    *(uint32_t*)(smem + MXH + row * XS + k * 2) = 0u;
                    *(uint32_t*)(smem + MXL + row * XS + k * 2) = 0u;
                }
            }
        }
        __syncthreads();
        // stage 1: C1[16 x 64-window] = X @ W1^T (3-term)
        float acc[8][4];
        #pragma unroll
        for (int nt = 0; nt < 8; nt++)
            #pragma unroll
            for (int i = 0; i < 4; i++) acc[nt][i] = 0.f;
        #pragma unroll
        for (int ks = 0; ks < 4; ks++) {
            uint32_t ah0, ah1, ah2, ah3, al0, al1, al2, al3;
            ldsm4(ah0, ah1, ah2, ah3, aXHa + ks * 32);
            ldsm4(al0, al1, al2, al3, aXLa + ks * 32);
            #pragma unroll
            for (int p = 0; p < 4; p++) {
                uint32_t bh0, bh1, bh2, bh3, bl0, bl1, bl2, bl3;
                ldsm4(bh0, bh1, bh2, bh3, bW1Ha + p * (16 * XS) + ks * 32);
                ldsm4(bl0, bl1, bl2, bl3, bW1La + p * (16 * XS) + ks * 32);
                mma16816(acc[2 * p],     ah0, ah1, ah2, ah3, bh0, bh1);
                mma16816(acc[2 * p],     ah0, ah1, ah2, ah3, bl0, bl1);
                mma16816(acc[2 * p],     al0, al1, al2, al3, bh0, bh1);
                mma16816(acc[2 * p + 1], ah0, ah1, ah2, ah3, bh2, bh3);
                mma16816(acc[2 * p + 1], ah0, ah1, ah2, ah3, bl2, bl3);
                mma16816(acc[2 * p + 1], al0, al1, al2, al3, bh2, bh3);
            }
        }
        // H = relu(C1+b1) -> bf16 hi/lo via stmatrix (col window jbase..+64)
        #pragma unroll
        for (int p = 0; p < 4; p++) {
            uint32_t hiA, loA, hiB, loB, hiC, loC, hiD, loD;
            int colE = jbase + 16 * p + 2 * tq, colO = colE + 8;
            split2(fmaxf(acc[2*p][0] + b1s[colE], 0.f),
                   fmaxf(acc[2*p][1] + b1s[colE + 1], 0.f), hiA, loA);
            split2(fmaxf(acc[2*p][2] + b1s[colE], 0.f),
                   fmaxf(acc[2*p][3] + b1s[colE + 1], 0.f), hiB, loB);
            split2(fmaxf(acc[2*p+1][0] + b1s[colO], 0.f),
                   fmaxf(acc[2*p+1][1] + b1s[colO + 1], 0.f), hiC, loC);
            split2(fmaxf(acc[2*p+1][2] + b1s[colO], 0.f),
                   fmaxf(acc[2*p+1][3] + b1s[colO + 1], 0.f), hiD, loD);
            stsm4(aHHa + jbase * 2 + p * 32, hiA, hiB, hiC, hiD);
            stsm4(aHLa + jbase * 2 + p * 32, loA, loB, loC, loD);
        }
        __syncthreads();   // stage2 A reads H cols written by both col-groups
        // stage 2: C2[16 x 64-window] = H[*, 0..128] @ W2^T (3-term)
        #pragma unroll
        for (int nt = 0; nt < 8; nt++)
            #pragma unroll
            for (int i = 0; i < 4; i++) acc[nt][i] = 0.f;
        #pragma unroll
        for (int ks = 0; ks < 8; ks++) {
            uint32_t ah0, ah1, ah2, ah3, al0, al1, al2, al3;
            ldsm4(ah0, ah1, ah2, ah3, aHHa + ks * 32);
            ldsm4(al0, al1, al2, al3, aHLa + ks * 32);
            #pragma unroll
            for (int p = 0; p < 4; p++) {
                uint32_t bh0, bh1, bh2, bh3, bl0, bl1, bl2, bl3;
                ldsm4(bh0, bh1, bh2, bh3, bW2Ha + p * (16 * HS) + ks * 32);
                ldsm4(bl0, bl1, bl2, bl3, bW2La + p * (16 * HS) + ks * 32);
                mma16816(acc[2 * p],     ah0, ah1, ah2, ah3, bh0, bh1);
                mma16816(acc[2 * p],     ah0, ah1, ah2, ah3, bl0, bl1);
                mma16816(acc[2 * p],     al0, al1, al2, al3, bh0, bh1);
                mma16816(acc[2 * p + 1], ah0, ah1, ah2, ah3, bh2, bh3);
                mma16816(acc[2 * p + 1], ah0, ah1, ah2, ah3, bl2, bl3);
                mma16816(acc[2 * p + 1], al0, al1, al2, al3, bh2, bh3);
            }
        }
        __syncthreads();    // all H reads done before O overwrites the region
        // O = C2 + b2 into smem (reuse H region)
        float* O = (float*)(smem + MHH);
        #pragma unroll
        for (int nt = 0; nt < 8; nt++) {
            int col = jbase + 8 * nt + 2 * tq;
            O[(m0 + g) * OS + col]         = acc[nt][0] + b2s[col];
            O[(m0 + g) * OS + col + 1]     = acc[nt][1] + b2s[col + 1];
            O[(m0 + g + 8) * OS + col]     = acc[nt][2] + b2s[col];
            O[(m0 + g + 8) * OS + col + 1] = acc[nt][3] + b2s[col + 1];
        }
        __syncthreads();
        // pooled epilogue: run-length over sorted batch, v4 reductions
        {
            int cur = -1;
            float p[8];
            #pragma unroll
            for (int j = 0; j < 8; j++) p[j] = 0.f;
            for (int r = py * 4; r < py * 4 + 4; r++) {
                long gn = nb + r;
                if (gn >= N) break;
                int gg = __ldg(batch + gn);
                if (gg != cur) {
                    if (cur >= 0) {
                        red4(out + (long)cur * EMB + j0p,     p[0], p[1], p[2], p[3]);
                        red4(out + (long)cur * EMB + j0p + 4, p[4], p[5], p[6], p[7]);
                    }
                    cur = gg;
                    #pragma unroll
                    for (int j = 0; j < 8; j++) p[j] = 0.f;
                }
                #pragma unroll
                for (int j = 0; j < 8; j++) p[j] += O[r * OS + j0p + j];
            }
            if (cur >= 0) {
                red4(out + (long)cur * EMB + j0p,     p[0], p[1], p[2], p[3]);
                red4(out + (long)cur * EMB + j0p + 4, p[4], p[5], p[6], p[7]);
            }
        }
    }
}

// ---------------------------------------------------------------------------
__global__ void div_kernel(float* __restrict__ out, int total) {
    int idx = blockIdx.x * blockDim.x + threadIdx.x;
    if (idx < total) {
        int g = idx >> 7;
        int c = g_cnt[g];
        out[idx] *= (1.0f / (float)(c > 0 ? c : 1));
    }
}

// ---------------------------------------------------------------------------
extern "C" void kernel_launch(void* const* d_in, const int* in_sizes, int n_in,
                              void* d_out, int out_size) {
    const float* x     = (const float*)d_in[0];
    const float* ea    = (const float*)d_in[1];
    const int*   ei    = (const int*)  d_in[2];
    const int*   batch = (const int*)  d_in[3];
    const float* el1_w = (const float*)d_in[4];
    const float* el1_b = (const float*)d_in[5];
    const float* w1a   = (const float*)d_in[6];
    const float* b1a   = (const float*)d_in[7];
    const float* w1b   = (const float*)d_in[8];
    const float* b1b   = (const float*)d_in[9];
    const float* el2_w = (const float*)d_in[10];
    const float* el2_b = (const float*)d_in[11];
    const float* w2a   = (const float*)d_in[12];
    const float* b2a   = (const float*)d_in[13];
    const float* w2b   = (const float*)d_in[14];
    const float* b2b   = (const float*)d_in[15];

    int N = in_sizes[0] / ND;
    int E = in_sizes[1] / ED;
    float* out = (float*)d_out;
    const int* src = ei;
    const int* dst = ei + E;

    zero_all<<<2048, 256>>>(out, (long)out_size, N);
    count_kernel<<<(N + 255) / 256, 256>>>(batch, N);

    edge1_kernel<<<2048, 352>>>(x, ea, src, dst, el1_w, el1_b, E);

    cudaFuncSetAttribute(mlp1_mma, cudaFuncAttributeMaxDynamicSharedMemorySize, P1TOT);
    mlp1_mma<<<296, 512, P1TOT>>>(x, w1a, b1a, w1b, b1b, N);

    edge2_kernel<<<2048, 256>>>(ea, src, dst, el2_w, el2_b, E);

    cudaFuncSetAttribute(mlp2_mma, cudaFuncAttributeMaxDynamicSharedMemorySize, MTOT);
    mlp2_mma<<<148, 512, MTOT>>>(w2a, b2a, w2b, b2b, batch, out, N);

    div_kernel<<<(out_size + 255) / 256, 256>>>(out, out_size);
}